// round 10
// baseline (speedup 1.0000x reference)
#include <cuda_runtime.h>
#include <math.h>

#define Bv   2
#define Tv   2048
#define Dv   768
#define Hv   12
#define HDv  64
#define Lv   4
#define DFv  3072
#define Vv   32000
#define Mv   (Bv*Tv)        /* 4096 rows */
#define QKVN (3*Hv*HDv)     /* 2304 */

// ---------------- scratch (static device globals; no allocs) ----------------
__device__ float g_x  [Mv*Dv];     // residual stream
__device__ float g_ln [Mv*Dv];     // layernorm output (tf32-rounded)
__device__ float g_qkv[Mv*QKVN];   // qkv projection (tf32-rounded)
__device__ float g_att[Mv*Dv];     // attention output (tf32-rounded)
__device__ float g_ff [Mv*DFv];    // ffn hidden (tf32-rounded)
// tf32-canonical weight copies
__device__ float g_wqkv[Lv*Dv*QKVN];
__device__ float g_wout[Lv*Dv*Dv];
__device__ float g_wup [Lv*Dv*DFv];
__device__ float g_wdn [Lv*DFv*Dv];
__device__ float g_te  [Vv*Dv];

// ---------------- TF32 / async helpers ----------------
__device__ __forceinline__ unsigned f2t(float f) {
    unsigned u; asm("cvt.rna.tf32.f32 %0, %1;" : "=r"(u) : "f"(f)); return u;
}
__device__ __forceinline__ float f2tf(float f) { return __uint_as_float(f2t(f)); }
__device__ __forceinline__ void mma_tf32(float* c, const unsigned* a, const unsigned* b) {
    asm volatile(
        "mma.sync.aligned.m16n8k8.row.col.f32.tf32.tf32.f32 "
        "{%0,%1,%2,%3}, {%4,%5,%6,%7}, {%8,%9}, {%0,%1,%2,%3};\n"
        : "+f"(c[0]), "+f"(c[1]), "+f"(c[2]), "+f"(c[3])
        : "r"(a[0]), "r"(a[1]), "r"(a[2]), "r"(a[3]), "r"(b[0]), "r"(b[1]));
}
__device__ __forceinline__ void cp16(unsigned sdst, const float* g) {
    asm volatile("cp.async.cg.shared.global [%0], [%1], 16;" :: "r"(sdst), "l"(g));
}
__device__ __forceinline__ void cp_commit() {
    asm volatile("cp.async.commit_group;");
}
template <int N>
__device__ __forceinline__ void cp_wait() {
    asm volatile("cp.async.wait_group %0;" :: "n"(N));
}

// ---------------- weight conversion: fp32 -> tf32-canonical fp32 ----------------
__global__ void cvt_k(const float* __restrict__ in, float* __restrict__ out, int n4) {
    int i = blockIdx.x * blockDim.x + threadIdx.x;
    if (i >= n4) return;
    float4 v = ((const float4*)in)[i];
    ((float4*)out)[i] = make_float4(f2tf(v.x), f2tf(v.y), f2tf(v.z), f2tf(v.w));
}

// ---------------- embedding ----------------
__global__ void embed_k(const int* __restrict__ ids, const float* __restrict__ te,
                        const float* __restrict__ pe, float* __restrict__ x) {
    int i = blockIdx.x * blockDim.x + threadIdx.x;
    if (i >= Mv * Dv) return;
    int r = i / Dv, d = i - r * Dv;
    int t = r % Tv;
    x[i] = te[(size_t)ids[r] * Dv + d] + pe[(size_t)t * Dv + d];
}

// ---------------- layernorm (writes tf32-rounded output) ----------------
__global__ void ln_k(const float* __restrict__ x, const float* __restrict__ s,
                     const float* __restrict__ bb, float* __restrict__ y) {
    int r = blockIdx.x;
    const float* xr = x + (size_t)r * Dv;
    float*       yr = y + (size_t)r * Dv;
    __shared__ float red[8];
    int tid = threadIdx.x; // 256
    float v0 = xr[tid], v1 = xr[tid + 256], v2 = xr[tid + 512];
    float sum = v0 + v1 + v2;
    #pragma unroll
    for (int o = 16; o; o >>= 1) sum += __shfl_xor_sync(0xffffffffu, sum, o);
    if ((tid & 31) == 0) red[tid >> 5] = sum;
    __syncthreads();
    float mu = (red[0]+red[1]+red[2]+red[3]+red[4]+red[5]+red[6]+red[7]) * (1.0f/Dv);
    float d0 = v0 - mu, d1 = v1 - mu, d2 = v2 - mu;
    float sq = d0*d0 + d1*d1 + d2*d2;
    __syncthreads();
    #pragma unroll
    for (int o = 16; o; o >>= 1) sq += __shfl_xor_sync(0xffffffffu, sq, o);
    if ((tid & 31) == 0) red[tid >> 5] = sq;
    __syncthreads();
    float var = (red[0]+red[1]+red[2]+red[3]+red[4]+red[5]+red[6]+red[7]) * (1.0f/Dv);
    float rstd = rsqrtf(var + 1e-5f);
    yr[tid      ] = f2tf(d0 * rstd * s[tid      ] + bb[tid      ]);
    yr[tid + 256] = f2tf(d1 * rstd * s[tid + 256] + bb[tid + 256]);
    yr[tid + 512] = f2tf(d2 * rstd * s[tid + 512] + bb[tid + 512]);
}

// ---------------- Tensor-core GEMM: C[M,N] = A[M,K] @ B (+bias)(+silu)(+res) ----
// Inputs MUST be tf32-canonical fp32. 128x128 tile, BK=16, 8 warps (4x2),
// warp tile 32x64, 5-stage cp.async pipeline; next-slab issue moved to loop top.
#define APAD 20
#define BPAD 136
#define NSTAGE 5
#define AW (128*APAD)

template <bool TRANSB, int ACT, bool RES, bool TF32OUT>
__global__ __launch_bounds__(256, 2) void gemm_tc(
    const float* __restrict__ A, const float* __restrict__ B,
    const float* __restrict__ bias, const float* __restrict__ res,
    float* __restrict__ C, int M, int N, int K) {
    constexpr int BW = TRANSB ? 128 * APAD : 16 * BPAD;
    constexpr int SW = AW + BW;
    extern __shared__ float gsm[];

    const int tid  = threadIdx.x;
    const int lane = tid & 31, warp = tid >> 5;
    const int wm = warp >> 1, wn = warp & 1;
    const int m0 = blockIdx.y * 128, n0 = blockIdx.x * 128;
    const unsigned sbase = (unsigned)__cvta_generic_to_shared(gsm);

    float acc[2][8][4];
    #pragma unroll
    for (int i = 0; i < 2; i++)
        #pragma unroll
        for (int j = 0; j < 8; j++)
            #pragma unroll
            for (int q = 0; q < 4; q++) acc[i][j][q] = 0.0f;

    const int arow = tid >> 1, akoff = (tid & 1) * 8;
    const int brow = tid >> 4, bnoff = (tid & 15) * 8;
    const int tbn  = tid >> 1, tbk   = (tid & 1) * 8;

    auto issue = [&](int stg, int k0) {
        const float* ap = A + (size_t)(m0 + arow) * K + k0 + akoff;
        unsigned ad = sbase + (stg * SW + arow * APAD + akoff) * 4;
        cp16(ad, ap); cp16(ad + 16, ap + 4);
        if (!TRANSB) {
            const float* bp = B + (size_t)(k0 + brow) * N + n0 + bnoff;
            unsigned bd = sbase + (stg * SW + AW + brow * BPAD + bnoff) * 4;
            cp16(bd, bp); cp16(bd + 16, bp + 4);
        } else {
            const float* bp = B + (size_t)(n0 + tbn) * K + k0 + tbk;
            unsigned bd = sbase + (stg * SW + AW + tbn * APAD + tbk) * 4;
            cp16(bd, bp); cp16(bd + 16, bp + 4);
        }
    };

    const int nslab = K / 16;
    #pragma unroll
    for (int s = 0; s < NSTAGE - 1; s++) {
        if (s < nslab) issue(s, s * 16);
        cp_commit();
    }

    for (int i = 0; i < nslab; i++) {
        cp_wait<NSTAGE - 2>();
        __syncthreads();

        // issue next slab FIRST: its target stage was fully consumed in iter i-1
        // (guaranteed by the barrier above), and early issue hides more latency.
        int j = i + NSTAGE - 1;
        if (j < nslab) issue(j % NSTAGE, j * 16);
        cp_commit();

        const unsigned* Asf = (const unsigned*)(gsm + (i % NSTAGE) * SW);
        const unsigned* Bsf = Asf + AW;

        #pragma unroll
        for (int ks = 0; ks < 2; ks++) {
            const int kb = ks * 8;
            unsigned af[2][4], bf[8][2];
            #pragma unroll
            for (int mt = 0; mt < 2; mt++) {
                int m = wm * 32 + mt * 16 + (lane >> 2);
                int k = kb + (lane & 3);
                af[mt][0] = Asf[m * APAD + k];
                af[mt][1] = Asf[(m + 8) * APAD + k];
                af[mt][2] = Asf[m * APAD + k + 4];
                af[mt][3] = Asf[(m + 8) * APAD + k + 4];
            }
            #pragma unroll
            for (int nt = 0; nt < 8; nt++) {
                int n = wn * 64 + nt * 8 + (lane >> 2);
                int k = kb + (lane & 3);
                if (!TRANSB) {
                    bf[nt][0] = Bsf[k * BPAD + n];
                    bf[nt][1] = Bsf[(k + 4) * BPAD + n];
                } else {
                    bf[nt][0] = Bsf[n * APAD + k];
                    bf[nt][1] = Bsf[n * APAD + k + 4];
                }
            }
            #pragma unroll
            for (int mt = 0; mt < 2; mt++)
                #pragma unroll
                for (int nt = 0; nt < 8; nt++)
                    mma_tf32(acc[mt][nt], af[mt], bf[nt]);
        }
    }

    #pragma unroll
    for (int mt = 0; mt < 2; mt++) {
        int r0 = m0 + wm * 32 + mt * 16 + (lane >> 2);
        #pragma unroll
        for (int nt = 0; nt < 8; nt++) {
            int c0i = n0 + wn * 64 + nt * 8 + 2 * (lane & 3);
            #pragma unroll
            for (int half = 0; half < 2; half++) {
                int r = r0 + half * 8;
                float v0 = acc[mt][nt][half * 2 + 0];
                float v1 = acc[mt][nt][half * 2 + 1];
                if (bias) { v0 += bias[c0i]; v1 += bias[c0i + 1]; }
                if (ACT == 1) {
                    v0 = v0 * (1.0f / (1.0f + __expf(-v0)));
                    v1 = v1 * (1.0f / (1.0f + __expf(-v1)));
                }
                if (RES) {
                    const float* rp = res + (size_t)r * N + c0i;
                    v0 += rp[0]; v1 += rp[1];
                }
                if (TF32OUT) { v0 = f2tf(v0); v1 = f2tf(v1); }
                float2* cp = (float2*)(C + (size_t)r * N + c0i);
                *cp = make_float2(v0, v1);
            }
        }
    }
}
#define GEMM_SMEM_NT (NSTAGE * (AW + 16 * BPAD) * 4)
#define GEMM_SMEM_T  (NSTAGE * (AW + 128 * APAD) * 4)

// ---------------- flash attention: 128 queries x one (b,h) per block -----------
// 8 warps (4x2), warp tile 32x32. K/V chunks of 64 staged once per 128 queries.
// qkv is tf32-canonical; output written tf32-rounded.
#define QPAD 68
#define VPAD 72
#define ATTN_SMEM ((128*QPAD + 64*QPAD + 64*VPAD + 128*QPAD + 3*128) * 4)

__global__ __launch_bounds__(256) void attn_flash_k(
    const float* __restrict__ qkv, float* __restrict__ out) {
    extern __shared__ unsigned smem[];
    unsigned* Qs = smem;                        // [128][QPAD]
    unsigned* Ks = Qs + 128 * QPAD;             // [64][QPAD]
    unsigned* Vs = Ks + 64 * QPAD;              // [64][VPAD]
    float*    Ss = (float*)(Vs + 64 * VPAD);    // [128][QPAD]
    float*    m_sm = Ss + 128 * QPAD;           // [128]
    float*    l_sm = m_sm + 128;                // [128]
    float*    sc_sm = l_sm + 128;               // [128]

    const int q0 = blockIdx.x * 128;
    const int h  = blockIdx.y;
    const int b  = blockIdx.z;
    const int tid = threadIdx.x;
    const int lane = tid & 31, warp = tid >> 5;
    const int wm = warp >> 1, wn = warp & 1;    // 4 x 2, warp tile 32x32

    const float* qbase = qkv + (size_t)(b * Tv) * QKVN + h * HDv;
    const float* kbase = qbase + Hv * HDv;
    const float* vbase = qbase + 2 * Hv * HDv;

    // load Q (128 x 64), pre-scaled (power of 2 -> stays tf32-canonical)
    #pragma unroll
    for (int it = 0; it < 8; it++) {
        int e = tid + 256 * it;                 // float4 index over 2048
        int r = e >> 4, d = (e & 15) * 4;
        float4 q4 = *(const float4*)(qbase + (size_t)(q0 + r) * QKVN + d);
        unsigned* dst = Qs + r * QPAD + d;
        dst[0] = __float_as_uint(q4.x * 0.125f);
        dst[1] = __float_as_uint(q4.y * 0.125f);
        dst[2] = __float_as_uint(q4.z * 0.125f);
        dst[3] = __float_as_uint(q4.w * 0.125f);
    }
    if (tid < 128) { m_sm[tid] = -1e30f; l_sm[tid] = 0.0f; }

    float acc_o[2][4][4];
    #pragma unroll
    for (int mt = 0; mt < 2; mt++)
        #pragma unroll
        for (int nt = 0; nt < 4; nt++)
            #pragma unroll
            for (int q = 0; q < 4; q++) acc_o[mt][nt][q] = 0.0f;

    for (int c0 = 0; c0 <= q0 + 64; c0 += 64) {
        // ---- stage K, V chunk (64 x 64 each) ----
        #pragma unroll
        for (int it = 0; it < 4; it++) {
            int e = tid + 256 * it;
            int r = e >> 4, d = (e & 15) * 4;
            float4 k4 = *(const float4*)(kbase + (size_t)(c0 + r) * QKVN + d);
            unsigned* kd = Ks + r * QPAD + d;
            kd[0] = __float_as_uint(k4.x); kd[1] = __float_as_uint(k4.y);
            kd[2] = __float_as_uint(k4.z); kd[3] = __float_as_uint(k4.w);
            float4 v4 = *(const float4*)(vbase + (size_t)(c0 + r) * QKVN + d);
            unsigned* vd = Vs + r * VPAD + d;
            vd[0] = __float_as_uint(v4.x); vd[1] = __float_as_uint(v4.y);
            vd[2] = __float_as_uint(v4.z); vd[3] = __float_as_uint(v4.w);
        }
        __syncthreads();

        // ---- S = Q . K^T  (warp tile 32x32) ----
        float s_acc[2][4][4];
        #pragma unroll
        for (int mt = 0; mt < 2; mt++)
            #pragma unroll
            for (int nt = 0; nt < 4; nt++)
                #pragma unroll
                for (int q = 0; q < 4; q++) s_acc[mt][nt][q] = 0.0f;
        #pragma unroll
        for (int kb = 0; kb < 64; kb += 8) {
            unsigned af[2][4], bf[4][2];
            int kk = kb + (lane & 3);
            #pragma unroll
            for (int mt = 0; mt < 2; mt++) {
                int m = wm * 32 + mt * 16 + (lane >> 2);
                af[mt][0] = Qs[m * QPAD + kk];
                af[mt][1] = Qs[(m + 8) * QPAD + kk];
                af[mt][2] = Qs[m * QPAD + kk + 4];
                af[mt][3] = Qs[(m + 8) * QPAD + kk + 4];
            }
            #pragma unroll
            for (int nt = 0; nt < 4; nt++) {
                int n = wn * 32 + nt * 8 + (lane >> 2);
                bf[nt][0] = Ks[n * QPAD + kk];
                bf[nt][1] = Ks[n * QPAD + kk + 4];
            }
            #pragma unroll
            for (int mt = 0; mt < 2; mt++)
                #pragma unroll
                for (int nt = 0; nt < 4; nt++)
                    mma_tf32(s_acc[mt][nt], af[mt], bf[nt]);
        }
        const bool diag = (c0 + 64 > q0);
        #pragma unroll
        for (int mt = 0; mt < 2; mt++) {
            #pragma unroll
            for (int nt = 0; nt < 4; nt++) {
                int c = wn * 32 + nt * 8 + 2 * (lane & 3);
                #pragma unroll
                for (int half = 0; half < 2; half++) {
                    int r = wm * 32 + mt * 16 + (lane >> 2) + half * 8;
                    float v0 = s_acc[mt][nt][half * 2 + 0];
                    float v1 = s_acc[mt][nt][half * 2 + 1];
                    if (diag) {
                        if (c0 + c     > q0 + r) v0 = -1e30f;
                        if (c0 + c + 1 > q0 + r) v1 = -1e30f;
                    }
                    Ss[r * QPAD + c] = v0; Ss[r * QPAD + c + 1] = v1;
                }
            }
        }
        __syncthreads();

        // ---- online softmax: 2 threads per row ----
        {
            int r = tid >> 1, g = tid & 1;
            float* row = Ss + r * QPAD;
            float cmax = -1e30f;
            #pragma unroll
            for (int j = 0; j < 32; j++) cmax = fmaxf(cmax, row[g + 2 * j]);
            cmax = fmaxf(cmax, __shfl_xor_sync(0xffffffffu, cmax, 1));
            float m_old = m_sm[r];
            float m_new = fmaxf(m_old, cmax);
            float csum = 0.0f;
            unsigned* prow = (unsigned*)row;
            #pragma unroll
            for (int j = 0; j < 32; j++) {
                float p = __expf(row[g + 2 * j] - m_new);
                csum += p;
                prow[g + 2 * j] = f2t(p);
            }
            csum += __shfl_xor_sync(0xffffffffu, csum, 1);
            if (g == 0) {
                float scale = __expf(m_old - m_new);
                sc_sm[r] = scale;
                l_sm[r] = l_sm[r] * scale + csum;
                m_sm[r] = m_new;
            }
        }
        __syncthreads();

        // ---- rescale O, then O += P . V ----
        #pragma unroll
        for (int mt = 0; mt < 2; mt++) {
            int r1 = wm * 32 + mt * 16 + (lane >> 2);
            float s1 = sc_sm[r1], s2 = sc_sm[r1 + 8];
            #pragma unroll
            for (int nt = 0; nt < 4; nt++) {
                acc_o[mt][nt][0] *= s1; acc_o[mt][nt][1] *= s1;
                acc_o[mt][nt][2] *= s2; acc_o[mt][nt][3] *= s2;
            }
        }
        const unsigned* Pu = (const unsigned*)Ss;
        #pragma unroll
        for (int kb = 0; kb < 64; kb += 8) {
            unsigned af[2][4], bf[4][2];
            int kk = kb + (lane & 3);
            #pragma unroll
            for (int mt = 0; mt < 2; mt++) {
                int m = wm * 32 + mt * 16 + (lane >> 2);
                af[mt][0] = Pu[m * QPAD + kk];
                af[mt][1] = Pu[(m + 8) * QPAD + kk];
                af[mt][2] = Pu[m * QPAD + kk + 4];
                af[mt][3] = Pu[(m + 8) * QPAD + kk + 4];
            }
            #pragma unroll
            for (int nt = 0; nt < 4; nt++) {
                int n = wn * 32 + nt * 8 + (lane >> 2);
                bf[nt][0] = Vs[kk * VPAD + n];
                bf[nt][1] = Vs[(kk + 4) * VPAD + n];
            }
            #pragma unroll
            for (int mt = 0; mt < 2; mt++)
                #pragma unroll
                for (int nt = 0; nt < 4; nt++)
                    mma_tf32(acc_o[mt][nt], af[mt], bf[nt]);
        }
        __syncthreads();
    }

    // ---- output: O / l, tf32-rounded ----
    #pragma unroll
    for (int mt = 0; mt < 2; mt++) {
        int r1 = wm * 32 + mt * 16 + (lane >> 2);
        float inv1 = 1.0f / l_sm[r1], inv2 = 1.0f / l_sm[r1 + 8];
        #pragma unroll
        for (int nt = 0; nt < 4; nt++) {
            int c = wn * 32 + nt * 8 + 2 * (lane & 3);
            float* o1 = out + (size_t)(b * Tv + q0 + r1) * Dv + h * HDv + c;
            float* o2 = out + (size_t)(b * Tv + q0 + r1 + 8) * Dv + h * HDv + c;
            o1[0] = f2tf(acc_o[mt][nt][0] * inv1); o1[1] = f2tf(acc_o[mt][nt][1] * inv1);
            o2[0] = f2tf(acc_o[mt][nt][2] * inv2); o2[1] = f2tf(acc_o[mt][nt][3] * inv2);
        }
    }
}

// ---------------- driver ----------------
extern "C" void kernel_launch(void* const* d_in, const int* in_sizes, int n_in,
                              void* d_out, int out_size) {
    const int*   ids   = (const int*)  d_in[0];
    const float* te    = (const float*)d_in[1];
    const float* pe    = (const float*)d_in[2];
    const float* ln1_s = (const float*)d_in[3];
    const float* ln1_b = (const float*)d_in[4];
    const float* qkv_w = (const float*)d_in[5];
    const float* qkv_b = (const float*)d_in[6];
    const float* out_w = (const float*)d_in[7];
    const float* out_b = (const float*)d_in[8];
    const float* ln2_s = (const float*)d_in[9];
    const float* ln2_b = (const float*)d_in[10];
    const float* up_w  = (const float*)d_in[11];
    const float* up_b  = (const float*)d_in[12];
    const float* dn_w  = (const float*)d_in[13];
    const float* dn_b  = (const float*)d_in[14];
    const float* lnf_s = (const float*)d_in[15];
    const float* lnf_b = (const float*)d_in[16];
    float* logits = (float*)d_out;

    float *x, *lnb, *qkv, *att, *ff;
    float *wqkv, *wout, *wup, *wdn, *tet;
    cudaGetSymbolAddress((void**)&x,    g_x);
    cudaGetSymbolAddress((void**)&lnb,  g_ln);
    cudaGetSymbolAddress((void**)&qkv,  g_qkv);
    cudaGetSymbolAddress((void**)&att,  g_att);
    cudaGetSymbolAddress((void**)&ff,   g_ff);
    cudaGetSymbolAddress((void**)&wqkv, g_wqkv);
    cudaGetSymbolAddress((void**)&wout, g_wout);
    cudaGetSymbolAddress((void**)&wup,  g_wup);
    cudaGetSymbolAddress((void**)&wdn,  g_wdn);
    cudaGetSymbolAddress((void**)&tet,  g_te);

    cudaFuncSetAttribute(attn_flash_k,
                         cudaFuncAttributeMaxDynamicSharedMemorySize, ATTN_SMEM);
    cudaFuncSetAttribute(gemm_tc<false, 0, false, true>,
                         cudaFuncAttributeMaxDynamicSharedMemorySize, GEMM_SMEM_NT);
    cudaFuncSetAttribute(gemm_tc<false, 0, true, false>,
                         cudaFuncAttributeMaxDynamicSharedMemorySize, GEMM_SMEM_NT);
    cudaFuncSetAttribute(gemm_tc<false, 1, false, true>,
                         cudaFuncAttributeMaxDynamicSharedMemorySize, GEMM_SMEM_NT);
    cudaFuncSetAttribute(gemm_tc<true, 0, false, false>,
                         cudaFuncAttributeMaxDynamicSharedMemorySize, GEMM_SMEM_T);

    // weight pre-conversion to tf32-canonical fp32
    {
        int n;
        n = Lv * Dv * QKVN / 4; cvt_k<<<(n + 255) / 256, 256>>>(qkv_w, wqkv, n);
        n = Lv * Dv * Dv   / 4; cvt_k<<<(n + 255) / 256, 256>>>(out_w, wout, n);
        n = Lv * Dv * DFv  / 4; cvt_k<<<(n + 255) / 256, 256>>>(up_w,  wup,  n);
        n = Lv * DFv * Dv  / 4; cvt_k<<<(n + 255) / 256, 256>>>(dn_w,  wdn,  n);
        n = Vv * Dv        / 4; cvt_k<<<(n + 255) / 256, 256>>>(te,    tet,  n);
    }

    embed_k<<<(Mv * Dv + 255) / 256, 256>>>(ids, te, pe, x);

    for (int i = 0; i < Lv; i++) {
        ln_k<<<Mv, 256>>>(x, ln1_s + (size_t)i * Dv, ln1_b + (size_t)i * Dv, lnb);
        gemm_tc<false, 0, false, true><<<dim3(QKVN / 128, Mv / 128), 256, GEMM_SMEM_NT>>>(
            lnb, wqkv + (size_t)i * Dv * QKVN, qkv_b + (size_t)i * QKVN,
            nullptr, qkv, Mv, QKVN, Dv);
        attn_flash_k<<<dim3(Tv / 128, Hv, Bv), 256, ATTN_SMEM>>>(qkv, att);
        gemm_tc<false, 0, true, false><<<dim3(Dv / 128, Mv / 128), 256, GEMM_SMEM_NT>>>(
            att, wout + (size_t)i * Dv * Dv, out_b + (size_t)i * Dv,
            x, x, Mv, Dv, Dv);
        ln_k<<<Mv, 256>>>(x, ln2_s + (size_t)i * Dv, ln2_b + (size_t)i * Dv, lnb);
        gemm_tc<false, 1, false, true><<<dim3(DFv / 128, Mv / 128), 256, GEMM_SMEM_NT>>>(
            lnb, wup + (size_t)i * Dv * DFv, up_b + (size_t)i * DFv,
            nullptr, ff, Mv, DFv, Dv);
        gemm_tc<false, 0, true, false><<<dim3(Dv / 128, Mv / 128), 256, GEMM_SMEM_NT>>>(
            ff, wdn + (size_t)i * DFv * Dv, dn_b + (size_t)i * Dv,
            x, x, Mv, Dv, DFv);
    }

    ln_k<<<Mv, 256>>>(x, lnf_s, lnf_b, lnb);
    gemm_tc<true, 0, false, false><<<dim3(Vv / 128, Mv / 128), 256, GEMM_SMEM_T>>>(
        lnb, tet, nullptr, nullptr, logits, Mv, Vv, Dv);
}

// round 11
// speedup vs baseline: 1.0955x; 1.0955x over previous
#include <cuda_runtime.h>
#include <math.h>

#define Bv   2
#define Tv   2048
#define Dv   768
#define Hv   12
#define HDv  64
#define Lv   4
#define DFv  3072
#define Vv   32000
#define Mv   (Bv*Tv)        /* 4096 rows */
#define QKVN (3*Hv*HDv)     /* 2304 */

// ---------------- scratch (static device globals; no allocs) ----------------
__device__ float g_x  [Mv*Dv];     // residual stream
__device__ float g_ln [Mv*Dv];     // layernorm output (tf32-rounded)
__device__ float g_qkv[Mv*QKVN];   // qkv projection (tf32-rounded)
__device__ float g_att[Mv*Dv];     // attention output (tf32-rounded)
__device__ float g_ff [Mv*DFv];    // ffn hidden (tf32-rounded)
// tf32-canonical weight copies
__device__ float g_wqkv[Lv*Dv*QKVN];
__device__ float g_wout[Lv*Dv*Dv];
__device__ float g_wup [Lv*Dv*DFv];
__device__ float g_wdn [Lv*DFv*Dv];
__device__ float g_te  [Vv*Dv];

// ---------------- TF32 / async helpers ----------------
__device__ __forceinline__ unsigned f2t(float f) {
    unsigned u; asm("cvt.rna.tf32.f32 %0, %1;" : "=r"(u) : "f"(f)); return u;
}
__device__ __forceinline__ float f2tf(float f) { return __uint_as_float(f2t(f)); }
__device__ __forceinline__ void mma_tf32(float* c, const unsigned* a, const unsigned* b) {
    asm volatile(
        "mma.sync.aligned.m16n8k8.row.col.f32.tf32.tf32.f32 "
        "{%0,%1,%2,%3}, {%4,%5,%6,%7}, {%8,%9}, {%0,%1,%2,%3};\n"
        : "+f"(c[0]), "+f"(c[1]), "+f"(c[2]), "+f"(c[3])
        : "r"(a[0]), "r"(a[1]), "r"(a[2]), "r"(a[3]), "r"(b[0]), "r"(b[1]));
}
__device__ __forceinline__ void cp16(unsigned sdst, const float* g) {
    asm volatile("cp.async.cg.shared.global [%0], [%1], 16;" :: "r"(sdst), "l"(g));
}
__device__ __forceinline__ void cp_commit() {
    asm volatile("cp.async.commit_group;");
}
template <int N>
__device__ __forceinline__ void cp_wait() {
    asm volatile("cp.async.wait_group %0;" :: "n"(N));
}

// ---------------- weight conversion: fp32 -> tf32-canonical fp32 ----------------
__global__ void cvt_k(const float* __restrict__ in, float* __restrict__ out, int n4) {
    int i = blockIdx.x * blockDim.x + threadIdx.x;
    if (i >= n4) return;
    float4 v = ((const float4*)in)[i];
    ((float4*)out)[i] = make_float4(f2tf(v.x), f2tf(v.y), f2tf(v.z), f2tf(v.w));
}

// ---------------- embedding ----------------
__global__ void embed_k(const int* __restrict__ ids, const float* __restrict__ te,
                        const float* __restrict__ pe, float* __restrict__ x) {
    int i = blockIdx.x * blockDim.x + threadIdx.x;
    if (i >= Mv * Dv) return;
    int r = i / Dv, d = i - r * Dv;
    int t = r % Tv;
    x[i] = te[(size_t)ids[r] * Dv + d] + pe[(size_t)t * Dv + d];
}

// ---------------- layernorm (writes tf32-rounded output) ----------------
__global__ void ln_k(const float* __restrict__ x, const float* __restrict__ s,
                     const float* __restrict__ bb, float* __restrict__ y) {
    int r = blockIdx.x;
    const float* xr = x + (size_t)r * Dv;
    float*       yr = y + (size_t)r * Dv;
    __shared__ float red[8];
    int tid = threadIdx.x; // 256
    float v0 = xr[tid], v1 = xr[tid + 256], v2 = xr[tid + 512];
    float sum = v0 + v1 + v2;
    #pragma unroll
    for (int o = 16; o; o >>= 1) sum += __shfl_xor_sync(0xffffffffu, sum, o);
    if ((tid & 31) == 0) red[tid >> 5] = sum;
    __syncthreads();
    float mu = (red[0]+red[1]+red[2]+red[3]+red[4]+red[5]+red[6]+red[7]) * (1.0f/Dv);
    float d0 = v0 - mu, d1 = v1 - mu, d2 = v2 - mu;
    float sq = d0*d0 + d1*d1 + d2*d2;
    __syncthreads();
    #pragma unroll
    for (int o = 16; o; o >>= 1) sq += __shfl_xor_sync(0xffffffffu, sq, o);
    if ((tid & 31) == 0) red[tid >> 5] = sq;
    __syncthreads();
    float var = (red[0]+red[1]+red[2]+red[3]+red[4]+red[5]+red[6]+red[7]) * (1.0f/Dv);
    float rstd = rsqrtf(var + 1e-5f);
    yr[tid      ] = f2tf(d0 * rstd * s[tid      ] + bb[tid      ]);
    yr[tid + 256] = f2tf(d1 * rstd * s[tid + 256] + bb[tid + 256]);
    yr[tid + 512] = f2tf(d2 * rstd * s[tid + 512] + bb[tid + 512]);
}

// ---------------- Tensor-core GEMM (128x128): C = A @ B (+bias)(+silu)(+res) ----
// Inputs MUST be tf32-canonical fp32. BK=16, 8 warps (4x2), warp tile 32x64,
// 5-stage cp.async pipeline. (Exact R7 structure.)
#define APAD 20
#define BPAD 136
#define NSTAGE 5
#define AW (128*APAD)

template <bool TRANSB, int ACT, bool RES, bool TF32OUT>
__global__ __launch_bounds__(256, 2) void gemm_tc(
    const float* __restrict__ A, const float* __restrict__ B,
    const float* __restrict__ bias, const float* __restrict__ res,
    float* __restrict__ C, int M, int N, int K) {
    constexpr int BW = TRANSB ? 128 * APAD : 16 * BPAD;
    constexpr int SW = AW + BW;
    extern __shared__ float gsm[];

    const int tid  = threadIdx.x;
    const int lane = tid & 31, warp = tid >> 5;
    const int wm = warp >> 1, wn = warp & 1;
    const int m0 = blockIdx.y * 128, n0 = blockIdx.x * 128;
    const unsigned sbase = (unsigned)__cvta_generic_to_shared(gsm);

    float acc[2][8][4];
    #pragma unroll
    for (int i = 0; i < 2; i++)
        #pragma unroll
        for (int j = 0; j < 8; j++)
            #pragma unroll
            for (int q = 0; q < 4; q++) acc[i][j][q] = 0.0f;

    const int arow = tid >> 1, akoff = (tid & 1) * 8;
    const int brow = tid >> 4, bnoff = (tid & 15) * 8;
    const int tbn  = tid >> 1, tbk   = (tid & 1) * 8;

    auto issue = [&](int stg, int k0) {
        const float* ap = A + (size_t)(m0 + arow) * K + k0 + akoff;
        unsigned ad = sbase + (stg * SW + arow * APAD + akoff) * 4;
        cp16(ad, ap); cp16(ad + 16, ap + 4);
        if (!TRANSB) {
            const float* bp = B + (size_t)(k0 + brow) * N + n0 + bnoff;
            unsigned bd = sbase + (stg * SW + AW + brow * BPAD + bnoff) * 4;
            cp16(bd, bp); cp16(bd + 16, bp + 4);
        } else {
            const float* bp = B + (size_t)(n0 + tbn) * K + k0 + tbk;
            unsigned bd = sbase + (stg * SW + AW + tbn * APAD + tbk) * 4;
            cp16(bd, bp); cp16(bd + 16, bp + 4);
        }
    };

    const int nslab = K / 16;
    #pragma unroll
    for (int s = 0; s < NSTAGE - 1; s++) {
        if (s < nslab) issue(s, s * 16);
        cp_commit();
    }

    for (int i = 0; i < nslab; i++) {
        cp_wait<NSTAGE - 2>();
        __syncthreads();

        const unsigned* Asf = (const unsigned*)(gsm + (i % NSTAGE) * SW);
        const unsigned* Bsf = Asf + AW;

        #pragma unroll
        for (int ks = 0; ks < 2; ks++) {
            const int kb = ks * 8;
            unsigned af[2][4], bf[8][2];
            #pragma unroll
            for (int mt = 0; mt < 2; mt++) {
                int m = wm * 32 + mt * 16 + (lane >> 2);
                int k = kb + (lane & 3);
                af[mt][0] = Asf[m * APAD + k];
                af[mt][1] = Asf[(m + 8) * APAD + k];
                af[mt][2] = Asf[m * APAD + k + 4];
                af[mt][3] = Asf[(m + 8) * APAD + k + 4];
            }
            #pragma unroll
            for (int nt = 0; nt < 8; nt++) {
                int n = wn * 64 + nt * 8 + (lane >> 2);
                int k = kb + (lane & 3);
                if (!TRANSB) {
                    bf[nt][0] = Bsf[k * BPAD + n];
                    bf[nt][1] = Bsf[(k + 4) * BPAD + n];
                } else {
                    bf[nt][0] = Bsf[n * APAD + k];
                    bf[nt][1] = Bsf[n * APAD + k + 4];
                }
            }
            #pragma unroll
            for (int mt = 0; mt < 2; mt++)
                #pragma unroll
                for (int nt = 0; nt < 8; nt++)
                    mma_tf32(acc[mt][nt], af[mt], bf[nt]);
        }

        int j = i + NSTAGE - 1;
        if (j < nslab) issue(j % NSTAGE, j * 16);
        cp_commit();
    }

    #pragma unroll
    for (int mt = 0; mt < 2; mt++) {
        int r0 = m0 + wm * 32 + mt * 16 + (lane >> 2);
        #pragma unroll
        for (int nt = 0; nt < 8; nt++) {
            int c0i = n0 + wn * 64 + nt * 8 + 2 * (lane & 3);
            #pragma unroll
            for (int half = 0; half < 2; half++) {
                int r = r0 + half * 8;
                float v0 = acc[mt][nt][half * 2 + 0];
                float v1 = acc[mt][nt][half * 2 + 1];
                if (bias) { v0 += bias[c0i]; v1 += bias[c0i + 1]; }
                if (ACT == 1) {
                    v0 = v0 * (1.0f / (1.0f + __expf(-v0)));
                    v1 = v1 * (1.0f / (1.0f + __expf(-v1)));
                }
                if (RES) {
                    const float* rp = res + (size_t)r * N + c0i;
                    v0 += rp[0]; v1 += rp[1];
                }
                if (TF32OUT) { v0 = f2tf(v0); v1 = f2tf(v1); }
                float2* cp = (float2*)(C + (size_t)r * N + c0i);
                *cp = make_float2(v0, v1);
            }
        }
    }
}
#define GEMM_SMEM_NT (NSTAGE * (AW + 16 * BPAD) * 4)
#define GEMM_SMEM_T  (NSTAGE * (AW + 128 * APAD) * 4)

// ---------------- 128x64-tile GEMM for narrow-N projections (out/dn) ----------
// Same pipeline & per-element accumulation order as gemm_tc (bit-identical C).
// Warp tile 32x32; per-stage SMEM 14.8KB -> 3 CTAs/SM; grid N/64 x M/128.
#define BPAD64 72
#define GEMM_SMEM_64 (NSTAGE * (AW + 16 * BPAD64) * 4)

template <int ACT, bool RES, bool TF32OUT>
__global__ __launch_bounds__(256, 3) void gemm_tc64(
    const float* __restrict__ A, const float* __restrict__ B,
    const float* __restrict__ bias, const float* __restrict__ res,
    float* __restrict__ C, int M, int N, int K) {
    constexpr int SW = AW + 16 * BPAD64;
    extern __shared__ float gsm[];

    const int tid  = threadIdx.x;
    const int lane = tid & 31, warp = tid >> 5;
    const int wm = warp >> 1, wn = warp & 1;
    const int m0 = blockIdx.y * 128, n0 = blockIdx.x * 64;
    const unsigned sbase = (unsigned)__cvta_generic_to_shared(gsm);

    float acc[2][4][4];
    #pragma unroll
    for (int i = 0; i < 2; i++)
        #pragma unroll
        for (int j = 0; j < 4; j++)
            #pragma unroll
            for (int q = 0; q < 4; q++) acc[i][j][q] = 0.0f;

    const int arow = tid >> 1, akoff = (tid & 1) * 8;
    const int brow = tid >> 4, bnoff = (tid & 15) * 4;   // 16 rows x 64 n, 1 float4/thr

    auto issue = [&](int stg, int k0) {
        const float* ap = A + (size_t)(m0 + arow) * K + k0 + akoff;
        unsigned ad = sbase + (stg * SW + arow * APAD + akoff) * 4;
        cp16(ad, ap); cp16(ad + 16, ap + 4);
        const float* bp = B + (size_t)(k0 + brow) * N + n0 + bnoff;
        unsigned bd = sbase + (stg * SW + AW + brow * BPAD64 + bnoff) * 4;
        cp16(bd, bp);
    };

    const int nslab = K / 16;
    #pragma unroll
    for (int s = 0; s < NSTAGE - 1; s++) {
        if (s < nslab) issue(s, s * 16);
        cp_commit();
    }

    for (int i = 0; i < nslab; i++) {
        cp_wait<NSTAGE - 2>();
        __syncthreads();

        const unsigned* Asf = (const unsigned*)(gsm + (i % NSTAGE) * SW);
        const unsigned* Bsf = Asf + AW;

        #pragma unroll
        for (int ks = 0; ks < 2; ks++) {
            const int kb = ks * 8;
            unsigned af[2][4], bf[4][2];
            #pragma unroll
            for (int mt = 0; mt < 2; mt++) {
                int m = wm * 32 + mt * 16 + (lane >> 2);
                int k = kb + (lane & 3);
                af[mt][0] = Asf[m * APAD + k];
                af[mt][1] = Asf[(m + 8) * APAD + k];
                af[mt][2] = Asf[m * APAD + k + 4];
                af[mt][3] = Asf[(m + 8) * APAD + k + 4];
            }
            #pragma unroll
            for (int nt = 0; nt < 4; nt++) {
                int n = wn * 32 + nt * 8 + (lane >> 2);
                int k = kb + (lane & 3);
                bf[nt][0] = Bsf[k * BPAD64 + n];
                bf[nt][1] = Bsf[(k + 4) * BPAD64 + n];
            }
            #pragma unroll
            for (int mt = 0; mt < 2; mt++)
                #pragma unroll
                for (int nt = 0; nt < 4; nt++)
                    mma_tf32(acc[mt][nt], af[mt], bf[nt]);
        }

        int j = i + NSTAGE - 1;
        if (j < nslab) issue(j % NSTAGE, j * 16);
        cp_commit();
    }

    #pragma unroll
    for (int mt = 0; mt < 2; mt++) {
        int r0 = m0 + wm * 32 + mt * 16 + (lane >> 2);
        #pragma unroll
        for (int nt = 0; nt < 4; nt++) {
            int c0i = n0 + wn * 32 + nt * 8 + 2 * (lane & 3);
            #pragma unroll
            for (int half = 0; half < 2; half++) {
                int r = r0 + half * 8;
                float v0 = acc[mt][nt][half * 2 + 0];
                float v1 = acc[mt][nt][half * 2 + 1];
                if (bias) { v0 += bias[c0i]; v1 += bias[c0i + 1]; }
                if (ACT == 1) {
                    v0 = v0 * (1.0f / (1.0f + __expf(-v0)));
                    v1 = v1 * (1.0f / (1.0f + __expf(-v1)));
                }
                if (RES) {
                    const float* rp = res + (size_t)r * N + c0i;
                    v0 += rp[0]; v1 += rp[1];
                }
                if (TF32OUT) { v0 = f2tf(v0); v1 = f2tf(v1); }
                float2* cp = (float2*)(C + (size_t)r * N + c0i);
                *cp = make_float2(v0, v1);
            }
        }
    }
}

// ---------------- flash attention: 64 queries x one (b,h) per block ------------
// Heavy-first scheduling: large-q0 blocks launch first (pure permutation).
#define QPAD 68
#define VPAD 72
#define ATTN_SMEM ((64*QPAD + 64*QPAD + 64*VPAD + 64*QPAD + 3*64) * 4)

__global__ __launch_bounds__(256) void attn_flash_k(
    const float* __restrict__ qkv, float* __restrict__ out) {
    extern __shared__ unsigned smem[];
    unsigned* Qs = smem;
    unsigned* Ks = Qs + 64 * QPAD;
    unsigned* Vs = Ks + 64 * QPAD;
    float*    Ss = (float*)(Vs + 64 * VPAD);
    float*    m_sm = Ss + 64 * QPAD;
    float*    l_sm = m_sm + 64;
    float*    sc_sm = l_sm + 64;

    const int q0 = ((int)gridDim.x - 1 - (int)blockIdx.x) * 64;  // heavy-first
    const int h  = blockIdx.y;
    const int b  = blockIdx.z;
    const int tid = threadIdx.x;
    const int lane = tid & 31, warp = tid >> 5;
    const int wm = warp >> 1, wn = warp & 1;

    const float* qbase = qkv + (size_t)(b * Tv) * QKVN + h * HDv;
    const float* kbase = qbase + Hv * HDv;
    const float* vbase = qbase + 2 * Hv * HDv;

    #pragma unroll
    for (int it = 0; it < 4; it++) {
        int e = tid + 256 * it;
        int r = e >> 4, d = (e & 15) * 4;
        float4 q4 = *(const float4*)(qbase + (size_t)(q0 + r) * QKVN + d);
        unsigned* dst = Qs + r * QPAD + d;
        dst[0] = __float_as_uint(q4.x * 0.125f);
        dst[1] = __float_as_uint(q4.y * 0.125f);
        dst[2] = __float_as_uint(q4.z * 0.125f);
        dst[3] = __float_as_uint(q4.w * 0.125f);
    }
    if (tid < 64) { m_sm[tid] = -1e30f; l_sm[tid] = 0.0f; }

    float acc_o[4][4];
    #pragma unroll
    for (int i = 0; i < 4; i++)
        #pragma unroll
        for (int j = 0; j < 4; j++) acc_o[i][j] = 0.0f;

    for (int c0 = 0; c0 <= q0; c0 += 64) {
        #pragma unroll
        for (int it = 0; it < 4; it++) {
            int e = tid + 256 * it;
            int r = e >> 4, d = (e & 15) * 4;
            float4 k4 = *(const float4*)(kbase + (size_t)(c0 + r) * QKVN + d);
            unsigned* kd = Ks + r * QPAD + d;
            kd[0] = __float_as_uint(k4.x); kd[1] = __float_as_uint(k4.y);
            kd[2] = __float_as_uint(k4.z); kd[3] = __float_as_uint(k4.w);
            float4 v4 = *(const float4*)(vbase + (size_t)(c0 + r) * QKVN + d);
            unsigned* vd = Vs + r * VPAD + d;
            vd[0] = __float_as_uint(v4.x); vd[1] = __float_as_uint(v4.y);
            vd[2] = __float_as_uint(v4.z); vd[3] = __float_as_uint(v4.w);
        }
        __syncthreads();

        float s_acc[4][4];
        #pragma unroll
        for (int i = 0; i < 4; i++)
            #pragma unroll
            for (int j = 0; j < 4; j++) s_acc[i][j] = 0.0f;
        #pragma unroll
        for (int kb = 0; kb < 64; kb += 8) {
            unsigned af[4], bf[4][2];
            int mr = wm * 16 + (lane >> 2);
            int kk = kb + (lane & 3);
            af[0] = Qs[mr * QPAD + kk];
            af[1] = Qs[(mr + 8) * QPAD + kk];
            af[2] = Qs[mr * QPAD + kk + 4];
            af[3] = Qs[(mr + 8) * QPAD + kk + 4];
            #pragma unroll
            for (int nt = 0; nt < 4; nt++) {
                int n = wn * 32 + nt * 8 + (lane >> 2);
                bf[nt][0] = Ks[n * QPAD + kb + (lane & 3)];
                bf[nt][1] = Ks[n * QPAD + kb + (lane & 3) + 4];
            }
            #pragma unroll
            for (int nt = 0; nt < 4; nt++)
                mma_tf32(s_acc[nt], af, bf[nt]);
        }
        const bool diag = (c0 == q0);
        #pragma unroll
        for (int nt = 0; nt < 4; nt++) {
            int c = wn * 32 + nt * 8 + 2 * (lane & 3);
            #pragma unroll
            for (int half = 0; half < 2; half++) {
                int r = wm * 16 + (lane >> 2) + half * 8;
                float v0 = s_acc[nt][half * 2 + 0];
                float v1 = s_acc[nt][half * 2 + 1];
                if (diag) {
                    if (c     > r) v0 = -1e30f;
                    if (c + 1 > r) v1 = -1e30f;
                }
                Ss[r * QPAD + c] = v0; Ss[r * QPAD + c + 1] = v1;
            }
        }
        __syncthreads();

        {
            int r = tid >> 2, g = tid & 3;
            float* row = Ss + r * QPAD;
            float cmax = -1e30f;
            #pragma unroll
            for (int j = 0; j < 16; j++) cmax = fmaxf(cmax, row[g + 4 * j]);
            cmax = fmaxf(cmax, __shfl_xor_sync(0xffffffffu, cmax, 1));
            cmax = fmaxf(cmax, __shfl_xor_sync(0xffffffffu, cmax, 2));
            float m_old = m_sm[r];
            float m_new = fmaxf(m_old, cmax);
            float csum = 0.0f;
            unsigned* prow = (unsigned*)row;
            #pragma unroll
            for (int j = 0; j < 16; j++) {
                float p = __expf(row[g + 4 * j] - m_new);
                csum += p;
                prow[g + 4 * j] = f2t(p);
            }
            csum += __shfl_xor_sync(0xffffffffu, csum, 1);
            csum += __shfl_xor_sync(0xffffffffu, csum, 2);
            if (g == 0) {
                float scale = __expf(m_old - m_new);
                sc_sm[r] = scale;
                l_sm[r] = l_sm[r] * scale + csum;
                m_sm[r] = m_new;
            }
        }
        __syncthreads();

        {
            int r1 = wm * 16 + (lane >> 2);
            float s1 = sc_sm[r1], s2 = sc_sm[r1 + 8];
            #pragma unroll
            for (int nt = 0; nt < 4; nt++) {
                acc_o[nt][0] *= s1; acc_o[nt][1] *= s1;
                acc_o[nt][2] *= s2; acc_o[nt][3] *= s2;
            }
        }
        const unsigned* Pu = (const unsigned*)Ss;
        #pragma unroll
        for (int kb = 0; kb < 64; kb += 8) {
            unsigned af[4], bf[4][2];
            int mr = wm * 16 + (lane >> 2);
            int kk = kb + (lane & 3);
            af[0] = Pu[mr * QPAD + kk];
            af[1] = Pu[(mr + 8) * QPAD + kk];
            af[2] = Pu[mr * QPAD + kk + 4];
            af[3] = Pu[(mr + 8) * QPAD + kk + 4];
            #pragma unroll
            for (int nt = 0; nt < 4; nt++) {
                int n = wn * 32 + nt * 8 + (lane >> 2);
                bf[nt][0] = Vs[(kb + (lane & 3)) * VPAD + n];
                bf[nt][1] = Vs[(kb + (lane & 3) + 4) * VPAD + n];
            }
            #pragma unroll
            for (int nt = 0; nt < 4; nt++)
                mma_tf32(acc_o[nt], af, bf[nt]);
        }
        __syncthreads();
    }

    {
        int r1 = wm * 16 + (lane >> 2);
        float inv1 = 1.0f / l_sm[r1], inv2 = 1.0f / l_sm[r1 + 8];
        #pragma unroll
        for (int nt = 0; nt < 4; nt++) {
            int c = wn * 32 + nt * 8 + 2 * (lane & 3);
            float* o1 = out + (size_t)(b * Tv + q0 + r1) * Dv + h * HDv + c;
            float* o2 = out + (size_t)(b * Tv + q0 + r1 + 8) * Dv + h * HDv + c;
            o1[0] = f2tf(acc_o[nt][0] * inv1); o1[1] = f2tf(acc_o[nt][1] * inv1);
            o2[0] = f2tf(acc_o[nt][2] * inv2); o2[1] = f2tf(acc_o[nt][3] * inv2);
        }
    }
}

// ---------------- driver ----------------
extern "C" void kernel_launch(void* const* d_in, const int* in_sizes, int n_in,
                              void* d_out, int out_size) {
    const int*   ids   = (const int*)  d_in[0];
    const float* te    = (const float*)d_in[1];
    const float* pe    = (const float*)d_in[2];
    const float* ln1_s = (const float*)d_in[3];
    const float* ln1_b = (const float*)d_in[4];
    const float* qkv_w = (const float*)d_in[5];
    const float* qkv_b = (const float*)d_in[6];
    const float* out_w = (const float*)d_in[7];
    const float* out_b = (const float*)d_in[8];
    const float* ln2_s = (const float*)d_in[9];
    const float* ln2_b = (const float*)d_in[10];
    const float* up_w  = (const float*)d_in[11];
    const float* up_b  = (const float*)d_in[12];
    const float* dn_w  = (const float*)d_in[13];
    const float* dn_b  = (const float*)d_in[14];
    const float* lnf_s = (const float*)d_in[15];
    const float* lnf_b = (const float*)d_in[16];
    float* logits = (float*)d_out;

    float *x, *lnb, *qkv, *att, *ff;
    float *wqkv, *wout, *wup, *wdn, *tet;
    cudaGetSymbolAddress((void**)&x,    g_x);
    cudaGetSymbolAddress((void**)&lnb,  g_ln);
    cudaGetSymbolAddress((void**)&qkv,  g_qkv);
    cudaGetSymbolAddress((void**)&att,  g_att);
    cudaGetSymbolAddress((void**)&ff,   g_ff);
    cudaGetSymbolAddress((void**)&wqkv, g_wqkv);
    cudaGetSymbolAddress((void**)&wout, g_wout);
    cudaGetSymbolAddress((void**)&wup,  g_wup);
    cudaGetSymbolAddress((void**)&wdn,  g_wdn);
    cudaGetSymbolAddress((void**)&tet,  g_te);

    cudaFuncSetAttribute(attn_flash_k,
                         cudaFuncAttributeMaxDynamicSharedMemorySize, ATTN_SMEM);
    cudaFuncSetAttribute(gemm_tc<false, 0, false, true>,
                         cudaFuncAttributeMaxDynamicSharedMemorySize, GEMM_SMEM_NT);
    cudaFuncSetAttribute(gemm_tc<false, 1, false, true>,
                         cudaFuncAttributeMaxDynamicSharedMemorySize, GEMM_SMEM_NT);
    cudaFuncSetAttribute(gemm_tc<true, 0, false, false>,
                         cudaFuncAttributeMaxDynamicSharedMemorySize, GEMM_SMEM_T);
    cudaFuncSetAttribute(gemm_tc64<0, true, false>,
                         cudaFuncAttributeMaxDynamicSharedMemorySize, GEMM_SMEM_64);

    // weight pre-conversion to tf32-canonical fp32
    {
        int n;
        n = Lv * Dv * QKVN / 4; cvt_k<<<(n + 255) / 256, 256>>>(qkv_w, wqkv, n);
        n = Lv * Dv * Dv   / 4; cvt_k<<<(n + 255) / 256, 256>>>(out_w, wout, n);
        n = Lv * Dv * DFv  / 4; cvt_k<<<(n + 255) / 256, 256>>>(up_w,  wup,  n);
        n = Lv * DFv * Dv  / 4; cvt_k<<<(n + 255) / 256, 256>>>(dn_w,  wdn,  n);
        n = Vv * Dv        / 4; cvt_k<<<(n + 255) / 256, 256>>>(te,    tet,  n);
    }

    embed_k<<<(Mv * Dv + 255) / 256, 256>>>(ids, te, pe, x);

    for (int i = 0; i < Lv; i++) {
        ln_k<<<Mv, 256>>>(x, ln1_s + (size_t)i * Dv, ln1_b + (size_t)i * Dv, lnb);
        gemm_tc<false, 0, false, true><<<dim3(QKVN / 128, Mv / 128), 256, GEMM_SMEM_NT>>>(
            lnb, wqkv + (size_t)i * Dv * QKVN, qkv_b + (size_t)i * QKVN,
            nullptr, qkv, Mv, QKVN, Dv);
        attn_flash_k<<<dim3(Tv / 64, Hv, Bv), 256, ATTN_SMEM>>>(qkv, att);
        gemm_tc64<0, true, false><<<dim3(Dv / 64, Mv / 128), 256, GEMM_SMEM_64>>>(
            att, wout + (size_t)i * Dv * Dv, out_b + (size_t)i * Dv,
            x, x, Mv, Dv, Dv);
        ln_k<<<Mv, 256>>>(x, ln2_s + (size_t)i * Dv, ln2_b + (size_t)i * Dv, lnb);
        gemm_tc<false, 1, false, true><<<dim3(DFv / 128, Mv / 128), 256, GEMM_SMEM_NT>>>(
            lnb, wup + (size_t)i * Dv * DFv, up_b + (size_t)i * DFv,
            nullptr, ff, Mv, DFv, Dv);
        gemm_tc64<0, true, false><<<dim3(Dv / 64, Mv / 128), 256, GEMM_SMEM_64>>>(
            ff, wdn + (size_t)i * DFv * Dv, dn_b + (size_t)i * Dv,
            x, x, Mv, Dv, DFv);
    }

    ln_k<<<Mv, 256>>>(x, lnf_s, lnf_b, lnb);
    gemm_tc<true, 0, false, false><<<dim3(Vv / 128, Mv / 128), 256, GEMM_SMEM_T>>>(
        lnb, tet, nullptr, nullptr, logits, Mv, Vv, Dv);
}

// round 12
// speedup vs baseline: 1.8365x; 1.6765x over previous
#include <cuda_runtime.h>
#include <cuda_fp16.h>
#include <math.h>

#define Bv   2
#define Tv   2048
#define Dv   768
#define Hv   12
#define HDv  64
#define Lv   4
#define DFv  3072
#define Vv   32000
#define Mv   (Bv*Tv)        /* 4096 rows */
#define QKVN (3*Hv*HDv)     /* 2304 */

// ---------------- scratch (static device globals; no allocs) ----------------
__device__ float  g_x  [Mv*Dv];     // residual stream (fp32)
__device__ float  g_qkv[Mv*QKVN];   // qkv projection (fp32, tf32-rounded)
__device__ __half g_ln [Mv*Dv];     // layernorm output (half)
__device__ __half g_att[Mv*Dv];     // attention output (half)
__device__ __half g_ff [Mv*DFv];    // ffn hidden (half)
// half weight copies, transposed to [N,K]
__device__ __half g_wqkv[Lv*QKVN*Dv];
__device__ __half g_wout[Lv*Dv*Dv];
__device__ __half g_wup [Lv*DFv*Dv];
__device__ __half g_wdn [Lv*Dv*DFv];
__device__ __half g_te  [Vv*Dv];    // te is [V,D] = [N,K] already

// ---------------- helpers ----------------
__device__ __forceinline__ unsigned f2t(float f) {
    unsigned u; asm("cvt.rna.tf32.f32 %0, %1;" : "=r"(u) : "f"(f)); return u;
}
__device__ __forceinline__ float f2tf(float f) { return __uint_as_float(f2t(f)); }
__device__ __forceinline__ void mma_tf32(float* c, const unsigned* a, const unsigned* b) {
    asm volatile(
        "mma.sync.aligned.m16n8k8.row.col.f32.tf32.tf32.f32 "
        "{%0,%1,%2,%3}, {%4,%5,%6,%7}, {%8,%9}, {%0,%1,%2,%3};\n"
        : "+f"(c[0]), "+f"(c[1]), "+f"(c[2]), "+f"(c[3])
        : "r"(a[0]), "r"(a[1]), "r"(a[2]), "r"(a[3]), "r"(b[0]), "r"(b[1]));
}
__device__ __forceinline__ void mma_f16(float* c, const unsigned* a, const unsigned* b) {
    asm volatile(
        "mma.sync.aligned.m16n8k16.row.col.f32.f16.f16.f32 "
        "{%0,%1,%2,%3}, {%4,%5,%6,%7}, {%8,%9}, {%0,%1,%2,%3};\n"
        : "+f"(c[0]), "+f"(c[1]), "+f"(c[2]), "+f"(c[3])
        : "r"(a[0]), "r"(a[1]), "r"(a[2]), "r"(a[3]), "r"(b[0]), "r"(b[1]));
}
__device__ __forceinline__ void cp16(unsigned sdst, const void* g) {
    asm volatile("cp.async.cg.shared.global [%0], [%1], 16;" :: "r"(sdst), "l"(g));
}
__device__ __forceinline__ void cp_commit() { asm volatile("cp.async.commit_group;"); }
template <int N>
__device__ __forceinline__ void cp_wait() {
    asm volatile("cp.async.wait_group %0;" :: "n"(N));
}

// ---------------- weight prep ----------------
// transpose + half-convert: W[K,N] fp32 -> Wt[N,K] half (per layer z)
__global__ void thsplit_k(const float* __restrict__ W, __half* __restrict__ o,
                          int K, int N) {
    __shared__ float t[32][33];
    const float* Wl = W + (size_t)blockIdx.z * K * N;
    __half* ol = o + (size_t)blockIdx.z * K * N;
    int kb = blockIdx.y * 32, nb = blockIdx.x * 32;
    int tx = threadIdx.x, ty = threadIdx.y;   // 32 x 8
    #pragma unroll
    for (int i = 0; i < 32; i += 8)
        t[ty + i][tx] = Wl[(size_t)(kb + ty + i) * N + nb + tx];
    __syncthreads();
    #pragma unroll
    for (int i = 0; i < 32; i += 8)
        ol[(size_t)(nb + ty + i) * K + kb + tx] = __float2half(t[tx][ty + i]);
}
// elementwise fp32 -> half
__global__ void hcvt_k(const float* __restrict__ in, __half* __restrict__ out, int n4) {
    int i = blockIdx.x * blockDim.x + threadIdx.x;
    if (i >= n4) return;
    float4 v = ((const float4*)in)[i];
    __half2* o = (__half2*)out;
    o[i * 2    ] = __floats2half2_rn(v.x, v.y);
    o[i * 2 + 1] = __floats2half2_rn(v.z, v.w);
}

// ---------------- embedding ----------------
__global__ void embed_k(const int* __restrict__ ids, const float* __restrict__ te,
                        const float* __restrict__ pe, float* __restrict__ x) {
    int i = blockIdx.x * blockDim.x + threadIdx.x;
    if (i >= Mv * Dv) return;
    int r = i / Dv, d = i - r * Dv;
    int t = r % Tv;
    x[i] = te[(size_t)ids[r] * Dv + d] + pe[(size_t)t * Dv + d];
}

// ---------------- layernorm (writes half) ----------------
__global__ void ln_k(const float* __restrict__ x, const float* __restrict__ s,
                     const float* __restrict__ bb, __half* __restrict__ y) {
    int r = blockIdx.x;
    const float* xr = x + (size_t)r * Dv;
    __half*      yr = y + (size_t)r * Dv;
    __shared__ float red[8];
    int tid = threadIdx.x; // 256
    float v0 = xr[tid], v1 = xr[tid + 256], v2 = xr[tid + 512];
    float sum = v0 + v1 + v2;
    #pragma unroll
    for (int o = 16; o; o >>= 1) sum += __shfl_xor_sync(0xffffffffu, sum, o);
    if ((tid & 31) == 0) red[tid >> 5] = sum;
    __syncthreads();
    float mu = (red[0]+red[1]+red[2]+red[3]+red[4]+red[5]+red[6]+red[7]) * (1.0f/Dv);
    float d0 = v0 - mu, d1 = v1 - mu, d2 = v2 - mu;
    float sq = d0*d0 + d1*d1 + d2*d2;
    __syncthreads();
    #pragma unroll
    for (int o = 16; o; o >>= 1) sq += __shfl_xor_sync(0xffffffffu, sq, o);
    if ((tid & 31) == 0) red[tid >> 5] = sq;
    __syncthreads();
    float var = (red[0]+red[1]+red[2]+red[3]+red[4]+red[5]+red[6]+red[7]) * (1.0f/Dv);
    float rstd = rsqrtf(var + 1e-5f);
    yr[tid      ] = __float2half(d0 * rstd * s[tid      ] + bb[tid      ]);
    yr[tid + 256] = __float2half(d1 * rstd * s[tid + 256] + bb[tid + 256]);
    yr[tid + 512] = __float2half(d2 * rstd * s[tid + 512] + bb[tid + 512]);
}

// ---------------- fp16 tensor-core GEMM (128x128): C = A @ B^T ------------------
// A[M,K] half, B[N,K] half (pre-transposed). BK=32 halves/slab, 8 warps (4x2),
// warp tile 32x64, m16n8k16, 5-stage cp.async pipeline.
// OUT: 0 = fp32, 1 = fp32 tf32-rounded, 2 = half.
#define HSTU 20                    /* u32 per smem row (32 data halves + 8 pad) */
#define NSTG 5
#define TILEW (128*HSTU)           /* u32 per 128-row tile */
#define SWU (2*TILEW)              /* u32 per stage */
#define GEMM_H_SMEM (NSTG * SWU * 4)

template <int ACT, bool RES, int OUT>
__global__ __launch_bounds__(256, 2) void gemm_h(
    const __half* __restrict__ A, const __half* __restrict__ B,
    const float* __restrict__ bias, const float* __restrict__ res,
    float* __restrict__ C, __half* __restrict__ Ch, int M, int N, int K) {
    extern __shared__ unsigned ghsm[];
    const int tid  = threadIdx.x;
    const int lane = tid & 31, warp = tid >> 5;
    const int wm = warp >> 1, wn = warp & 1;
    const int m0 = blockIdx.y * 128, n0 = blockIdx.x * 128;
    const unsigned sbase = (unsigned)__cvta_generic_to_shared(ghsm);

    float acc[2][8][4];
    #pragma unroll
    for (int i = 0; i < 2; i++)
        #pragma unroll
        for (int j = 0; j < 8; j++)
            #pragma unroll
            for (int q = 0; q < 4; q++) acc[i][j][q] = 0.0f;

    auto issue = [&](int stg, int k0) {
        #pragma unroll
        for (int i = 0; i < 2; i++) {
            int c = tid + 256 * i;              // 0..511
            int row = c >> 2, off = (c & 3) * 8;  // halves
            unsigned ad = sbase + (stg * SWU + row * HSTU) * 4 + off * 2;
            cp16(ad, A + (size_t)(m0 + row) * K + k0 + off);
            cp16(ad + TILEW * 4, B + (size_t)(n0 + row) * K + k0 + off);
        }
    };

    const int nslab = K / 32;
    #pragma unroll
    for (int s = 0; s < NSTG - 1; s++) {
        if (s < nslab) issue(s, s * 32);
        cp_commit();
    }

    for (int i = 0; i < nslab; i++) {
        cp_wait<NSTG - 2>();
        __syncthreads();

        const unsigned* Asf = ghsm + (i % NSTG) * SWU;
        const unsigned* Bsf = Asf + TILEW;

        #pragma unroll
        for (int ks = 0; ks < 2; ks++) {
            const int kb = ks * 8;                 // u32 offset within row
            unsigned af[2][4], bf[8][2];
            #pragma unroll
            for (int mt = 0; mt < 2; mt++) {
                int m = wm * 32 + mt * 16 + (lane >> 2);
                int k = kb + (lane & 3);
                af[mt][0] = Asf[m * HSTU + k];
                af[mt][1] = Asf[(m + 8) * HSTU + k];
                af[mt][2] = Asf[m * HSTU + k + 4];
                af[mt][3] = Asf[(m + 8) * HSTU + k + 4];
            }
            #pragma unroll
            for (int nt = 0; nt < 8; nt++) {
                int n = wn * 64 + nt * 8 + (lane >> 2);
                int k = kb + (lane & 3);
                bf[nt][0] = Bsf[n * HSTU + k];
                bf[nt][1] = Bsf[n * HSTU + k + 4];
            }
            #pragma unroll
            for (int mt = 0; mt < 2; mt++)
                #pragma unroll
                for (int nt = 0; nt < 8; nt++)
                    mma_f16(acc[mt][nt], af[mt], bf[nt]);
        }

        int j = i + NSTG - 1;
        if (j < nslab) issue(j % NSTG, j * 32);
        cp_commit();
    }

    #pragma unroll
    for (int mt = 0; mt < 2; mt++) {
        int r0 = m0 + wm * 32 + mt * 16 + (lane >> 2);
        #pragma unroll
        for (int nt = 0; nt < 8; nt++) {
            int c0i = n0 + wn * 64 + nt * 8 + 2 * (lane & 3);
            #pragma unroll
            for (int half = 0; half < 2; half++) {
                int r = r0 + half * 8;
                float v0 = acc[mt][nt][half * 2 + 0];
                float v1 = acc[mt][nt][half * 2 + 1];
                if (bias) { v0 += bias[c0i]; v1 += bias[c0i + 1]; }
                if (ACT == 1) {
                    v0 = v0 * (1.0f / (1.0f + __expf(-v0)));
                    v1 = v1 * (1.0f / (1.0f + __expf(-v1)));
                }
                if (RES) {
                    const float* rp = res + (size_t)r * N + c0i;
                    v0 += rp[0]; v1 += rp[1];
                }
                if (OUT == 2) {
                    *(__half2*)(Ch + (size_t)r * N + c0i) = __floats2half2_rn(v0, v1);
                } else {
                    if (OUT == 1) { v0 = f2tf(v0); v1 = f2tf(v1); }
                    *(float2*)(C + (size_t)r * N + c0i) = make_float2(v0, v1);
                }
            }
        }
    }
}

// ---------------- fp16 GEMM, 128x64 tile (out/dn projections) ------------------
// Warp tile 32x32, 4 stages -> 3 CTAs/SM. Same frag mapping.
#define NSTG4 4
#define SW64 (TILEW + 64*HSTU)
#define GEMM_H64_SMEM (NSTG4 * SW64 * 4)

template <int ACT, bool RES, int OUT>
__global__ __launch_bounds__(256, 3) void gemm_h64(
    const __half* __restrict__ A, const __half* __restrict__ B,
    const float* __restrict__ bias, const float* __restrict__ res,
    float* __restrict__ C, __half* __restrict__ Ch, int M, int N, int K) {
    extern __shared__ unsigned ghsm[];
    const int tid  = threadIdx.x;
    const int lane = tid & 31, warp = tid >> 5;
    const int wm = warp >> 1, wn = warp & 1;
    const int m0 = blockIdx.y * 128, n0 = blockIdx.x * 64;
    const unsigned sbase = (unsigned)__cvta_generic_to_shared(ghsm);

    float acc[2][4][4];
    #pragma unroll
    for (int i = 0; i < 2; i++)
        #pragma unroll
        for (int j = 0; j < 4; j++)
            #pragma unroll
            for (int q = 0; q < 4; q++) acc[i][j][q] = 0.0f;

    auto issue = [&](int stg, int k0) {
        #pragma unroll
        for (int i = 0; i < 3; i++) {
            int c = tid + 256 * i;              // 0..767
            if (c < 512) {                      // A: 128 rows x 4 chunks
                int row = c >> 2, off = (c & 3) * 8;
                unsigned ad = sbase + (stg * SW64 + row * HSTU) * 4 + off * 2;
                cp16(ad, A + (size_t)(m0 + row) * K + k0 + off);
            } else {                            // B: 64 rows x 4 chunks
                int cb = c - 512;
                int row = cb >> 2, off = (cb & 3) * 8;
                unsigned bd = sbase + (stg * SW64 + TILEW + row * HSTU) * 4 + off * 2;
                cp16(bd, B + (size_t)(n0 + row) * K + k0 + off);
            }
        }
    };

    const int nslab = K / 32;
    #pragma unroll
    for (int s = 0; s < NSTG4 - 1; s++) {
        if (s < nslab) issue(s, s * 32);
        cp_commit();
    }

    for (int i = 0; i < nslab; i++) {
        cp_wait<NSTG4 - 2>();
        __syncthreads();

        const unsigned* Asf = ghsm + (i % NSTG4) * SW64;
        const unsigned* Bsf = Asf + TILEW;

        #pragma unroll
        for (int ks = 0; ks < 2; ks++) {
            const int kb = ks * 8;
            unsigned af[2][4], bf[4][2];
            #pragma unroll
            for (int mt = 0; mt < 2; mt++) {
                int m = wm * 32 + mt * 16 + (lane >> 2);
                int k = kb + (lane & 3);
                af[mt][0] = Asf[m * HSTU + k];
                af[mt][1] = Asf[(m + 8) * HSTU + k];
                af[mt][2] = Asf[m * HSTU + k + 4];
                af[mt][3] = Asf[(m + 8) * HSTU + k + 4];
            }
            #pragma unroll
            for (int nt = 0; nt < 4; nt++) {
                int n = wn * 32 + nt * 8 + (lane >> 2);
                int k = kb + (lane & 3);
                bf[nt][0] = Bsf[n * HSTU + k];
                bf[nt][1] = Bsf[n * HSTU + k + 4];
            }
            #pragma unroll
            for (int mt = 0; mt < 2; mt++)
                #pragma unroll
                for (int nt = 0; nt < 4; nt++)
                    mma_f16(acc[mt][nt], af[mt], bf[nt]);
        }

        int j = i + NSTG4 - 1;
        if (j < nslab) issue(j % NSTG4, j * 32);
        cp_commit();
    }

    #pragma unroll
    for (int mt = 0; mt < 2; mt++) {
        int r0 = m0 + wm * 32 + mt * 16 + (lane >> 2);
        #pragma unroll
        for (int nt = 0; nt < 4; nt++) {
            int c0i = n0 + wn * 32 + nt * 8 + 2 * (lane & 3);
            #pragma unroll
            for (int half = 0; half < 2; half++) {
                int r = r0 + half * 8;
                float v0 = acc[mt][nt][half * 2 + 0];
                float v1 = acc[mt][nt][half * 2 + 1];
                if (bias) { v0 += bias[c0i]; v1 += bias[c0i + 1]; }
                if (ACT == 1) {
                    v0 = v0 * (1.0f / (1.0f + __expf(-v0)));
                    v1 = v1 * (1.0f / (1.0f + __expf(-v1)));
                }
                if (RES) {
                    const float* rp = res + (size_t)r * N + c0i;
                    v0 += rp[0]; v1 += rp[1];
                }
                if (OUT == 2) {
                    *(__half2*)(Ch + (size_t)r * N + c0i) = __floats2half2_rn(v0, v1);
                } else {
                    if (OUT == 1) { v0 = f2tf(v0); v1 = f2tf(v1); }
                    *(float2*)(C + (size_t)r * N + c0i) = make_float2(v0, v1);
                }
            }
        }
    }
}

// ---------------- flash attention (tf32 mma), heavy-first, half output ---------
#define QPAD 68
#define VPAD 72
#define ATTN_SMEM ((64*QPAD + 64*QPAD + 64*VPAD + 64*QPAD + 3*64) * 4)

__global__ __launch_bounds__(256) void attn_flash_k(
    const float* __restrict__ qkv, __half* __restrict__ out) {
    extern __shared__ unsigned asm_[];
    unsigned* Qs = asm_;
    unsigned* Ks = Qs + 64 * QPAD;
    unsigned* Vs = Ks + 64 * QPAD;
    float*    Ss = (float*)(Vs + 64 * VPAD);
    float*    m_sm = Ss + 64 * QPAD;
    float*    l_sm = m_sm + 64;
    float*    sc_sm = l_sm + 64;

    const int q0 = ((int)gridDim.x - 1 - (int)blockIdx.x) * 64;  // heavy-first
    const int h  = blockIdx.y;
    const int b  = blockIdx.z;
    const int tid = threadIdx.x;
    const int lane = tid & 31, warp = tid >> 5;
    const int wm = warp >> 1, wn = warp & 1;

    const float* qbase = qkv + (size_t)(b * Tv) * QKVN + h * HDv;
    const float* kbase = qbase + Hv * HDv;
    const float* vbase = qbase + 2 * Hv * HDv;

    #pragma unroll
    for (int it = 0; it < 4; it++) {
        int e = tid + 256 * it;
        int r = e >> 4, d = (e & 15) * 4;
        float4 q4 = *(const float4*)(qbase + (size_t)(q0 + r) * QKVN + d);
        unsigned* dst = Qs + r * QPAD + d;
        dst[0] = __float_as_uint(q4.x * 0.125f);
        dst[1] = __float_as_uint(q4.y * 0.125f);
        dst[2] = __float_as_uint(q4.z * 0.125f);
        dst[3] = __float_as_uint(q4.w * 0.125f);
    }
    if (tid < 64) { m_sm[tid] = -1e30f; l_sm[tid] = 0.0f; }

    float acc_o[4][4];
    #pragma unroll
    for (int i = 0; i < 4; i++)
        #pragma unroll
        for (int j = 0; j < 4; j++) acc_o[i][j] = 0.0f;

    for (int c0 = 0; c0 <= q0; c0 += 64) {
        #pragma unroll
        for (int it = 0; it < 4; it++) {
            int e = tid + 256 * it;
            int r = e >> 4, d = (e & 15) * 4;
            float4 k4 = *(const float4*)(kbase + (size_t)(c0 + r) * QKVN + d);
            unsigned* kd = Ks + r * QPAD + d;
            kd[0] = __float_as_uint(k4.x); kd[1] = __float_as_uint(k4.y);
            kd[2] = __float_as_uint(k4.z); kd[3] = __float_as_uint(k4.w);
            float4 v4 = *(const float4*)(vbase + (size_t)(c0 + r) * QKVN + d);
            unsigned* vd = Vs + r * VPAD + d;
            vd[0] = __float_as_uint(v4.x); vd[1] = __float_as_uint(v4.y);
            vd[2] = __float_as_uint(v4.z); vd[3] = __float_as_uint(v4.w);
        }
        __syncthreads();

        float s_acc[4][4];
        #pragma unroll
        for (int i = 0; i < 4; i++)
            #pragma unroll
            for (int j = 0; j < 4; j++) s_acc[i][j] = 0.0f;
        #pragma unroll
        for (int kb = 0; kb < 64; kb += 8) {
            unsigned af[4], bf[4][2];
            int mr = wm * 16 + (lane >> 2);
            int kk = kb + (lane & 3);
            af[0] = Qs[mr * QPAD + kk];
            af[1] = Qs[(mr + 8) * QPAD + kk];
            af[2] = Qs[mr * QPAD + kk + 4];
            af[3] = Qs[(mr + 8) * QPAD + kk + 4];
            #pragma unroll
            for (int nt = 0; nt < 4; nt++) {
                int n = wn * 32 + nt * 8 + (lane >> 2);
                bf[nt][0] = Ks[n * QPAD + kb + (lane & 3)];
                bf[nt][1] = Ks[n * QPAD + kb + (lane & 3) + 4];
            }
            #pragma unroll
            for (int nt = 0; nt < 4; nt++)
                mma_tf32(s_acc[nt], af, bf[nt]);
        }
        const bool diag = (c0 == q0);
        #pragma unroll
        for (int nt = 0; nt < 4; nt++) {
            int c = wn * 32 + nt * 8 + 2 * (lane & 3);
            #pragma unroll
            for (int half = 0; half < 2; half++) {
                int r = wm * 16 + (lane >> 2) + half * 8;
                float v0 = s_acc[nt][half * 2 + 0];
                float v1 = s_acc[nt][half * 2 + 1];
                if (diag) {
                    if (c     > r) v0 = -1e30f;
                    if (c + 1 > r) v1 = -1e30f;
                }
                Ss[r * QPAD + c] = v0; Ss[r * QPAD + c + 1] = v1;
            }
        }
        __syncthreads();

        {
            int r = tid >> 2, g = tid & 3;
            float* row = Ss + r * QPAD;
            float cmax = -1e30f;
            #pragma unroll
            for (int j = 0; j < 16; j++) cmax = fmaxf(cmax, row[g + 4 * j]);
            cmax = fmaxf(cmax, __shfl_xor_sync(0xffffffffu, cmax, 1));
            cmax = fmaxf(cmax, __shfl_xor_sync(0xffffffffu, cmax, 2));
            float m_old = m_sm[r];
            float m_new = fmaxf(m_old, cmax);
            float csum = 0.0f;
            unsigned* prow = (unsigned*)row;
            #pragma unroll
            for (int j = 0; j < 16; j++) {
                float p = __expf(row[g + 4 * j] - m_new);
                csum += p;
                prow[g + 4 * j] = f2t(p);
            }
            csum += __shfl_xor_sync(0xffffffffu, csum, 1);
            csum += __shfl_xor_sync(0xffffffffu, csum, 2);
            if (g == 0) {
                float scale = __expf(m_old - m_new);
                sc_sm[r] = scale;
                l_sm[r] = l_sm[r] * scale + csum;
                m_sm[r] = m_new;
            }
        }
        __syncthreads();

        {
            int r1 = wm * 16 + (lane >> 2);
            float s1 = sc_sm[r1], s2 = sc_sm[r1 + 8];
            #pragma unroll
            for (int nt = 0; nt < 4; nt++) {
                acc_o[nt][0] *= s1; acc_o[nt][1] *= s1;
                acc_o[nt][2] *= s2; acc_o[nt][3] *= s2;
            }
        }
        const unsigned* Pu = (const unsigned*)Ss;
        #pragma unroll
        for (int kb = 0; kb < 64; kb += 8) {
            unsigned af[4], bf[4][2];
            int mr = wm * 16 + (lane >> 2);
            int kk = kb + (lane & 3);
            af[0] = Pu[mr * QPAD + kk];
            af[1] = Pu[(mr + 8) * QPAD + kk];
            af[2] = Pu[mr * QPAD + kk + 4];
            af[3] = Pu[(mr + 8) * QPAD + kk + 4];
            #pragma unroll
            for (int nt = 0; nt < 4; nt++) {
                int n = wn * 32 + nt * 8 + (lane >> 2);
                bf[nt][0] = Vs[(kb + (lane & 3)) * VPAD + n];
                bf[nt][1] = Vs[(kb + (lane & 3) + 4) * VPAD + n];
            }
            #pragma unroll
            for (int nt = 0; nt < 4; nt++)
                mma_tf32(acc_o[nt], af, bf[nt]);
        }
        __syncthreads();
    }

    {
        int r1 = wm * 16 + (lane >> 2);
        float inv1 = 1.0f / l_sm[r1], inv2 = 1.0f / l_sm[r1 + 8];
        #pragma unroll
        for (int nt = 0; nt < 4; nt++) {
            int c = wn * 32 + nt * 8 + 2 * (lane & 3);
            __half* o1 = out + (size_t)(b * Tv + q0 + r1) * Dv + h * HDv + c;
            __half* o2 = out + (size_t)(b * Tv + q0 + r1 + 8) * Dv + h * HDv + c;
            *(__half2*)o1 = __floats2half2_rn(acc_o[nt][0] * inv1, acc_o[nt][1] * inv1);
            *(__half2*)o2 = __floats2half2_rn(acc_o[nt][2] * inv2, acc_o[nt][3] * inv2);
        }
    }
}

// ---------------- driver ----------------
extern "C" void kernel_launch(void* const* d_in, const int* in_sizes, int n_in,
                              void* d_out, int out_size) {
    const int*   ids   = (const int*)  d_in[0];
    const float* te    = (const float*)d_in[1];
    const float* pe    = (const float*)d_in[2];
    const float* ln1_s = (const float*)d_in[3];
    const float* ln1_b = (const float*)d_in[4];
    const float* qkv_w = (const float*)d_in[5];
    const float* qkv_b = (const float*)d_in[6];
    const float* out_w = (const float*)d_in[7];
    const float* out_b = (const float*)d_in[8];
    const float* ln2_s = (const float*)d_in[9];
    const float* ln2_b = (const float*)d_in[10];
    const float* up_w  = (const float*)d_in[11];
    const float* up_b  = (const float*)d_in[12];
    const float* dn_w  = (const float*)d_in[13];
    const float* dn_b  = (const float*)d_in[14];
    const float* lnf_s = (const float*)d_in[15];
    const float* lnf_b = (const float*)d_in[16];
    float* logits = (float*)d_out;

    float *x, *qkv;
    __half *lnb, *att, *ff, *wqkv, *wout, *wup, *wdn, *teh;
    cudaGetSymbolAddress((void**)&x,    g_x);
    cudaGetSymbolAddress((void**)&qkv,  g_qkv);
    cudaGetSymbolAddress((void**)&lnb,  g_ln);
    cudaGetSymbolAddress((void**)&att,  g_att);
    cudaGetSymbolAddress((void**)&ff,   g_ff);
    cudaGetSymbolAddress((void**)&wqkv, g_wqkv);
    cudaGetSymbolAddress((void**)&wout, g_wout);
    cudaGetSymbolAddress((void**)&wup,  g_wup);
    cudaGetSymbolAddress((void**)&wdn,  g_wdn);
    cudaGetSymbolAddress((void**)&teh,  g_te);

    cudaFuncSetAttribute(attn_flash_k,
                         cudaFuncAttributeMaxDynamicSharedMemorySize, ATTN_SMEM);
    cudaFuncSetAttribute(gemm_h<0, false, 1>,
                         cudaFuncAttributeMaxDynamicSharedMemorySize, GEMM_H_SMEM);
    cudaFuncSetAttribute(gemm_h<1, false, 2>,
                         cudaFuncAttributeMaxDynamicSharedMemorySize, GEMM_H_SMEM);
    cudaFuncSetAttribute(gemm_h<0, false, 0>,
                         cudaFuncAttributeMaxDynamicSharedMemorySize, GEMM_H_SMEM);
    cudaFuncSetAttribute(gemm_h64<0, true, 0>,
                         cudaFuncAttributeMaxDynamicSharedMemorySize, GEMM_H64_SMEM);

    // ---- weight prep: transpose + half-convert (every launch; deterministic) ----
    {
        dim3 blk(32, 8);
        thsplit_k<<<dim3(QKVN / 32, Dv / 32, Lv), blk>>>(qkv_w, wqkv, Dv, QKVN);
        thsplit_k<<<dim3(Dv / 32,   Dv / 32, Lv), blk>>>(out_w, wout, Dv, Dv);
        thsplit_k<<<dim3(DFv / 32,  Dv / 32, Lv), blk>>>(up_w,  wup,  Dv, DFv);
        thsplit_k<<<dim3(Dv / 32,  DFv / 32, Lv), blk>>>(dn_w,  wdn,  DFv, Dv);
        int n4 = Vv * Dv / 4;
        hcvt_k<<<(n4 + 255) / 256, 256>>>(te, teh, n4);
    }

    embed_k<<<(Mv * Dv + 255) / 256, 256>>>(ids, te, pe, x);

    for (int i = 0; i < Lv; i++) {
        ln_k<<<Mv, 256>>>(x, ln1_s + (size_t)i * Dv, ln1_b + (size_t)i * Dv, lnb);
        gemm_h<0, false, 1><<<dim3(QKVN / 128, Mv / 128), 256, GEMM_H_SMEM>>>(
            lnb, wqkv + (size_t)i * QKVN * Dv, qkv_b + (size_t)i * QKVN,
            nullptr, qkv, nullptr, Mv, QKVN, Dv);
        attn_flash_k<<<dim3(Tv / 64, Hv, Bv), 256, ATTN_SMEM>>>(qkv, att);
        gemm_h64<0, true, 0><<<dim3(Dv / 64, Mv / 128), 256, GEMM_H64_SMEM>>>(
            att, wout + (size_t)i * Dv * Dv, out_b + (size_t)i * Dv,
            x, x, nullptr, Mv, Dv, Dv);
        ln_k<<<Mv, 256>>>(x, ln2_s + (size_t)i * Dv, ln2_b + (size_t)i * Dv, lnb);
        gemm_h<1, false, 2><<<dim3(DFv / 128, Mv / 128), 256, GEMM_H_SMEM>>>(
            lnb, wup + (size_t)i * DFv * Dv, up_b + (size_t)i * DFv,
            nullptr, nullptr, ff, Mv, DFv, Dv);
        gemm_h64<0, true, 0><<<dim3(Dv / 64, Mv / 128), 256, GEMM_H64_SMEM>>>(
            ff, wdn + (size_t)i * Dv * DFv, dn_b + (size_t)i * Dv,
            x, x, nullptr, Mv, Dv, DFv);
    }

    ln_k<<<Mv, 256>>>(x, lnf_s, lnf_b, lnb);
    gemm_h<0, false, 0><<<dim3(Vv / 128, Mv / 128), 256, GEMM_H_SMEM>>>(
        lnb, teh, nullptr, nullptr, logits, nullptr, Mv, Vv, Dv);
}

// round 14
// speedup vs baseline: 1.8985x; 1.0337x over previous
#include <cuda_runtime.h>
#include <cuda_fp16.h>
#include <math.h>

#define Bv   2
#define Tv   2048
#define Dv   768
#define Hv   12
#define HDv  64
#define Lv   4
#define DFv  3072
#define Vv   32000
#define Mv   (Bv*Tv)        /* 4096 rows */
#define QKVN (3*Hv*HDv)     /* 2304 */

// ---------------- scratch (static device globals; no allocs) ----------------
__device__ float  g_x   [Mv*Dv];     // residual stream (fp32)
__device__ __half g_qkvh[Mv*QKVN];   // qkv projection (half)
__device__ __half g_ln  [Mv*Dv];     // layernorm output (half)
__device__ __half g_att [Mv*Dv];     // attention output (half)
__device__ __half g_ff  [Mv*DFv];    // ffn hidden (half)
// half weight copies, transposed to [N,K]
__device__ __half g_wqkv[Lv*QKVN*Dv];
__device__ __half g_wout[Lv*Dv*Dv];
__device__ __half g_wup [Lv*DFv*Dv];
__device__ __half g_wdn [Lv*Dv*DFv];
__device__ __half g_te  [Vv*Dv];     // te is [V,D] = [N,K] already

// ---------------- helpers ----------------
__device__ __forceinline__ void mma_f16(float* c, const unsigned* a, const unsigned* b) {
    asm volatile(
        "mma.sync.aligned.m16n8k16.row.col.f32.f16.f16.f32 "
        "{%0,%1,%2,%3}, {%4,%5,%6,%7}, {%8,%9}, {%0,%1,%2,%3};\n"
        : "+f"(c[0]), "+f"(c[1]), "+f"(c[2]), "+f"(c[3])
        : "r"(a[0]), "r"(a[1]), "r"(a[2]), "r"(a[3]), "r"(b[0]), "r"(b[1]));
}
__device__ __forceinline__ void cp16(unsigned sdst, const void* g) {
    asm volatile("cp.async.cg.shared.global [%0], [%1], 16;" :: "r"(sdst), "l"(g));
}
__device__ __forceinline__ void cp_commit() { asm volatile("cp.async.commit_group;"); }
template <int N>
__device__ __forceinline__ void cp_wait() {
    asm volatile("cp.async.wait_group %0;" :: "n"(N));
}

// ---------------- weight prep ----------------
__global__ void thsplit_k(const float* __restrict__ W, __half* __restrict__ o,
                          int K, int N) {
    __shared__ float t[32][33];
    const float* Wl = W + (size_t)blockIdx.z * K * N;
    __half* ol = o + (size_t)blockIdx.z * K * N;
    int kb = blockIdx.y * 32, nb = blockIdx.x * 32;
    int tx = threadIdx.x, ty = threadIdx.y;   // 32 x 8
    #pragma unroll
    for (int i = 0; i < 32; i += 8)
        t[ty + i][tx] = Wl[(size_t)(kb + ty + i) * N + nb + tx];
    __syncthreads();
    #pragma unroll
    for (int i = 0; i < 32; i += 8)
        ol[(size_t)(nb + ty + i) * K + kb + tx] = __float2half(t[tx][ty + i]);
}
__global__ void hcvt_k(const float* __restrict__ in, __half* __restrict__ out, int n4) {
    int i = blockIdx.x * blockDim.x + threadIdx.x;
    if (i >= n4) return;
    float4 v = ((const float4*)in)[i];
    __half2* o = (__half2*)out;
    o[i * 2    ] = __floats2half2_rn(v.x, v.y);
    o[i * 2 + 1] = __floats2half2_rn(v.z, v.w);
}

// ---------------- embedding ----------------
__global__ void embed_k(const int* __restrict__ ids, const float* __restrict__ te,
                        const float* __restrict__ pe, float* __restrict__ x) {
    int i = blockIdx.x * blockDim.x + threadIdx.x;
    if (i >= Mv * Dv) return;
    int r = i / Dv, d = i - r * Dv;
    int t = r % Tv;
    x[i] = te[(size_t)ids[r] * Dv + d] + pe[(size_t)t * Dv + d];
}

// ---------------- layernorm (writes half) ----------------
__global__ void ln_k(const float* __restrict__ x, const float* __restrict__ s,
                     const float* __restrict__ bb, __half* __restrict__ y) {
    int r = blockIdx.x;
    const float* xr = x + (size_t)r * Dv;
    __half*      yr = y + (size_t)r * Dv;
    __shared__ float red[8];
    int tid = threadIdx.x; // 256
    float v0 = xr[tid], v1 = xr[tid + 256], v2 = xr[tid + 512];
    float sum = v0 + v1 + v2;
    #pragma unroll
    for (int o = 16; o; o >>= 1) sum += __shfl_xor_sync(0xffffffffu, sum, o);
    if ((tid & 31) == 0) red[tid >> 5] = sum;
    __syncthreads();
    float mu = (red[0]+red[1]+red[2]+red[3]+red[4]+red[5]+red[6]+red[7]) * (1.0f/Dv);
    float d0 = v0 - mu, d1 = v1 - mu, d2 = v2 - mu;
    float sq = d0*d0 + d1*d1 + d2*d2;
    __syncthreads();
    #pragma unroll
    for (int o = 16; o; o >>= 1) sq += __shfl_xor_sync(0xffffffffu, sq, o);
    if ((tid & 31) == 0) red[tid >> 5] = sq;
    __syncthreads();
    float var = (red[0]+red[1]+red[2]+red[3]+red[4]+red[5]+red[6]+red[7]) * (1.0f/Dv);
    float rstd = rsqrtf(var + 1e-5f);
    yr[tid      ] = __float2half(d0 * rstd * s[tid      ] + bb[tid      ]);
    yr[tid + 256] = __float2half(d1 * rstd * s[tid + 256] + bb[tid + 256]);
    yr[tid + 512] = __float2half(d2 * rstd * s[tid + 512] + bb[tid + 512]);
}

// ---------------- fp16 tensor-core GEMM (128x128): C = A @ B^T ------------------
// A[M,K] half, B[N,K] half (pre-transposed). BK=32 halves/slab, 8 warps (4x2),
// warp tile 32x64, m16n8k16, 5-stage cp.async pipeline.
// OUT: 0 = fp32, 2 = half.
#define HSTU 20                    /* u32 per smem row (32 data halves + 8 pad) */
#define NSTG 5
#define TILEW (128*HSTU)
#define SWU (2*TILEW)
#define GEMM_H_SMEM (NSTG * SWU * 4)

template <int ACT, bool RES, int OUT>
__global__ __launch_bounds__(256, 2) void gemm_h(
    const __half* __restrict__ A, const __half* __restrict__ B,
    const float* __restrict__ bias, const float* __restrict__ res,
    float* __restrict__ C, __half* __restrict__ Ch, int M, int N, int K) {
    extern __shared__ unsigned ghsm[];
    const int tid  = threadIdx.x;
    const int lane = tid & 31, warp = tid >> 5;
    const int wm = warp >> 1, wn = warp & 1;
    const int m0 = blockIdx.y * 128, n0 = blockIdx.x * 128;
    const unsigned sbase = (unsigned)__cvta_generic_to_shared(ghsm);

    float acc[2][8][4];
    #pragma unroll
    for (int i = 0; i < 2; i++)
        #pragma unroll
        for (int j = 0; j < 8; j++)
            #pragma unroll
            for (int q = 0; q < 4; q++) acc[i][j][q] = 0.0f;

    auto issue = [&](int stg, int k0) {
        #pragma unroll
        for (int i = 0; i < 2; i++) {
            int c = tid + 256 * i;
            int row = c >> 2, off = (c & 3) * 8;
            unsigned ad = sbase + (stg * SWU + row * HSTU) * 4 + off * 2;
            cp16(ad, A + (size_t)(m0 + row) * K + k0 + off);
            cp16(ad + TILEW * 4, B + (size_t)(n0 + row) * K + k0 + off);
        }
    };

    const int nslab = K / 32;
    #pragma unroll
    for (int s = 0; s < NSTG - 1; s++) {
        if (s < nslab) issue(s, s * 32);
        cp_commit();
    }

    for (int i = 0; i < nslab; i++) {
        cp_wait<NSTG - 2>();
        __syncthreads();

        const unsigned* Asf = ghsm + (i % NSTG) * SWU;
        const unsigned* Bsf = Asf + TILEW;

        #pragma unroll
        for (int ks = 0; ks < 2; ks++) {
            const int kb = ks * 8;
            unsigned af[2][4], bf[8][2];
            #pragma unroll
            for (int mt = 0; mt < 2; mt++) {
                int m = wm * 32 + mt * 16 + (lane >> 2);
                int k = kb + (lane & 3);
                af[mt][0] = Asf[m * HSTU + k];
                af[mt][1] = Asf[(m + 8) * HSTU + k];
                af[mt][2] = Asf[m * HSTU + k + 4];
                af[mt][3] = Asf[(m + 8) * HSTU + k + 4];
            }
            #pragma unroll
            for (int nt = 0; nt < 8; nt++) {
                int n = wn * 64 + nt * 8 + (lane >> 2);
                int k = kb + (lane & 3);
                bf[nt][0] = Bsf[n * HSTU + k];
                bf[nt][1] = Bsf[n * HSTU + k + 4];
            }
            #pragma unroll
            for (int mt = 0; mt < 2; mt++)
                #pragma unroll
                for (int nt = 0; nt < 8; nt++)
                    mma_f16(acc[mt][nt], af[mt], bf[nt]);
        }

        int j = i + NSTG - 1;
        if (j < nslab) issue(j % NSTG, j * 32);
        cp_commit();
    }

    #pragma unroll
    for (int mt = 0; mt < 2; mt++) {
        int r0 = m0 + wm * 32 + mt * 16 + (lane >> 2);
        #pragma unroll
        for (int nt = 0; nt < 8; nt++) {
            int c0i = n0 + wn * 64 + nt * 8 + 2 * (lane & 3);
            #pragma unroll
            for (int half = 0; half < 2; half++) {
                int r = r0 + half * 8;
                float v0 = acc[mt][nt][half * 2 + 0];
                float v1 = acc[mt][nt][half * 2 + 1];
                if (bias) { v0 += bias[c0i]; v1 += bias[c0i + 1]; }
                if (ACT == 1) {
                    v0 = v0 * (1.0f / (1.0f + __expf(-v0)));
                    v1 = v1 * (1.0f / (1.0f + __expf(-v1)));
                }
                if (RES) {
                    const float* rp = res + (size_t)r * N + c0i;
                    v0 += rp[0]; v1 += rp[1];
                }
                if (OUT == 2) {
                    *(__half2*)(Ch + (size_t)r * N + c0i) = __floats2half2_rn(v0, v1);
                } else {
                    *(float2*)(C + (size_t)r * N + c0i) = make_float2(v0, v1);
                }
            }
        }
    }
}

// ---------------- fp16 GEMM, 128x64 tile (out/dn projections) ------------------
#define NSTG4 4
#define SW64 (TILEW + 64*HSTU)
#define GEMM_H64_SMEM (NSTG4 * SW64 * 4)

template <int ACT, bool RES, int OUT>
__global__ __launch_bounds__(256, 3) void gemm_h64(
    const __half* __restrict__ A, const __half* __restrict__ B,
    const float* __restrict__ bias, const float* __restrict__ res,
    float* __restrict__ C, __half* __restrict__ Ch, int M, int N, int K) {
    extern __shared__ unsigned ghsm[];
    const int tid  = threadIdx.x;
    const int lane = tid & 31, warp = tid >> 5;
    const int wm = warp >> 1, wn = warp & 1;
    const int m0 = blockIdx.y * 128, n0 = blockIdx.x * 64;
    const unsigned sbase = (unsigned)__cvta_generic_to_shared(ghsm);

    float acc[2][4][4];
    #pragma unroll
    for (int i = 0; i < 2; i++)
        #pragma unroll
        for (int j = 0; j < 4; j++)
            #pragma unroll
            for (int q = 0; q < 4; q++) acc[i][j][q] = 0.0f;

    auto issue = [&](int stg, int k0) {
        #pragma unroll
        for (int i = 0; i < 3; i++) {
            int c = tid + 256 * i;
            if (c < 512) {
                int row = c >> 2, off = (c & 3) * 8;
                unsigned ad = sbase + (stg * SW64 + row * HSTU) * 4 + off * 2;
                cp16(ad, A + (size_t)(m0 + row) * K + k0 + off);
            } else {
                int cb = c - 512;
                int row = cb >> 2, off = (cb & 3) * 8;
                unsigned bd = sbase + (stg * SW64 + TILEW + row * HSTU) * 4 + off * 2;
                cp16(bd, B + (size_t)(n0 + row) * K + k0 + off);
            }
        }
    };

    const int nslab = K / 32;
    #pragma unroll
    for (int s = 0; s < NSTG4 - 1; s++) {
        if (s < nslab) issue(s, s * 32);
        cp_commit();
    }

    for (int i = 0; i < nslab; i++) {
        cp_wait<NSTG4 - 2>();
        __syncthreads();

        const unsigned* Asf = ghsm + (i % NSTG4) * SW64;
        const unsigned* Bsf = Asf + TILEW;

        #pragma unroll
        for (int ks = 0; ks < 2; ks++) {
            const int kb = ks * 8;
            unsigned af[2][4], bf[4][2];
            #pragma unroll
            for (int mt = 0; mt < 2; mt++) {
                int m = wm * 32 + mt * 16 + (lane >> 2);
                int k = kb + (lane & 3);
                af[mt][0] = Asf[m * HSTU + k];
                af[mt][1] = Asf[(m + 8) * HSTU + k];
                af[mt][2] = Asf[m * HSTU + k + 4];
                af[mt][3] = Asf[(m + 8) * HSTU + k + 4];
            }
            #pragma unroll
            for (int nt = 0; nt < 4; nt++) {
                int n = wn * 32 + nt * 8 + (lane >> 2);
                int k = kb + (lane & 3);
                bf[nt][0] = Bsf[n * HSTU + k];
                bf[nt][1] = Bsf[n * HSTU + k + 4];
            }
            #pragma unroll
            for (int mt = 0; mt < 2; mt++)
                #pragma unroll
                for (int nt = 0; nt < 4; nt++)
                    mma_f16(acc[mt][nt], af[mt], bf[nt]);
        }

        int j = i + NSTG4 - 1;
        if (j < nslab) issue(j % NSTG4, j * 32);
        cp_commit();
    }

    #pragma unroll
    for (int mt = 0; mt < 2; mt++) {
        int r0 = m0 + wm * 32 + mt * 16 + (lane >> 2);
        #pragma unroll
        for (int nt = 0; nt < 4; nt++) {
            int c0i = n0 + wn * 32 + nt * 8 + 2 * (lane & 3);
            #pragma unroll
            for (int half = 0; half < 2; half++) {
                int r = r0 + half * 8;
                float v0 = acc[mt][nt][half * 2 + 0];
                float v1 = acc[mt][nt][half * 2 + 1];
                if (bias) { v0 += bias[c0i]; v1 += bias[c0i + 1]; }
                if (ACT == 1) {
                    v0 = v0 * (1.0f / (1.0f + __expf(-v0)));
                    v1 = v1 * (1.0f / (1.0f + __expf(-v1)));
                }
                if (RES) {
                    const float* rp = res + (size_t)r * N + c0i;
                    v0 += rp[0]; v1 += rp[1];
                }
                if (OUT == 2) {
                    *(__half2*)(Ch + (size_t)r * N + c0i) = __floats2half2_rn(v0, v1);
                } else {
                    *(float2*)(C + (size_t)r * N + c0i) = make_float2(v0, v1);
                }
            }
        }
    }
}

// ---------------- fp16 flash attention: 64 queries x one (b,h) per block -------
// All-half operands, m16n8k16 for S=QK^T and O+=P.V. Heavy-first order.
// Attention row stride AHS: 64 halves data = 32 u32, +4 pad = 36 u32.
#define AHS 36
#define SQPAD 68
#define ATTN_SMEM ((4*64*AHS + 64*SQPAD + 3*64) * 4)

__global__ __launch_bounds__(256) void attn_h_k(
    const __half* __restrict__ qkv, __half* __restrict__ out) {
    extern __shared__ unsigned asm_[];
    unsigned* Qs = asm_;                      // [64][AHS]
    unsigned* Ks = Qs + 64 * AHS;             // [64][AHS]
    unsigned* Vt = Ks + 64 * AHS;             // [64 d][AHS] (V transposed)
    unsigned* Ps = Vt + 64 * AHS;             // [64][AHS]
    float*    Ss = (float*)(Ps + 64 * AHS);   // [64][SQPAD] fp32
    float*    m_sm = Ss + 64 * SQPAD;
    float*    l_sm = m_sm + 64;
    float*    sc_sm = l_sm + 64;

    const int q0 = ((int)gridDim.x - 1 - (int)blockIdx.x) * 64;  // heavy-first
    const int h  = blockIdx.y;
    const int b  = blockIdx.z;
    const int tid = threadIdx.x;
    const int lane = tid & 31, warp = tid >> 5;
    const int wm = warp >> 1, wn = warp & 1;   // 4 x 2, warp S-tile 16x32

    const __half* qbase = qkv + (size_t)(b * Tv) * QKVN + h * HDv;
    const __half* kbase = qbase + Hv * HDv;
    const __half* vbase = qbase + 2 * Hv * HDv;

    const int srow = tid >> 2, sseg = tid & 3;   // 4 threads/row, 16 halves each

    // load Q (64 x 64 halves), scaled by 0.125 (exact in half)
    {
        const __half* src = qbase + (size_t)(q0 + srow) * QKVN + sseg * 16;
        uint4 a = *(const uint4*)src;
        uint4 bq = *(const uint4*)(src + 8);
        unsigned va[8] = {a.x, a.y, a.z, a.w, bq.x, bq.y, bq.z, bq.w};
        const __half2 sc = __floats2half2_rn(0.125f, 0.125f);
        unsigned* dst = Qs + srow * AHS + sseg * 8;
        #pragma unroll
        for (int i = 0; i < 8; i++) {
            __half2 hv = __hmul2(*(__half2*)&va[i], sc);
            dst[i] = *(unsigned*)&hv;
        }
    }
    if (tid < 64) { m_sm[tid] = -1e30f; l_sm[tid] = 0.0f; }

    float acc_o[4][4];
    #pragma unroll
    for (int i = 0; i < 4; i++)
        #pragma unroll
        for (int j = 0; j < 4; j++) acc_o[i][j] = 0.0f;

    for (int c0 = 0; c0 <= q0; c0 += 64) {
        // ---- stage K (row-major) and V (transposed) ----
        {
            const __half* ksrc = kbase + (size_t)(c0 + srow) * QKVN + sseg * 16;
            uint4 a = *(const uint4*)ksrc;
            uint4 bk = *(const uint4*)(ksrc + 8);
            unsigned* dst = Ks + srow * AHS + sseg * 8;
            *(uint4*)dst = a;
            *(uint4*)(dst + 4) = bk;

            const __half* vsrc = vbase + (size_t)(c0 + srow) * QKVN + sseg * 16;
            uint4 va = *(const uint4*)vsrc;
            uint4 vb = *(const uint4*)(vsrc + 8);
            unsigned vv[8] = {va.x, va.y, va.z, va.w, vb.x, vb.y, vb.z, vb.w};
            __half* VtH = (__half*)Vt;
            #pragma unroll
            for (int i = 0; i < 8; i++) {
                int d = sseg * 16 + i * 2;
                __half2 hv = *(__half2*)&vv[i];
                VtH[(size_t)d * (AHS * 2) + srow]       = __low2half(hv);
                VtH[(size_t)(d + 1) * (AHS * 2) + srow] = __high2half(hv);
            }
        }
        __syncthreads();

        // ---- S = Q . K^T  (m16n8k16; K-dim = 64 halves = 32 u32) ----
        float s_acc[4][4];
        #pragma unroll
        for (int i = 0; i < 4; i++)
            #pragma unroll
            for (int j = 0; j < 4; j++) s_acc[i][j] = 0.0f;
        #pragma unroll
        for (int kb = 0; kb < 32; kb += 8) {
            unsigned af[4], bf[4][2];
            int mr = wm * 16 + (lane >> 2);
            int kk = kb + (lane & 3);
            af[0] = Qs[mr * AHS + kk];
            af[1] = Qs[(mr + 8) * AHS + kk];
            af[2] = Qs[mr * AHS + kk + 4];
            af[3] = Qs[(mr + 8) * AHS + kk + 4];
            #pragma unroll
            for (int nt = 0; nt < 4; nt++) {
                int n = wn * 32 + nt * 8 + (lane >> 2);
                bf[nt][0] = Ks[n * AHS + kk];
                bf[nt][1] = Ks[n * AHS + kk + 4];
            }
            #pragma unroll
            for (int nt = 0; nt < 4; nt++)
                mma_f16(s_acc[nt], af, bf[nt]);
        }
        const bool diag = (c0 == q0);
        #pragma unroll
        for (int nt = 0; nt < 4; nt++) {
            int c = wn * 32 + nt * 8 + 2 * (lane & 3);
            #pragma unroll
            for (int half = 0; half < 2; half++) {
                int r = wm * 16 + (lane >> 2) + half * 8;
                float v0 = s_acc[nt][half * 2 + 0];
                float v1 = s_acc[nt][half * 2 + 1];
                if (diag) {
                    if (c     > r) v0 = -1e30f;
                    if (c + 1 > r) v1 = -1e30f;
                }
                Ss[r * SQPAD + c] = v0; Ss[r * SQPAD + c + 1] = v1;
            }
        }
        __syncthreads();

        // ---- online softmax: 4 thr/row, contiguous 16-wide segments; pack P half2 ----
        {
            const float* seg = Ss + srow * SQPAD + sseg * 16;
            float cmax = -1e30f;
            #pragma unroll
            for (int j = 0; j < 16; j++) cmax = fmaxf(cmax, seg[j]);
            cmax = fmaxf(cmax, __shfl_xor_sync(0xffffffffu, cmax, 1));
            cmax = fmaxf(cmax, __shfl_xor_sync(0xffffffffu, cmax, 2));
            float m_old = m_sm[srow];
            float m_new = fmaxf(m_old, cmax);
            float csum = 0.0f;
            unsigned* pdst = Ps + srow * AHS + sseg * 8;
            #pragma unroll
            for (int j = 0; j < 16; j += 2) {
                float p0 = __expf(seg[j] - m_new);
                float p1 = __expf(seg[j + 1] - m_new);
                csum += p0 + p1;
                __half2 ph = __floats2half2_rn(p0, p1);
                pdst[j >> 1] = *(unsigned*)&ph;
            }
            csum += __shfl_xor_sync(0xffffffffu, csum, 1);
            csum += __shfl_xor_sync(0xffffffffu, csum, 2);
            if (sseg == 0) {
                float scale = __expf(m_old - m_new);
                sc_sm[srow] = scale;
                l_sm[srow] = l_sm[srow] * scale + csum;
                m_sm[srow] = m_new;
            }
        }
        __syncthreads();

        // ---- rescale O, then O += P . V  (m16n8k16, B = Vt[d][j]) ----
        {
            int r1 = wm * 16 + (lane >> 2);
            float s1 = sc_sm[r1], s2 = sc_sm[r1 + 8];
            #pragma unroll
            for (int nt = 0; nt < 4; nt++) {
                acc_o[nt][0] *= s1; acc_o[nt][1] *= s1;
                acc_o[nt][2] *= s2; acc_o[nt][3] *= s2;
            }
        }
        #pragma unroll
        for (int kb = 0; kb < 32; kb += 8) {
            unsigned af[4], bf[4][2];
            int mr = wm * 16 + (lane >> 2);
            int kk = kb + (lane & 3);
            af[0] = Ps[mr * AHS + kk];
            af[1] = Ps[(mr + 8) * AHS + kk];
            af[2] = Ps[mr * AHS + kk + 4];
            af[3] = Ps[(mr + 8) * AHS + kk + 4];
            #pragma unroll
            for (int nt = 0; nt < 4; nt++) {
                int n = wn * 32 + nt * 8 + (lane >> 2);
                bf[nt][0] = Vt[n * AHS + kk];
                bf[nt][1] = Vt[n * AHS + kk + 4];
            }
            #pragma unroll
            for (int nt = 0; nt < 4; nt++)
                mma_f16(acc_o[nt], af, bf[nt]);
        }
        __syncthreads();
    }

    // ---- output: O / l, half ----
    {
        int r1 = wm * 16 + (lane >> 2);
        float inv1 = 1.0f / l_sm[r1], inv2 = 1.0f / l_sm[r1 + 8];
        #pragma unroll
        for (int nt = 0; nt < 4; nt++) {
            int c = wn * 32 + nt * 8 + 2 * (lane & 3);
            __half* o1 = out + (size_t)(b * Tv + q0 + r1) * Dv + h * HDv + c;
            __half* o2 = out + (size_t)(b * Tv + q0 + r1 + 8) * Dv + h * HDv + c;
            *(__half2*)o1 = __floats2half2_rn(acc_o[nt][0] * inv1, acc_o[nt][1] * inv1);
            *(__half2*)o2 = __floats2half2_rn(acc_o[nt][2] * inv2, acc_o[nt][3] * inv2);
        }
    }
}

// ---------------- driver ----------------
extern "C" void kernel_launch(void* const* d_in, const int* in_sizes, int n_in,
                              void* d_out, int out_size) {
    const int*   ids   = (const int*)  d_in[0];
    const float* te    = (const float*)d_in[1];
    const float* pe    = (const float*)d_in[2];
    const float* ln1_s = (const float*)d_in[3];
    const float* ln1_b = (const float*)d_in[4];
    const float* qkv_w = (const float*)d_in[5];
    const float* qkv_b = (const float*)d_in[6];
    const float* out_w = (const float*)d_in[7];
    const float* out_b = (const float*)d_in[8];
    const float* ln2_s = (const float*)d_in[9];
    const float* ln2_b = (const float*)d_in[10];
    const float* up_w  = (const float*)d_in[11];
    const float* up_b  = (const float*)d_in[12];
    const float* dn_w  = (const float*)d_in[13];
    const float* dn_b  = (const float*)d_in[14];
    const float* lnf_s = (const float*)d_in[15];
    const float* lnf_b = (const float*)d_in[16];
    float* logits = (float*)d_out;

    float *x;
    __half *qkvh, *lnb, *att, *ff, *wqkv, *wout, *wup, *wdn, *teh;
    cudaGetSymbolAddress((void**)&x,    g_x);
    cudaGetSymbolAddress((void**)&qkvh, g_qkvh);
    cudaGetSymbolAddress((void**)&lnb,  g_ln);
    cudaGetSymbolAddress((void**)&att,  g_att);
    cudaGetSymbolAddress((void**)&ff,   g_ff);
    cudaGetSymbolAddress((void**)&wqkv, g_wqkv);
    cudaGetSymbolAddress((void**)&wout, g_wout);
    cudaGetSymbolAddress((void**)&wup,  g_wup);
    cudaGetSymbolAddress((void**)&wdn,  g_wdn);
    cudaGetSymbolAddress((void**)&teh,  g_te);

    cudaFuncSetAttribute(attn_h_k,
                         cudaFuncAttributeMaxDynamicSharedMemorySize, ATTN_SMEM);
    cudaFuncSetAttribute(gemm_h<0, false, 2>,
                         cudaFuncAttributeMaxDynamicSharedMemorySize, GEMM_H_SMEM);
    cudaFuncSetAttribute(gemm_h<1, false, 2>,
                         cudaFuncAttributeMaxDynamicSharedMemorySize, GEMM_H_SMEM);
    cudaFuncSetAttribute(gemm_h<0, false, 0>,
                         cudaFuncAttributeMaxDynamicSharedMemorySize, GEMM_H_SMEM);
    cudaFuncSetAttribute(gemm_h64<0, true, 0>,
                         cudaFuncAttributeMaxDynamicSharedMemorySize, GEMM_H64_SMEM);

    // ---- weight prep: transpose + half-convert (every launch; deterministic) ----
    {
        dim3 blk(32, 8);
        thsplit_k<<<dim3(QKVN / 32, Dv / 32, Lv), blk>>>(qkv_w, wqkv, Dv, QKVN);
        thsplit_k<<<dim3(Dv / 32,   Dv / 32, Lv), blk>>>(out_w, wout, Dv, Dv);
        thsplit_k<<<dim3(DFv / 32,  Dv / 32, Lv), blk>>>(up_w,  wup,  Dv, DFv);
        thsplit_k<<<dim3(Dv / 32,  DFv / 32, Lv), blk>>>(dn_w,  wdn,  DFv, Dv);
        int n4 = Vv * Dv / 4;
        hcvt_k<<<(n4 + 255) / 256, 256>>>(te, teh, n4);
    }

    embed_k<<<(Mv * Dv + 255) / 256, 256>>>(ids, te, pe, x);

    for (int i = 0; i < Lv; i++) {
        ln_k<<<Mv, 256>>>(x, ln1_s + (size_t)i * Dv, ln1_b + (size_t)i * Dv, lnb);
        gemm_h<0, false, 2><<<dim3(QKVN / 128, Mv / 128), 256, GEMM_H_SMEM>>>(
            lnb, wqkv + (size_t)i * QKVN * Dv, qkv_b + (size_t)i * QKVN,
            nullptr, nullptr, qkvh, Mv, QKVN, Dv);
        attn_h_k<<<dim3(Tv / 64, Hv, Bv), 256, ATTN_SMEM>>>(qkvh, att);
        gemm_h64<0, true, 0><<<dim3(Dv / 64, Mv / 128), 256, GEMM_H64_SMEM>>>(
            att, wout + (size_t)i * Dv * Dv, out_b + (size_t)i * Dv,
            x, x, nullptr, Mv, Dv, Dv);
        ln_k<<<Mv, 256>>>(x, ln2_s + (size_t)i * Dv, ln2_b + (size_t)i * Dv, lnb);
        gemm_h<1, false, 2><<<dim3(DFv / 128, Mv / 128), 256, GEMM_H_SMEM>>>(
            lnb, wup + (size_t)i * DFv * Dv, up_b + (size_t)i * DFv,
            nullptr, nullptr, ff, Mv, DFv, Dv);
        gemm_h64<0, true, 0><<<dim3(Dv / 64, Mv / 128), 256, GEMM_H64_SMEM>>>(
            ff, wdn + (size_t)i * Dv * DFv, dn_b + (size_t)i * Dv,
            x, x, nullptr, Mv, Dv, DFv);
    }

    ln_k<<<Mv, 256>>>(x, lnf_s, lnf_b, lnb);
    gemm_h<0, false, 0><<<dim3(Vv / 128, Mv / 128), 256, GEMM_H_SMEM>>>(
        lnb, teh, nullptr, nullptr, logits, nullptr, Mv, Vv, Dv);
}

// round 15
// speedup vs baseline: 2.0321x; 1.0704x over previous
#include <cuda_runtime.h>
#include <cuda_fp16.h>
#include <math.h>

#define Bv   2
#define Tv   2048
#define Dv   768
#define Hv   12
#define HDv  64
#define Lv   4
#define DFv  3072
#define Vv   32000
#define Mv   (Bv*Tv)        /* 4096 rows */
#define QKVN (3*Hv*HDv)     /* 2304 */

// ---------------- scratch (static device globals; no allocs) ----------------
__device__ float  g_x   [Mv*Dv];     // residual stream (fp32)
__device__ __half g_qkvh[Mv*QKVN];   // qkv projection (half)
__device__ __half g_ln  [Mv*Dv];     // layernorm output (half)
__device__ __half g_att [Mv*Dv];     // attention output (half)
__device__ __half g_ff  [Mv*DFv];    // ffn hidden (half)
// half weight copies, transposed to [N,K]
__device__ __half g_wqkv[Lv*QKVN*Dv];
__device__ __half g_wout[Lv*Dv*Dv];
__device__ __half g_wup [Lv*DFv*Dv];
__device__ __half g_wdn [Lv*Dv*DFv];
__device__ __half g_te  [Vv*Dv];     // te is [V,D] = [N,K] already

// ---------------- helpers ----------------
__device__ __forceinline__ void mma_f16(float* c, const unsigned* a, const unsigned* b) {
    asm volatile(
        "mma.sync.aligned.m16n8k16.row.col.f32.f16.f16.f32 "
        "{%0,%1,%2,%3}, {%4,%5,%6,%7}, {%8,%9}, {%0,%1,%2,%3};\n"
        : "+f"(c[0]), "+f"(c[1]), "+f"(c[2]), "+f"(c[3])
        : "r"(a[0]), "r"(a[1]), "r"(a[2]), "r"(a[3]), "r"(b[0]), "r"(b[1]));
}
__device__ __forceinline__ void cp16(unsigned sdst, const void* g) {
    asm volatile("cp.async.cg.shared.global [%0], [%1], 16;" :: "r"(sdst), "l"(g));
}
__device__ __forceinline__ void cp_commit() { asm volatile("cp.async.commit_group;"); }
template <int N>
__device__ __forceinline__ void cp_wait() {
    asm volatile("cp.async.wait_group %0;" :: "n"(N));
}

// ---------------- weight prep ----------------
__global__ void thsplit_k(const float* __restrict__ W, __half* __restrict__ o,
                          int K, int N) {
    __shared__ float t[32][33];
    const float* Wl = W + (size_t)blockIdx.z * K * N;
    __half* ol = o + (size_t)blockIdx.z * K * N;
    int kb = blockIdx.y * 32, nb = blockIdx.x * 32;
    int tx = threadIdx.x, ty = threadIdx.y;   // 32 x 8
    #pragma unroll
    for (int i = 0; i < 32; i += 8)
        t[ty + i][tx] = Wl[(size_t)(kb + ty + i) * N + nb + tx];
    __syncthreads();
    #pragma unroll
    for (int i = 0; i < 32; i += 8)
        ol[(size_t)(nb + ty + i) * K + kb + tx] = __float2half(t[tx][ty + i]);
}
__global__ void hcvt_k(const float* __restrict__ in, __half* __restrict__ out, int n4) {
    int i = blockIdx.x * blockDim.x + threadIdx.x;
    if (i >= n4) return;
    float4 v = ((const float4*)in)[i];
    __half2* o = (__half2*)out;
    o[i * 2    ] = __floats2half2_rn(v.x, v.y);
    o[i * 2 + 1] = __floats2half2_rn(v.z, v.w);
}

// ---------------- embedding ----------------
__global__ void embed_k(const int* __restrict__ ids, const float* __restrict__ te,
                        const float* __restrict__ pe, float* __restrict__ x) {
    int i = blockIdx.x * blockDim.x + threadIdx.x;
    if (i >= Mv * Dv) return;
    int r = i / Dv, d = i - r * Dv;
    int t = r % Tv;
    x[i] = te[(size_t)ids[r] * Dv + d] + pe[(size_t)t * Dv + d];
}

// ---------------- layernorm (writes half) ----------------
__global__ void ln_k(const float* __restrict__ x, const float* __restrict__ s,
                     const float* __restrict__ bb, __half* __restrict__ y) {
    int r = blockIdx.x;
    const float* xr = x + (size_t)r * Dv;
    __half*      yr = y + (size_t)r * Dv;
    __shared__ float red[8];
    int tid = threadIdx.x; // 256
    float v0 = xr[tid], v1 = xr[tid + 256], v2 = xr[tid + 512];
    float sum = v0 + v1 + v2;
    #pragma unroll
    for (int o = 16; o; o >>= 1) sum += __shfl_xor_sync(0xffffffffu, sum, o);
    if ((tid & 31) == 0) red[tid >> 5] = sum;
    __syncthreads();
    float mu = (red[0]+red[1]+red[2]+red[3]+red[4]+red[5]+red[6]+red[7]) * (1.0f/Dv);
    float d0 = v0 - mu, d1 = v1 - mu, d2 = v2 - mu;
    float sq = d0*d0 + d1*d1 + d2*d2;
    __syncthreads();
    #pragma unroll
    for (int o = 16; o; o >>= 1) sq += __shfl_xor_sync(0xffffffffu, sq, o);
    if ((tid & 31) == 0) red[tid >> 5] = sq;
    __syncthreads();
    float var = (red[0]+red[1]+red[2]+red[3]+red[4]+red[5]+red[6]+red[7]) * (1.0f/Dv);
    float rstd = rsqrtf(var + 1e-5f);
    yr[tid      ] = __float2half(d0 * rstd * s[tid      ] + bb[tid      ]);
    yr[tid + 256] = __float2half(d1 * rstd * s[tid + 256] + bb[tid + 256]);
    yr[tid + 512] = __float2half(d2 * rstd * s[tid + 512] + bb[tid + 512]);
}

// ---------------- fp16 tensor-core GEMM (128x128): C = A @ B^T ------------------
#define HSTU 20
#define NSTG 5
#define TILEW (128*HSTU)
#define SWU (2*TILEW)
#define GEMM_H_SMEM (NSTG * SWU * 4)

template <int ACT, bool RES, int OUT>
__global__ __launch_bounds__(256, 2) void gemm_h(
    const __half* __restrict__ A, const __half* __restrict__ B,
    const float* __restrict__ bias, const float* __restrict__ res,
    float* __restrict__ C, __half* __restrict__ Ch, int M, int N, int K) {
    extern __shared__ unsigned ghsm[];
    const int tid  = threadIdx.x;
    const int lane = tid & 31, warp = tid >> 5;
    const int wm = warp >> 1, wn = warp & 1;
    const int m0 = blockIdx.y * 128, n0 = blockIdx.x * 128;
    const unsigned sbase = (unsigned)__cvta_generic_to_shared(ghsm);

    float acc[2][8][4];
    #pragma unroll
    for (int i = 0; i < 2; i++)
        #pragma unroll
        for (int j = 0; j < 8; j++)
            #pragma unroll
            for (int q = 0; q < 4; q++) acc[i][j][q] = 0.0f;

    auto issue = [&](int stg, int k0) {
        #pragma unroll
        for (int i = 0; i < 2; i++) {
            int c = tid + 256 * i;
            int row = c >> 2, off = (c & 3) * 8;
            unsigned ad = sbase + (stg * SWU + row * HSTU) * 4 + off * 2;
            cp16(ad, A + (size_t)(m0 + row) * K + k0 + off);
            cp16(ad + TILEW * 4, B + (size_t)(n0 + row) * K + k0 + off);
        }
    };

    const int nslab = K / 32;
    #pragma unroll
    for (int s = 0; s < NSTG - 1; s++) {
        if (s < nslab) issue(s, s * 32);
        cp_commit();
    }

    for (int i = 0; i < nslab; i++) {
        cp_wait<NSTG - 2>();
        __syncthreads();

        const unsigned* Asf = ghsm + (i % NSTG) * SWU;
        const unsigned* Bsf = Asf + TILEW;

        #pragma unroll
        for (int ks = 0; ks < 2; ks++) {
            const int kb = ks * 8;
            unsigned af[2][4], bf[8][2];
            #pragma unroll
            for (int mt = 0; mt < 2; mt++) {
                int m = wm * 32 + mt * 16 + (lane >> 2);
                int k = kb + (lane & 3);
                af[mt][0] = Asf[m * HSTU + k];
                af[mt][1] = Asf[(m + 8) * HSTU + k];
                af[mt][2] = Asf[m * HSTU + k + 4];
                af[mt][3] = Asf[(m + 8) * HSTU + k + 4];
            }
            #pragma unroll
            for (int nt = 0; nt < 8; nt++) {
                int n = wn * 64 + nt * 8 + (lane >> 2);
                int k = kb + (lane & 3);
                bf[nt][0] = Bsf[n * HSTU + k];
                bf[nt][1] = Bsf[n * HSTU + k + 4];
            }
            #pragma unroll
            for (int mt = 0; mt < 2; mt++)
                #pragma unroll
                for (int nt = 0; nt < 8; nt++)
                    mma_f16(acc[mt][nt], af[mt], bf[nt]);
        }

        int j = i + NSTG - 1;
        if (j < nslab) issue(j % NSTG, j * 32);
        cp_commit();
    }

    #pragma unroll
    for (int mt = 0; mt < 2; mt++) {
        int r0 = m0 + wm * 32 + mt * 16 + (lane >> 2);
        #pragma unroll
        for (int nt = 0; nt < 8; nt++) {
            int c0i = n0 + wn * 64 + nt * 8 + 2 * (lane & 3);
            #pragma unroll
            for (int half = 0; half < 2; half++) {
                int r = r0 + half * 8;
                float v0 = acc[mt][nt][half * 2 + 0];
                float v1 = acc[mt][nt][half * 2 + 1];
                if (bias) { v0 += bias[c0i]; v1 += bias[c0i + 1]; }
                if (ACT == 1) {
                    v0 = v0 * (1.0f / (1.0f + __expf(-v0)));
                    v1 = v1 * (1.0f / (1.0f + __expf(-v1)));
                }
                if (RES) {
                    const float* rp = res + (size_t)r * N + c0i;
                    v0 += rp[0]; v1 += rp[1];
                }
                if (OUT == 2) {
                    *(__half2*)(Ch + (size_t)r * N + c0i) = __floats2half2_rn(v0, v1);
                } else {
                    *(float2*)(C + (size_t)r * N + c0i) = make_float2(v0, v1);
                }
            }
        }
    }
}

// ---------------- fp16 GEMM, 128x64 tile (out/dn projections) ------------------
#define NSTG4 4
#define SW64 (TILEW + 64*HSTU)
#define GEMM_H64_SMEM (NSTG4 * SW64 * 4)

template <int ACT, bool RES, int OUT>
__global__ __launch_bounds__(256, 3) void gemm_h64(
    const __half* __restrict__ A, const __half* __restrict__ B,
    const float* __restrict__ bias, const float* __restrict__ res,
    float* __restrict__ C, __half* __restrict__ Ch, int M, int N, int K) {
    extern __shared__ unsigned ghsm[];
    const int tid  = threadIdx.x;
    const int lane = tid & 31, warp = tid >> 5;
    const int wm = warp >> 1, wn = warp & 1;
    const int m0 = blockIdx.y * 128, n0 = blockIdx.x * 64;
    const unsigned sbase = (unsigned)__cvta_generic_to_shared(ghsm);

    float acc[2][4][4];
    #pragma unroll
    for (int i = 0; i < 2; i++)
        #pragma unroll
        for (int j = 0; j < 4; j++)
            #pragma unroll
            for (int q = 0; q < 4; q++) acc[i][j][q] = 0.0f;

    auto issue = [&](int stg, int k0) {
        #pragma unroll
        for (int i = 0; i < 3; i++) {
            int c = tid + 256 * i;
            if (c < 512) {
                int row = c >> 2, off = (c & 3) * 8;
                unsigned ad = sbase + (stg * SW64 + row * HSTU) * 4 + off * 2;
                cp16(ad, A + (size_t)(m0 + row) * K + k0 + off);
            } else {
                int cb = c - 512;
                int row = cb >> 2, off = (cb & 3) * 8;
                unsigned bd = sbase + (stg * SW64 + TILEW + row * HSTU) * 4 + off * 2;
                cp16(bd, B + (size_t)(n0 + row) * K + k0 + off);
            }
        }
    };

    const int nslab = K / 32;
    #pragma unroll
    for (int s = 0; s < NSTG4 - 1; s++) {
        if (s < nslab) issue(s, s * 32);
        cp_commit();
    }

    for (int i = 0; i < nslab; i++) {
        cp_wait<NSTG4 - 2>();
        __syncthreads();

        const unsigned* Asf = ghsm + (i % NSTG4) * SW64;
        const unsigned* Bsf = Asf + TILEW;

        #pragma unroll
        for (int ks = 0; ks < 2; ks++) {
            const int kb = ks * 8;
            unsigned af[2][4], bf[4][2];
            #pragma unroll
            for (int mt = 0; mt < 2; mt++) {
                int m = wm * 32 + mt * 16 + (lane >> 2);
                int k = kb + (lane & 3);
                af[mt][0] = Asf[m * HSTU + k];
                af[mt][1] = Asf[(m + 8) * HSTU + k];
                af[mt][2] = Asf[m * HSTU + k + 4];
                af[mt][3] = Asf[(m + 8) * HSTU + k + 4];
            }
            #pragma unroll
            for (int nt = 0; nt < 4; nt++) {
                int n = wn * 32 + nt * 8 + (lane >> 2);
                int k = kb + (lane & 3);
                bf[nt][0] = Bsf[n * HSTU + k];
                bf[nt][1] = Bsf[n * HSTU + k + 4];
            }
            #pragma unroll
            for (int mt = 0; mt < 2; mt++)
                #pragma unroll
                for (int nt = 0; nt < 4; nt++)
                    mma_f16(acc[mt][nt], af[mt], bf[nt]);
        }

        int j = i + NSTG4 - 1;
        if (j < nslab) issue(j % NSTG4, j * 32);
        cp_commit();
    }

    #pragma unroll
    for (int mt = 0; mt < 2; mt++) {
        int r0 = m0 + wm * 32 + mt * 16 + (lane >> 2);
        #pragma unroll
        for (int nt = 0; nt < 4; nt++) {
            int c0i = n0 + wn * 32 + nt * 8 + 2 * (lane & 3);
            #pragma unroll
            for (int half = 0; half < 2; half++) {
                int r = r0 + half * 8;
                float v0 = acc[mt][nt][half * 2 + 0];
                float v1 = acc[mt][nt][half * 2 + 1];
                if (bias) { v0 += bias[c0i]; v1 += bias[c0i + 1]; }
                if (ACT == 1) {
                    v0 = v0 * (1.0f / (1.0f + __expf(-v0)));
                    v1 = v1 * (1.0f / (1.0f + __expf(-v1)));
                }
                if (RES) {
                    const float* rp = res + (size_t)r * N + c0i;
                    v0 += rp[0]; v1 += rp[1];
                }
                if (OUT == 2) {
                    *(__half2*)(Ch + (size_t)r * N + c0i) = __floats2half2_rn(v0, v1);
                } else {
                    *(float2*)(C + (size_t)r * N + c0i) = make_float2(v0, v1);
                }
            }
        }
    }
}

// ---------------- fp16 flash attention, register-resident softmax --------------
// 64 queries x one (b,h) per block, heavy-first. S stays in registers; P is
// exchanged through SMEM only for the cross-warp k coverage of P.V.
#define AHS 36
#define ATTN_SMEM ((4*64*AHS + 6*64) * 4)

__global__ __launch_bounds__(256) void attn_h_k(
    const __half* __restrict__ qkv, __half* __restrict__ out) {
    extern __shared__ unsigned asm_[];
    unsigned* Qs = asm_;                      // [64][AHS]
    unsigned* Ks = Qs + 64 * AHS;             // [64][AHS]
    unsigned* Vt = Ks + 64 * AHS;             // [64 d][AHS] (V transposed)
    unsigned* Ps = Vt + 64 * AHS;             // [64][AHS]  (P halves, exchange)
    float*    m_sm  = (float*)(Ps + 64 * AHS);  // [64]
    float*    l_sm  = m_sm + 64;                // [64]
    float*    wmax  = l_sm + 64;                // [2][64]
    float*    wsum  = wmax + 2 * 64;            // [2][64]

    const int q0 = ((int)gridDim.x - 1 - (int)blockIdx.x) * 64;  // heavy-first
    const int h  = blockIdx.y;
    const int b  = blockIdx.z;
    const int tid = threadIdx.x;
    const int lane = tid & 31, warp = tid >> 5;
    const int wm = warp >> 1, wn = warp & 1;   // 4 x 2, warp S-tile 16x32
    const int lrow = lane >> 2, lcol = lane & 3;

    const __half* qbase = qkv + (size_t)(b * Tv) * QKVN + h * HDv;
    const __half* kbase = qbase + Hv * HDv;
    const __half* vbase = qbase + 2 * Hv * HDv;

    const int srow = tid >> 2, sseg = tid & 3;

    // load Q (64 x 64 halves), scaled by 0.125 (exact in half)
    {
        const __half* src = qbase + (size_t)(q0 + srow) * QKVN + sseg * 16;
        uint4 a = *(const uint4*)src;
        uint4 bq = *(const uint4*)(src + 8);
        unsigned va[8] = {a.x, a.y, a.z, a.w, bq.x, bq.y, bq.z, bq.w};
        const __half2 sc = __floats2half2_rn(0.125f, 0.125f);
        unsigned* dst = Qs + srow * AHS + sseg * 8;
        #pragma unroll
        for (int i = 0; i < 8; i++) {
            __half2 hv = __hmul2(*(__half2*)&va[i], sc);
            dst[i] = *(unsigned*)&hv;
        }
    }
    if (tid < 64) { m_sm[tid] = -1e30f; l_sm[tid] = 0.0f; }

    float acc_o[4][4];
    #pragma unroll
    for (int i = 0; i < 4; i++)
        #pragma unroll
        for (int j = 0; j < 4; j++) acc_o[i][j] = 0.0f;

    for (int c0 = 0; c0 <= q0; c0 += 64) {
        // ---- stage K (row-major) and V (transposed) ----
        {
            const __half* ksrc = kbase + (size_t)(c0 + srow) * QKVN + sseg * 16;
            uint4 a = *(const uint4*)ksrc;
            uint4 bk = *(const uint4*)(ksrc + 8);
            unsigned* dst = Ks + srow * AHS + sseg * 8;
            *(uint4*)dst = a;
            *(uint4*)(dst + 4) = bk;

            const __half* vsrc = vbase + (size_t)(c0 + srow) * QKVN + sseg * 16;
            uint4 va = *(const uint4*)vsrc;
            uint4 vb = *(const uint4*)(vsrc + 8);
            unsigned vv[8] = {va.x, va.y, va.z, va.w, vb.x, vb.y, vb.z, vb.w};
            __half* VtH = (__half*)Vt;
            #pragma unroll
            for (int i = 0; i < 8; i++) {
                int d = sseg * 16 + i * 2;
                __half2 hv = *(__half2*)&vv[i];
                VtH[(size_t)d * (AHS * 2) + srow]       = __low2half(hv);
                VtH[(size_t)(d + 1) * (AHS * 2) + srow] = __high2half(hv);
            }
        }
        __syncthreads();                                   // (1)

        // ---- S = Q . K^T in registers ----
        float s_acc[4][4];
        #pragma unroll
        for (int i = 0; i < 4; i++)
            #pragma unroll
            for (int j = 0; j < 4; j++) s_acc[i][j] = 0.0f;
        #pragma unroll
        for (int kb = 0; kb < 32; kb += 8) {
            unsigned af[4], bf[4][2];
            int mr = wm * 16 + lrow;
            int kk = kb + lcol;
            af[0] = Qs[mr * AHS + kk];
            af[1] = Qs[(mr + 8) * AHS + kk];
            af[2] = Qs[mr * AHS + kk + 4];
            af[3] = Qs[(mr + 8) * AHS + kk + 4];
            #pragma unroll
            for (int nt = 0; nt < 4; nt++) {
                int n = wn * 32 + nt * 8 + lrow;
                bf[nt][0] = Ks[n * AHS + kk];
                bf[nt][1] = Ks[n * AHS + kk + 4];
            }
            #pragma unroll
            for (int nt = 0; nt < 4; nt++)
                mma_f16(s_acc[nt], af, bf[nt]);
        }

        // ---- causal mask in-register ----
        if (c0 == q0) {
            #pragma unroll
            for (int nt = 0; nt < 4; nt++) {
                int c = wn * 32 + nt * 8 + 2 * lcol;
                int r0r = wm * 16 + lrow;
                if (c     > r0r)     s_acc[nt][0] = -1e30f;
                if (c + 1 > r0r)     s_acc[nt][1] = -1e30f;
                if (c     > r0r + 8) s_acc[nt][2] = -1e30f;
                if (c + 1 > r0r + 8) s_acc[nt][3] = -1e30f;
            }
        }

        // ---- register softmax, stage A: warp-local row max ----
        float mx0 = -1e30f, mx1 = -1e30f;
        #pragma unroll
        for (int nt = 0; nt < 4; nt++) {
            mx0 = fmaxf(mx0, fmaxf(s_acc[nt][0], s_acc[nt][1]));
            mx1 = fmaxf(mx1, fmaxf(s_acc[nt][2], s_acc[nt][3]));
        }
        mx0 = fmaxf(mx0, __shfl_xor_sync(0xffffffffu, mx0, 1));
        mx0 = fmaxf(mx0, __shfl_xor_sync(0xffffffffu, mx0, 2));
        mx1 = fmaxf(mx1, __shfl_xor_sync(0xffffffffu, mx1, 1));
        mx1 = fmaxf(mx1, __shfl_xor_sync(0xffffffffu, mx1, 2));
        if (lcol == 0) {
            wmax[wn * 64 + wm * 16 + lrow]     = mx0;
            wmax[wn * 64 + wm * 16 + lrow + 8] = mx1;
        }
        __syncthreads();                                   // (2)

        // ---- stage B: combine halves, exp, sums, pack P ----
        int row0 = wm * 16 + lrow, row1 = row0 + 8;
        float m_old0 = m_sm[row0], m_old1 = m_sm[row1];
        float m_new0 = fmaxf(m_old0, fmaxf(wmax[row0], wmax[64 + row0]));
        float m_new1 = fmaxf(m_old1, fmaxf(wmax[row1], wmax[64 + row1]));
        float scale0 = __expf(m_old0 - m_new0);
        float scale1 = __expf(m_old1 - m_new1);
        float cs0 = 0.0f, cs1 = 0.0f;
        unsigned pk[4][2];   // packed half2: [nt][rowhalf]
        #pragma unroll
        for (int nt = 0; nt < 4; nt++) {
            float p0 = __expf(s_acc[nt][0] - m_new0);
            float p1 = __expf(s_acc[nt][1] - m_new0);
            float p2 = __expf(s_acc[nt][2] - m_new1);
            float p3 = __expf(s_acc[nt][3] - m_new1);
            cs0 += p0 + p1; cs1 += p2 + p3;
            __half2 h0 = __floats2half2_rn(p0, p1);
            __half2 h1 = __floats2half2_rn(p2, p3);
            pk[nt][0] = *(unsigned*)&h0;
            pk[nt][1] = *(unsigned*)&h1;
        }
        cs0 += __shfl_xor_sync(0xffffffffu, cs0, 1);
        cs0 += __shfl_xor_sync(0xffffffffu, cs0, 2);
        cs1 += __shfl_xor_sync(0xffffffffu, cs1, 1);
        cs1 += __shfl_xor_sync(0xffffffffu, cs1, 2);
        if (lcol == 0) {
            wsum[wn * 64 + row0] = cs0;
            wsum[wn * 64 + row1] = cs1;
        }
        // store P halves to exchange buffer (u32 col = wn*16 + nt*4 + lcol)
        #pragma unroll
        for (int nt = 0; nt < 4; nt++) {
            Ps[row0 * AHS + wn * 16 + nt * 4 + lcol] = pk[nt][0];
            Ps[row1 * AHS + wn * 16 + nt * 4 + lcol] = pk[nt][1];
        }
        __syncthreads();                                   // (3)

        // ---- update m/l state (one lane per row) ----
        if (wn == 0 && lcol == 0) {
            l_sm[row0] = l_sm[row0] * scale0 + wsum[row0] + wsum[64 + row0];
            l_sm[row1] = l_sm[row1] * scale1 + wsum[row1] + wsum[64 + row1];
            m_sm[row0] = m_new0;
            m_sm[row1] = m_new1;
        }

        // ---- rescale O (lane-local scales), then O += P . V ----
        #pragma unroll
        for (int nt = 0; nt < 4; nt++) {
            acc_o[nt][0] *= scale0; acc_o[nt][1] *= scale0;
            acc_o[nt][2] *= scale1; acc_o[nt][3] *= scale1;
        }
        #pragma unroll
        for (int kb = 0; kb < 32; kb += 8) {
            unsigned af[4], bf[4][2];
            int mr = wm * 16 + lrow;
            int kk = kb + lcol;
            af[0] = Ps[mr * AHS + kk];
            af[1] = Ps[(mr + 8) * AHS + kk];
            af[2] = Ps[mr * AHS + kk + 4];
            af[3] = Ps[(mr + 8) * AHS + kk + 4];
            #pragma unroll
            for (int nt = 0; nt < 4; nt++) {
                int n = wn * 32 + nt * 8 + lrow;
                bf[nt][0] = Vt[n * AHS + kk];
                bf[nt][1] = Vt[n * AHS + kk + 4];
            }
            #pragma unroll
            for (int nt = 0; nt < 4; nt++)
                mma_f16(acc_o[nt], af, bf[nt]);
        }
        __syncthreads();                                   // (4)
    }

    // ---- output: O / l, half ----
    {
        int r1 = wm * 16 + lrow;
        float inv1 = 1.0f / l_sm[r1], inv2 = 1.0f / l_sm[r1 + 8];
        #pragma unroll
        for (int nt = 0; nt < 4; nt++) {
            int c = wn * 32 + nt * 8 + 2 * lcol;
            __half* o1 = out + (size_t)(b * Tv + q0 + r1) * Dv + h * HDv + c;
            __half* o2 = out + (size_t)(b * Tv + q0 + r1 + 8) * Dv + h * HDv + c;
            *(__half2*)o1 = __floats2half2_rn(acc_o[nt][0] * inv1, acc_o[nt][1] * inv1);
            *(__half2*)o2 = __floats2half2_rn(acc_o[nt][2] * inv2, acc_o[nt][3] * inv2);
        }
    }
}

// ---------------- driver ----------------
extern "C" void kernel_launch(void* const* d_in, const int* in_sizes, int n_in,
                              void* d_out, int out_size) {
    const int*   ids   = (const int*)  d_in[0];
    const float* te    = (const float*)d_in[1];
    const float* pe    = (const float*)d_in[2];
    const float* ln1_s = (const float*)d_in[3];
    const float* ln1_b = (const float*)d_in[4];
    const float* qkv_w = (const float*)d_in[5];
    const float* qkv_b = (const float*)d_in[6];
    const float* out_w = (const float*)d_in[7];
    const float* out_b = (const float*)d_in[8];
    const float* ln2_s = (const float*)d_in[9];
    const float* ln2_b = (const float*)d_in[10];
    const float* up_w  = (const float*)d_in[11];
    const float* up_b  = (const float*)d_in[12];
    const float* dn_w  = (const float*)d_in[13];
    const float* dn_b  = (const float*)d_in[14];
    const float* lnf_s = (const float*)d_in[15];
    const float* lnf_b = (const float*)d_in[16];
    float* logits = (float*)d_out;

    float *x;
    __half *qkvh, *lnb, *att, *ff, *wqkv, *wout, *wup, *wdn, *teh;
    cudaGetSymbolAddress((void**)&x,    g_x);
    cudaGetSymbolAddress((void**)&qkvh, g_qkvh);
    cudaGetSymbolAddress((void**)&lnb,  g_ln);
    cudaGetSymbolAddress((void**)&att,  g_att);
    cudaGetSymbolAddress((void**)&ff,   g_ff);
    cudaGetSymbolAddress((void**)&wqkv, g_wqkv);
    cudaGetSymbolAddress((void**)&wout, g_wout);
    cudaGetSymbolAddress((void**)&wup,  g_wup);
    cudaGetSymbolAddress((void**)&wdn,  g_wdn);
    cudaGetSymbolAddress((void**)&teh,  g_te);

    cudaFuncSetAttribute(attn_h_k,
                         cudaFuncAttributeMaxDynamicSharedMemorySize, ATTN_SMEM);
    cudaFuncSetAttribute(gemm_h<0, false, 2>,
                         cudaFuncAttributeMaxDynamicSharedMemorySize, GEMM_H_SMEM);
    cudaFuncSetAttribute(gemm_h<1, false, 2>,
                         cudaFuncAttributeMaxDynamicSharedMemorySize, GEMM_H_SMEM);
    cudaFuncSetAttribute(gemm_h<0, false, 0>,
                         cudaFuncAttributeMaxDynamicSharedMemorySize, GEMM_H_SMEM);
    cudaFuncSetAttribute(gemm_h64<0, true, 0>,
                         cudaFuncAttributeMaxDynamicSharedMemorySize, GEMM_H64_SMEM);

    // ---- weight prep: transpose + half-convert (every launch; deterministic) ----
    {
        dim3 blk(32, 8);
        thsplit_k<<<dim3(QKVN / 32, Dv / 32, Lv), blk>>>(qkv_w, wqkv, Dv, QKVN);
        thsplit_k<<<dim3(Dv / 32,   Dv / 32, Lv), blk>>>(out_w, wout, Dv, Dv);
        thsplit_k<<<dim3(DFv / 32,  Dv / 32, Lv), blk>>>(up_w,  wup,  Dv, DFv);
        thsplit_k<<<dim3(Dv / 32,  DFv / 32, Lv), blk>>>(dn_w,  wdn,  DFv, Dv);
        int n4 = Vv * Dv / 4;
        hcvt_k<<<(n4 + 255) / 256, 256>>>(te, teh, n4);
    }

    embed_k<<<(Mv * Dv + 255) / 256, 256>>>(ids, te, pe, x);

    for (int i = 0; i < Lv; i++) {
        ln_k<<<Mv, 256>>>(x, ln1_s + (size_t)i * Dv, ln1_b + (size_t)i * Dv, lnb);
        gemm_h<0, false, 2><<<dim3(QKVN / 128, Mv / 128), 256, GEMM_H_SMEM>>>(
            lnb, wqkv + (size_t)i * QKVN * Dv, qkv_b + (size_t)i * QKVN,
            nullptr, nullptr, qkvh, Mv, QKVN, Dv);
        attn_h_k<<<dim3(Tv / 64, Hv, Bv), 256, ATTN_SMEM>>>(qkvh, att);
        gemm_h64<0, true, 0><<<dim3(Dv / 64, Mv / 128), 256, GEMM_H64_SMEM>>>(
            att, wout + (size_t)i * Dv * Dv, out_b + (size_t)i * Dv,
            x, x, nullptr, Mv, Dv, Dv);
        ln_k<<<Mv, 256>>>(x, ln2_s + (size_t)i * Dv, ln2_b + (size_t)i * Dv, lnb);
        gemm_h<1, false, 2><<<dim3(DFv / 128, Mv / 128), 256, GEMM_H_SMEM>>>(
            lnb, wup + (size_t)i * DFv * Dv, up_b + (size_t)i * DFv,
            nullptr, nullptr, ff, Mv, DFv, Dv);
        gemm_h64<0, true, 0><<<dim3(Dv / 64, Mv / 128), 256, GEMM_H64_SMEM>>>(
            ff, wdn + (size_t)i * Dv * DFv, dn_b + (size_t)i * Dv,
            x, x, nullptr, Mv, Dv, DFv);
    }

    ln_k<<<Mv, 256>>>(x, lnf_s, lnf_b, lnb);
    gemm_h<0, false, 0><<<dim3(Vv / 128, Mv / 128), 256, GEMM_H_SMEM>>>(
        lnb, teh, nullptr, nullptr, logits, nullptr, Mv, Vv, Dv);
}

// round 16
// speedup vs baseline: 2.1806x; 1.0731x over previous
#include <cuda_runtime.h>
#include <cuda_fp16.h>
#include <math.h>

#define Bv   2
#define Tv   2048
#define Dv   768
#define Hv   12
#define HDv  64
#define Lv   4
#define DFv  3072
#define Vv   32000
#define Mv   (Bv*Tv)        /* 4096 rows */
#define QKVN (3*Hv*HDv)     /* 2304 */

// ---------------- scratch (static device globals; no allocs) ----------------
__device__ float  g_x   [Mv*Dv];     // residual stream (fp32)
__device__ __half g_qkvh[Mv*QKVN];   // qkv projection (half)
__device__ __half g_ln  [Mv*Dv];     // layernorm output (half)
__device__ __half g_att [Mv*Dv];     // attention output (half)
__device__ __half g_ff  [Mv*DFv];    // ffn hidden (half)
// half weight copies, transposed to [N,K]
__device__ __half g_wqkv[Lv*QKVN*Dv];
__device__ __half g_wout[Lv*Dv*Dv];
__device__ __half g_wup [Lv*DFv*Dv];
__device__ __half g_wdn [Lv*Dv*DFv];
__device__ __half g_te  [Vv*Dv];     // te is [V,D] = [N,K] already

// ---------------- helpers ----------------
__device__ __forceinline__ void mma_f16(float* c, const unsigned* a, const unsigned* b) {
    asm volatile(
        "mma.sync.aligned.m16n8k16.row.col.f32.f16.f16.f32 "
        "{%0,%1,%2,%3}, {%4,%5,%6,%7}, {%8,%9}, {%0,%1,%2,%3};\n"
        : "+f"(c[0]), "+f"(c[1]), "+f"(c[2]), "+f"(c[3])
        : "r"(a[0]), "r"(a[1]), "r"(a[2]), "r"(a[3]), "r"(b[0]), "r"(b[1]));
}
__device__ __forceinline__ void ldsm4(unsigned* r, unsigned saddr) {
    asm volatile("ldmatrix.sync.aligned.m8n8.x4.shared.b16 {%0,%1,%2,%3}, [%4];"
                 : "=r"(r[0]), "=r"(r[1]), "=r"(r[2]), "=r"(r[3]) : "r"(saddr));
}
__device__ __forceinline__ void cp16(unsigned sdst, const void* g) {
    asm volatile("cp.async.cg.shared.global [%0], [%1], 16;" :: "r"(sdst), "l"(g));
}
__device__ __forceinline__ void cp_commit() { asm volatile("cp.async.commit_group;"); }
template <int N>
__device__ __forceinline__ void cp_wait() {
    asm volatile("cp.async.wait_group %0;" :: "n"(N));
}

// ---------------- weight prep ----------------
__global__ void thsplit_k(const float* __restrict__ W, __half* __restrict__ o,
                          int K, int N) {
    __shared__ float t[32][33];
    const float* Wl = W + (size_t)blockIdx.z * K * N;
    __half* ol = o + (size_t)blockIdx.z * K * N;
    int kb = blockIdx.y * 32, nb = blockIdx.x * 32;
    int tx = threadIdx.x, ty = threadIdx.y;   // 32 x 8
    #pragma unroll
    for (int i = 0; i < 32; i += 8)
        t[ty + i][tx] = Wl[(size_t)(kb + ty + i) * N + nb + tx];
    __syncthreads();
    #pragma unroll
    for (int i = 0; i < 32; i += 8)
        ol[(size_t)(nb + ty + i) * K + kb + tx] = __float2half(t[tx][ty + i]);
}
__global__ void hcvt_k(const float* __restrict__ in, __half* __restrict__ out, int n4) {
    int i = blockIdx.x * blockDim.x + threadIdx.x;
    if (i >= n4) return;
    float4 v = ((const float4*)in)[i];
    __half2* o = (__half2*)out;
    o[i * 2    ] = __floats2half2_rn(v.x, v.y);
    o[i * 2 + 1] = __floats2half2_rn(v.z, v.w);
}

// ---------------- embedding ----------------
__global__ void embed_k(const int* __restrict__ ids, const float* __restrict__ te,
                        const float* __restrict__ pe, float* __restrict__ x) {
    int i = blockIdx.x * blockDim.x + threadIdx.x;
    if (i >= Mv * Dv) return;
    int r = i / Dv, d = i - r * Dv;
    int t = r % Tv;
    x[i] = te[(size_t)ids[r] * Dv + d] + pe[(size_t)t * Dv + d];
}

// ---------------- layernorm (writes half) ----------------
__global__ void ln_k(const float* __restrict__ x, const float* __restrict__ s,
                     const float* __restrict__ bb, __half* __restrict__ y) {
    int r = blockIdx.x;
    const float* xr = x + (size_t)r * Dv;
    __half*      yr = y + (size_t)r * Dv;
    __shared__ float red[8];
    int tid = threadIdx.x; // 256
    float v0 = xr[tid], v1 = xr[tid + 256], v2 = xr[tid + 512];
    float sum = v0 + v1 + v2;
    #pragma unroll
    for (int o = 16; o; o >>= 1) sum += __shfl_xor_sync(0xffffffffu, sum, o);
    if ((tid & 31) == 0) red[tid >> 5] = sum;
    __syncthreads();
    float mu = (red[0]+red[1]+red[2]+red[3]+red[4]+red[5]+red[6]+red[7]) * (1.0f/Dv);
    float d0 = v0 - mu, d1 = v1 - mu, d2 = v2 - mu;
    float sq = d0*d0 + d1*d1 + d2*d2;
    __syncthreads();
    #pragma unroll
    for (int o = 16; o; o >>= 1) sq += __shfl_xor_sync(0xffffffffu, sq, o);
    if ((tid & 31) == 0) red[tid >> 5] = sq;
    __syncthreads();
    float var = (red[0]+red[1]+red[2]+red[3]+red[4]+red[5]+red[6]+red[7]) * (1.0f/Dv);
    float rstd = rsqrtf(var + 1e-5f);
    yr[tid      ] = __float2half(d0 * rstd * s[tid      ] + bb[tid      ]);
    yr[tid + 256] = __float2half(d1 * rstd * s[tid + 256] + bb[tid + 256]);
    yr[tid + 512] = __float2half(d2 * rstd * s[tid + 512] + bb[tid + 512]);
}

// ---------------- fp16 tensor-core GEMM (128x128): C = A @ B^T ------------------
// A[M,K] half, B[N,K] half (pre-transposed). BK=32 halves/slab, 8 warps (4x2),
// warp tile 32x64, m16n8k16, 5-stage cp.async pipeline, ldmatrix fragment loads.
#define HSTU 20
#define NSTG 5
#define TILEW (128*HSTU)
#define SWU (2*TILEW)
#define GEMM_H_SMEM (NSTG * SWU * 4)

template <int ACT, bool RES, int OUT>
__global__ __launch_bounds__(256, 2) void gemm_h(
    const __half* __restrict__ A, const __half* __restrict__ B,
    const float* __restrict__ bias, const float* __restrict__ res,
    float* __restrict__ C, __half* __restrict__ Ch, int M, int N, int K) {
    extern __shared__ unsigned ghsm[];
    const int tid  = threadIdx.x;
    const int lane = tid & 31, warp = tid >> 5;
    const int wm = warp >> 1, wn = warp & 1;
    const int g8 = lane >> 3, lr = lane & 7;
    const int m0 = blockIdx.y * 128, n0 = blockIdx.x * 128;
    const unsigned sbase = (unsigned)__cvta_generic_to_shared(ghsm);

    float acc[2][8][4];
    #pragma unroll
    for (int i = 0; i < 2; i++)
        #pragma unroll
        for (int j = 0; j < 8; j++)
            #pragma unroll
            for (int q = 0; q < 4; q++) acc[i][j][q] = 0.0f;

    auto issue = [&](int stg, int k0) {
        #pragma unroll
        for (int i = 0; i < 2; i++) {
            int c = tid + 256 * i;
            int row = c >> 2, off = (c & 3) * 8;
            unsigned ad = sbase + (stg * SWU + row * HSTU) * 4 + off * 2;
            cp16(ad, A + (size_t)(m0 + row) * K + k0 + off);
            cp16(ad + TILEW * 4, B + (size_t)(n0 + row) * K + k0 + off);
        }
    };

    const int nslab = K / 32;
    #pragma unroll
    for (int s = 0; s < NSTG - 1; s++) {
        if (s < nslab) issue(s, s * 32);
        cp_commit();
    }

    for (int i = 0; i < nslab; i++) {
        cp_wait<NSTG - 2>();
        __syncthreads();

        const unsigned sA = sbase + ((i % NSTG) * SWU) * 4;
        const unsigned sB = sA + TILEW * 4;

        #pragma unroll
        for (int ks = 0; ks < 2; ks++) {
            const int kb = ks * 8;
            unsigned af[2][4], bf[8][2];
            #pragma unroll
            for (int mt = 0; mt < 2; mt++) {
                int m = wm * 32 + mt * 16 + (g8 & 1) * 8 + lr;
                ldsm4(af[mt], sA + (m * HSTU + kb + (g8 >> 1) * 4) * 4);
            }
            #pragma unroll
            for (int ntp = 0; ntp < 8; ntp += 2) {
                int n = wn * 64 + ntp * 8 + (g8 >> 1) * 8 + lr;
                unsigned tmp[4];
                ldsm4(tmp, sB + (n * HSTU + kb + (g8 & 1) * 4) * 4);
                bf[ntp][0] = tmp[0]; bf[ntp][1] = tmp[1];
                bf[ntp + 1][0] = tmp[2]; bf[ntp + 1][1] = tmp[3];
            }
            #pragma unroll
            for (int mt = 0; mt < 2; mt++)
                #pragma unroll
                for (int nt = 0; nt < 8; nt++)
                    mma_f16(acc[mt][nt], af[mt], bf[nt]);
        }

        int j = i + NSTG - 1;
        if (j < nslab) issue(j % NSTG, j * 32);
        cp_commit();
    }

    #pragma unroll
    for (int mt = 0; mt < 2; mt++) {
        int r0 = m0 + wm * 32 + mt * 16 + (lane >> 2);
        #pragma unroll
        for (int nt = 0; nt < 8; nt++) {
            int c0i = n0 + wn * 64 + nt * 8 + 2 * (lane & 3);
            #pragma unroll
            for (int half = 0; half < 2; half++) {
                int r = r0 + half * 8;
                float v0 = acc[mt][nt][half * 2 + 0];
                float v1 = acc[mt][nt][half * 2 + 1];
                if (bias) { v0 += bias[c0i]; v1 += bias[c0i + 1]; }
                if (ACT == 1) {
                    v0 = v0 * (1.0f / (1.0f + __expf(-v0)));
                    v1 = v1 * (1.0f / (1.0f + __expf(-v1)));
                }
                if (RES) {
                    const float* rp = res + (size_t)r * N + c0i;
                    v0 += rp[0]; v1 += rp[1];
                }
                if (OUT == 2) {
                    *(__half2*)(Ch + (size_t)r * N + c0i) = __floats2half2_rn(v0, v1);
                } else {
                    *(float2*)(C + (size_t)r * N + c0i) = make_float2(v0, v1);
                }
            }
        }
    }
}

// ---------------- fp16 GEMM, 128x64 tile (out/dn projections) ------------------
#define NSTG4 4
#define SW64 (TILEW + 64*HSTU)
#define GEMM_H64_SMEM (NSTG4 * SW64 * 4)

template <int ACT, bool RES, int OUT>
__global__ __launch_bounds__(256, 3) void gemm_h64(
    const __half* __restrict__ A, const __half* __restrict__ B,
    const float* __restrict__ bias, const float* __restrict__ res,
    float* __restrict__ C, __half* __restrict__ Ch, int M, int N, int K) {
    extern __shared__ unsigned ghsm[];
    const int tid  = threadIdx.x;
    const int lane = tid & 31, warp = tid >> 5;
    const int wm = warp >> 1, wn = warp & 1;
    const int g8 = lane >> 3, lr = lane & 7;
    const int m0 = blockIdx.y * 128, n0 = blockIdx.x * 64;
    const unsigned sbase = (unsigned)__cvta_generic_to_shared(ghsm);

    float acc[2][4][4];
    #pragma unroll
    for (int i = 0; i < 2; i++)
        #pragma unroll
        for (int j = 0; j < 4; j++)
            #pragma unroll
            for (int q = 0; q < 4; q++) acc[i][j][q] = 0.0f;

    auto issue = [&](int stg, int k0) {
        #pragma unroll
        for (int i = 0; i < 3; i++) {
            int c = tid + 256 * i;
            if (c < 512) {
                int row = c >> 2, off = (c & 3) * 8;
                unsigned ad = sbase + (stg * SW64 + row * HSTU) * 4 + off * 2;
                cp16(ad, A + (size_t)(m0 + row) * K + k0 + off);
            } else {
                int cb = c - 512;
                int row = cb >> 2, off = (cb & 3) * 8;
                unsigned bd = sbase + (stg * SW64 + TILEW + row * HSTU) * 4 + off * 2;
                cp16(bd, B + (size_t)(n0 + row) * K + k0 + off);
            }
        }
    };

    const int nslab = K / 32;
    #pragma unroll
    for (int s = 0; s < NSTG4 - 1; s++) {
        if (s < nslab) issue(s, s * 32);
        cp_commit();
    }

    for (int i = 0; i < nslab; i++) {
        cp_wait<NSTG4 - 2>();
        __syncthreads();

        const unsigned sA = sbase + ((i % NSTG4) * SW64) * 4;
        const unsigned sB = sA + TILEW * 4;

        #pragma unroll
        for (int ks = 0; ks < 2; ks++) {
            const int kb = ks * 8;
            unsigned af[2][4], bf[4][2];
            #pragma unroll
            for (int mt = 0; mt < 2; mt++) {
                int m = wm * 32 + mt * 16 + (g8 & 1) * 8 + lr;
                ldsm4(af[mt], sA + (m * HSTU + kb + (g8 >> 1) * 4) * 4);
            }
            #pragma unroll
            for (int ntp = 0; ntp < 4; ntp += 2) {
                int n = wn * 32 + ntp * 8 + (g8 >> 1) * 8 + lr;
                unsigned tmp[4];
                ldsm4(tmp, sB + (n * HSTU + kb + (g8 & 1) * 4) * 4);
                bf[ntp][0] = tmp[0]; bf[ntp][1] = tmp[1];
                bf[ntp + 1][0] = tmp[2]; bf[ntp + 1][1] = tmp[3];
            }
            #pragma unroll
            for (int mt = 0; mt < 2; mt++)
                #pragma unroll
                for (int nt = 0; nt < 4; nt++)
                    mma_f16(acc[mt][nt], af[mt], bf[nt]);
        }

        int j = i + NSTG4 - 1;
        if (j < nslab) issue(j % NSTG4, j * 32);
        cp_commit();
    }

    #pragma unroll
    for (int mt = 0; mt < 2; mt++) {
        int r0 = m0 + wm * 32 + mt * 16 + (lane >> 2);
        #pragma unroll
        for (int nt = 0; nt < 4; nt++) {
            int c0i = n0 + wn * 32 + nt * 8 + 2 * (lane & 3);
            #pragma unroll
            for (int half = 0; half < 2; half++) {
                int r = r0 + half * 8;
                float v0 = acc[mt][nt][half * 2 + 0];
                float v1 = acc[mt][nt][half * 2 + 1];
                if (bias) { v0 += bias[c0i]; v1 += bias[c0i + 1]; }
                if (ACT == 1) {
                    v0 = v0 * (1.0f / (1.0f + __expf(-v0)));
                    v1 = v1 * (1.0f / (1.0f + __expf(-v1)));
                }
                if (RES) {
                    const float* rp = res + (size_t)r * N + c0i;
                    v0 += rp[0]; v1 += rp[1];
                }
                if (OUT == 2) {
                    *(__half2*)(Ch + (size_t)r * N + c0i) = __floats2half2_rn(v0, v1);
                } else {
                    *(float2*)(C + (size_t)r * N + c0i) = make_float2(v0, v1);
                }
            }
        }
    }
}

// ---------------- fp16 flash attention, register-resident softmax --------------
#define AHS 36
#define ATTN_SMEM ((4*64*AHS + 6*64) * 4)

__global__ __launch_bounds__(256) void attn_h_k(
    const __half* __restrict__ qkv, __half* __restrict__ out) {
    extern __shared__ unsigned asm_[];
    unsigned* Qs = asm_;                      // [64][AHS]
    unsigned* Ks = Qs + 64 * AHS;             // [64][AHS]
    unsigned* Vt = Ks + 64 * AHS;             // [64 d][AHS] (V transposed)
    unsigned* Ps = Vt + 64 * AHS;             // [64][AHS]  (P halves, exchange)
    float*    m_sm  = (float*)(Ps + 64 * AHS);  // [64]
    float*    l_sm  = m_sm + 64;                // [64]
    float*    wmax  = l_sm + 64;                // [2][64]
    float*    wsum  = wmax + 2 * 64;            // [2][64]

    const int q0 = ((int)gridDim.x - 1 - (int)blockIdx.x) * 64;  // heavy-first
    const int h  = blockIdx.y;
    const int b  = blockIdx.z;
    const int tid = threadIdx.x;
    const int lane = tid & 31, warp = tid >> 5;
    const int wm = warp >> 1, wn = warp & 1;   // 4 x 2, warp S-tile 16x32
    const int lrow = lane >> 2, lcol = lane & 3;

    const __half* qbase = qkv + (size_t)(b * Tv) * QKVN + h * HDv;
    const __half* kbase = qbase + Hv * HDv;
    const __half* vbase = qbase + 2 * Hv * HDv;

    const int srow = tid >> 2, sseg = tid & 3;

    {
        const __half* src = qbase + (size_t)(q0 + srow) * QKVN + sseg * 16;
        uint4 a = *(const uint4*)src;
        uint4 bq = *(const uint4*)(src + 8);
        unsigned va[8] = {a.x, a.y, a.z, a.w, bq.x, bq.y, bq.z, bq.w};
        const __half2 sc = __floats2half2_rn(0.125f, 0.125f);
        unsigned* dst = Qs + srow * AHS + sseg * 8;
        #pragma unroll
        for (int i = 0; i < 8; i++) {
            __half2 hv = __hmul2(*(__half2*)&va[i], sc);
            dst[i] = *(unsigned*)&hv;
        }
    }
    if (tid < 64) { m_sm[tid] = -1e30f; l_sm[tid] = 0.0f; }

    float acc_o[4][4];
    #pragma unroll
    for (int i = 0; i < 4; i++)
        #pragma unroll
        for (int j = 0; j < 4; j++) acc_o[i][j] = 0.0f;

    for (int c0 = 0; c0 <= q0; c0 += 64) {
        {
            const __half* ksrc = kbase + (size_t)(c0 + srow) * QKVN + sseg * 16;
            uint4 a = *(const uint4*)ksrc;
            uint4 bk = *(const uint4*)(ksrc + 8);
            unsigned* dst = Ks + srow * AHS + sseg * 8;
            *(uint4*)dst = a;
            *(uint4*)(dst + 4) = bk;

            const __half* vsrc = vbase + (size_t)(c0 + srow) * QKVN + sseg * 16;
            uint4 va = *(const uint4*)vsrc;
            uint4 vb = *(const uint4*)(vsrc + 8);
            unsigned vv[8] = {va.x, va.y, va.z, va.w, vb.x, vb.y, vb.z, vb.w};
            __half* VtH = (__half*)Vt;
            #pragma unroll
            for (int i = 0; i < 8; i++) {
                int d = sseg * 16 + i * 2;
                __half2 hv = *(__half2*)&vv[i];
                VtH[(size_t)d * (AHS * 2) + srow]       = __low2half(hv);
                VtH[(size_t)(d + 1) * (AHS * 2) + srow] = __high2half(hv);
            }
        }
        __syncthreads();                                   // (1)

        float s_acc[4][4];
        #pragma unroll
        for (int i = 0; i < 4; i++)
            #pragma unroll
            for (int j = 0; j < 4; j++) s_acc[i][j] = 0.0f;
        #pragma unroll
        for (int kb = 0; kb < 32; kb += 8) {
            unsigned af[4], bf[4][2];
            int mr = wm * 16 + lrow;
            int kk = kb + lcol;
            af[0] = Qs[mr * AHS + kk];
            af[1] = Qs[(mr + 8) * AHS + kk];
            af[2] = Qs[mr * AHS + kk + 4];
            af[3] = Qs[(mr + 8) * AHS + kk + 4];
            #pragma unroll
            for (int nt = 0; nt < 4; nt++) {
                int n = wn * 32 + nt * 8 + lrow;
                bf[nt][0] = Ks[n * AHS + kk];
                bf[nt][1] = Ks[n * AHS + kk + 4];
            }
            #pragma unroll
            for (int nt = 0; nt < 4; nt++)
                mma_f16(s_acc[nt], af, bf[nt]);
        }

        if (c0 == q0) {
            #pragma unroll
            for (int nt = 0; nt < 4; nt++) {
                int c = wn * 32 + nt * 8 + 2 * lcol;
                int r0r = wm * 16 + lrow;
                if (c     > r0r)     s_acc[nt][0] = -1e30f;
                if (c + 1 > r0r)     s_acc[nt][1] = -1e30f;
                if (c     > r0r + 8) s_acc[nt][2] = -1e30f;
                if (c + 1 > r0r + 8) s_acc[nt][3] = -1e30f;
            }
        }

        float mx0 = -1e30f, mx1 = -1e30f;
        #pragma unroll
        for (int nt = 0; nt < 4; nt++) {
            mx0 = fmaxf(mx0, fmaxf(s_acc[nt][0], s_acc[nt][1]));
            mx1 = fmaxf(mx1, fmaxf(s_acc[nt][2], s_acc[nt][3]));
        }
        mx0 = fmaxf(mx0, __shfl_xor_sync(0xffffffffu, mx0, 1));
        mx0 = fmaxf(mx0, __shfl_xor_sync(0xffffffffu, mx0, 2));
        mx1 = fmaxf(mx1, __shfl_xor_sync(0xffffffffu, mx1, 1));
        mx1 = fmaxf(mx1, __shfl_xor_sync(0xffffffffu, mx1, 2));
        if (lcol == 0) {
            wmax[wn * 64 + wm * 16 + lrow]     = mx0;
            wmax[wn * 64 + wm * 16 + lrow + 8] = mx1;
        }
        __syncthreads();                                   // (2)

        int row0 = wm * 16 + lrow, row1 = row0 + 8;
        float m_old0 = m_sm[row0], m_old1 = m_sm[row1];
        float m_new0 = fmaxf(m_old0, fmaxf(wmax[row0], wmax[64 + row0]));
        float m_new1 = fmaxf(m_old1, fmaxf(wmax[row1], wmax[64 + row1]));
        float scale0 = __expf(m_old0 - m_new0);
        float scale1 = __expf(m_old1 - m_new1);
        float cs0 = 0.0f, cs1 = 0.0f;
        unsigned pk[4][2];
        #pragma unroll
        for (int nt = 0; nt < 4; nt++) {
            float p0 = __expf(s_acc[nt][0] - m_new0);
            float p1 = __expf(s_acc[nt][1] - m_new0);
            float p2 = __expf(s_acc[nt][2] - m_new1);
            float p3 = __expf(s_acc[nt][3] - m_new1);
            cs0 += p0 + p1; cs1 += p2 + p3;
            __half2 h0 = __floats2half2_rn(p0, p1);
            __half2 h1 = __floats2half2_rn(p2, p3);
            pk[nt][0] = *(unsigned*)&h0;
            pk[nt][1] = *(unsigned*)&h1;
        }
        cs0 += __shfl_xor_sync(0xffffffffu, cs0, 1);
        cs0 += __shfl_xor_sync(0xffffffffu, cs0, 2);
        cs1 += __shfl_xor_sync(0xffffffffu, cs1, 1);
        cs1 += __shfl_xor_sync(0xffffffffu, cs1, 2);
        if (lcol == 0) {
            wsum[wn * 64 + row0] = cs0;
            wsum[wn * 64 + row1] = cs1;
        }
        #pragma unroll
        for (int nt = 0; nt < 4; nt++) {
            Ps[row0 * AHS + wn * 16 + nt * 4 + lcol] = pk[nt][0];
            Ps[row1 * AHS + wn * 16 + nt * 4 + lcol] = pk[nt][1];
        }
        __syncthreads();                                   // (3)

        if (wn == 0 && lcol == 0) {
            l_sm[row0] = l_sm[row0] * scale0 + wsum[row0] + wsum[64 + row0];
            l_sm[row1] = l_sm[row1] * scale1 + wsum[row1] + wsum[64 + row1];
            m_sm[row0] = m_new0;
            m_sm[row1] = m_new1;
        }

        #pragma unroll
        for (int nt = 0; nt < 4; nt++) {
            acc_o[nt][0] *= scale0; acc_o[nt][1] *= scale0;
            acc_o[nt][2] *= scale1; acc_o[nt][3] *= scale1;
        }
        #pragma unroll
        for (int kb = 0; kb < 32; kb += 8) {
            unsigned af[4], bf[4][2];
            int mr = wm * 16 + lrow;
            int kk = kb + lcol;
            af[0] = Ps[mr * AHS + kk];
            af[1] = Ps[(mr + 8) * AHS + kk];
            af[2] = Ps[mr * AHS + kk + 4];
            af[3] = Ps[(mr + 8) * AHS + kk + 4];
            #pragma unroll
            for (int nt = 0; nt < 4; nt++) {
                int n = wn * 32 + nt * 8 + lrow;
                bf[nt][0] = Vt[n * AHS + kk];
                bf[nt][1] = Vt[n * AHS + kk + 4];
            }
            #pragma unroll
            for (int nt = 0; nt < 4; nt++)
                mma_f16(acc_o[nt], af, bf[nt]);
        }
        __syncthreads();                                   // (4)
    }

    {
        int r1 = wm * 16 + lrow;
        float inv1 = 1.0f / l_sm[r1], inv2 = 1.0f / l_sm[r1 + 8];
        #pragma unroll
        for (int nt = 0; nt < 4; nt++) {
            int c = wn * 32 + nt * 8 + 2 * lcol;
            __half* o1 = out + (size_t)(b * Tv + q0 + r1) * Dv + h * HDv + c;
            __half* o2 = out + (size_t)(b * Tv + q0 + r1 + 8) * Dv + h * HDv + c;
            *(__half2*)o1 = __floats2half2_rn(acc_o[nt][0] * inv1, acc_o[nt][1] * inv1);
            *(__half2*)o2 = __floats2half2_rn(acc_o[nt][2] * inv2, acc_o[nt][3] * inv2);
        }
    }
}

// ---------------- driver ----------------
extern "C" void kernel_launch(void* const* d_in, const int* in_sizes, int n_in,
                              void* d_out, int out_size) {
    const int*   ids   = (const int*)  d_in[0];
    const float* te    = (const float*)d_in[1];
    const float* pe    = (const float*)d_in[2];
    const float* ln1_s = (const float*)d_in[3];
    const float* ln1_b = (const float*)d_in[4];
    const float* qkv_w = (const float*)d_in[5];
    const float* qkv_b = (const float*)d_in[6];
    const float* out_w = (const float*)d_in[7];
    const float* out_b = (const float*)d_in[8];
    const float* ln2_s = (const float*)d_in[9];
    const float* ln2_b = (const float*)d_in[10];
    const float* up_w  = (const float*)d_in[11];
    const float* up_b  = (const float*)d_in[12];
    const float* dn_w  = (const float*)d_in[13];
    const float* dn_b  = (const float*)d_in[14];
    const float* lnf_s = (const float*)d_in[15];
    const float* lnf_b = (const float*)d_in[16];
    float* logits = (float*)d_out;

    float *x;
    __half *qkvh, *lnb, *att, *ff, *wqkv, *wout, *wup, *wdn, *teh;
    cudaGetSymbolAddress((void**)&x,    g_x);
    cudaGetSymbolAddress((void**)&qkvh, g_qkvh);
    cudaGetSymbolAddress((void**)&lnb,  g_ln);
    cudaGetSymbolAddress((void**)&att,  g_att);
    cudaGetSymbolAddress((void**)&ff,   g_ff);
    cudaGetSymbolAddress((void**)&wqkv, g_wqkv);
    cudaGetSymbolAddress((void**)&wout, g_wout);
    cudaGetSymbolAddress((void**)&wup,  g_wup);
    cudaGetSymbolAddress((void**)&wdn,  g_wdn);
    cudaGetSymbolAddress((void**)&teh,  g_te);

    cudaFuncSetAttribute(attn_h_k,
                         cudaFuncAttributeMaxDynamicSharedMemorySize, ATTN_SMEM);
    cudaFuncSetAttribute(gemm_h<0, false, 2>,
                         cudaFuncAttributeMaxDynamicSharedMemorySize, GEMM_H_SMEM);
    cudaFuncSetAttribute(gemm_h<1, false, 2>,
                         cudaFuncAttributeMaxDynamicSharedMemorySize, GEMM_H_SMEM);
    cudaFuncSetAttribute(gemm_h<0, false, 0>,
                         cudaFuncAttributeMaxDynamicSharedMemorySize, GEMM_H_SMEM);
    cudaFuncSetAttribute(gemm_h64<0, true, 0>,
                         cudaFuncAttributeMaxDynamicSharedMemorySize, GEMM_H64_SMEM);

    // ---- weight prep: transpose + half-convert (every launch; deterministic) ----
    {
        dim3 blk(32, 8);
        thsplit_k<<<dim3(QKVN / 32, Dv / 32, Lv), blk>>>(qkv_w, wqkv, Dv, QKVN);
        thsplit_k<<<dim3(Dv / 32,   Dv / 32, Lv), blk>>>(out_w, wout, Dv, Dv);
        thsplit_k<<<dim3(DFv / 32,  Dv / 32, Lv), blk>>>(up_w,  wup,  Dv, DFv);
        thsplit_k<<<dim3(Dv / 32,  DFv / 32, Lv), blk>>>(dn_w,  wdn,  DFv, Dv);
        int n4 = Vv * Dv / 4;
        hcvt_k<<<(n4 + 255) / 256, 256>>>(te, teh, n4);
    }

    embed_k<<<(Mv * Dv + 255) / 256, 256>>>(ids, te, pe, x);

    for (int i = 0; i < Lv; i++) {
        ln_k<<<Mv, 256>>>(x, ln1_s + (size_t)i * Dv, ln1_b + (size_t)i * Dv, lnb);
        gemm_h<0, false, 2><<<dim3(QKVN / 128, Mv / 128), 256, GEMM_H_SMEM>>>(
            lnb, wqkv + (size_t)i * QKVN * Dv, qkv_b + (size_t)i * QKVN,
            nullptr, nullptr, qkvh, Mv, QKVN, Dv);
        attn_h_k<<<dim3(Tv / 64, Hv, Bv), 256, ATTN_SMEM>>>(qkvh, att);
        gemm_h64<0, true, 0><<<dim3(Dv / 64, Mv / 128), 256, GEMM_H64_SMEM>>>(
            att, wout + (size_t)i * Dv * Dv, out_b + (size_t)i * Dv,
            x, x, nullptr, Mv, Dv, Dv);
        ln_k<<<Mv, 256>>>(x, ln2_s + (size_t)i * Dv, ln2_b + (size_t)i * Dv, lnb);
        gemm_h<1, false, 2><<<dim3(DFv / 128, Mv / 128), 256, GEMM_H_SMEM>>>(
            lnb, wup + (size_t)i * DFv * Dv, up_b + (size_t)i * DFv,
            nullptr, nullptr, ff, Mv, DFv, Dv);
        gemm_h64<0, true, 0><<<dim3(Dv / 64, Mv / 128), 256, GEMM_H64_SMEM>>>(
            ff, wdn + (size_t)i * Dv * DFv, dn_b + (size_t)i * Dv,
            x, x, nullptr, Mv, Dv, DFv);
    }

    ln_k<<<Mv, 256>>>(x, lnf_s, lnf_b, lnb);
    gemm_h<0, false, 0><<<dim3(Vv / 128, Mv / 128), 256, GEMM_H_SMEM>>>(
        lnb, teh, nullptr, nullptr, logits, nullptr, Mv, Vv, Dv);
}

// round 17
// speedup vs baseline: 2.2178x; 1.0171x over previous
#include <cuda_runtime.h>
#include <cuda_fp16.h>
#include <math.h>

#define Bv   2
#define Tv   2048
#define Dv   768
#define Hv   12
#define HDv  64
#define Lv   4
#define DFv  3072
#define Vv   32000
#define Mv   (Bv*Tv)        /* 4096 rows */
#define QKVN (3*Hv*HDv)     /* 2304 */

// ---------------- scratch (static device globals; no allocs) ----------------
__device__ float  g_x   [Mv*Dv];     // residual stream (fp32)
__device__ __half g_qkvh[Mv*QKVN];   // qkv projection (half)
__device__ __half g_ln  [Mv*Dv];     // layernorm output (half)
__device__ __half g_att [Mv*Dv];     // attention output (half)
__device__ __half g_ff  [Mv*DFv];    // ffn hidden (half)
// half weight copies, transposed to [N,K]
__device__ __half g_wqkv[Lv*QKVN*Dv];
__device__ __half g_wout[Lv*Dv*Dv];
__device__ __half g_wup [Lv*DFv*Dv];
__device__ __half g_wdn [Lv*Dv*DFv];
__device__ __half g_te  [Vv*Dv];     // te is [V,D] = [N,K] already

// ---------------- helpers ----------------
__device__ __forceinline__ void mma_f16(float* c, const unsigned* a, const unsigned* b) {
    asm volatile(
        "mma.sync.aligned.m16n8k16.row.col.f32.f16.f16.f32 "
        "{%0,%1,%2,%3}, {%4,%5,%6,%7}, {%8,%9}, {%0,%1,%2,%3};\n"
        : "+f"(c[0]), "+f"(c[1]), "+f"(c[2]), "+f"(c[3])
        : "r"(a[0]), "r"(a[1]), "r"(a[2]), "r"(a[3]), "r"(b[0]), "r"(b[1]));
}
__device__ __forceinline__ void ldsm4(unsigned* r, unsigned saddr) {
    asm volatile("ldmatrix.sync.aligned.m8n8.x4.shared.b16 {%0,%1,%2,%3}, [%4];"
                 : "=r"(r[0]), "=r"(r[1]), "=r"(r[2]), "=r"(r[3]) : "r"(saddr));
}
__device__ __forceinline__ void cp16(unsigned sdst, const void* g) {
    asm volatile("cp.async.cg.shared.global [%0], [%1], 16;" :: "r"(sdst), "l"(g));
}
__device__ __forceinline__ void cp_commit() { asm volatile("cp.async.commit_group;"); }
template <int N>
__device__ __forceinline__ void cp_wait() {
    asm volatile("cp.async.wait_group %0;" :: "n"(N));
}

// ---------------- weight prep ----------------
__global__ void thsplit_k(const float* __restrict__ W, __half* __restrict__ o,
                          int K, int N) {
    __shared__ float t[32][33];
    const float* Wl = W + (size_t)blockIdx.z * K * N;
    __half* ol = o + (size_t)blockIdx.z * K * N;
    int kb = blockIdx.y * 32, nb = blockIdx.x * 32;
    int tx = threadIdx.x, ty = threadIdx.y;   // 32 x 8
    #pragma unroll
    for (int i = 0; i < 32; i += 8)
        t[ty + i][tx] = Wl[(size_t)(kb + ty + i) * N + nb + tx];
    __syncthreads();
    #pragma unroll
    for (int i = 0; i < 32; i += 8)
        ol[(size_t)(nb + ty + i) * K + kb + tx] = __float2half(t[tx][ty + i]);
}
__global__ void hcvt_k(const float* __restrict__ in, __half* __restrict__ out, int n4) {
    int i = blockIdx.x * blockDim.x + threadIdx.x;
    if (i >= n4) return;
    float4 v = ((const float4*)in)[i];
    __half2* o = (__half2*)out;
    o[i * 2    ] = __floats2half2_rn(v.x, v.y);
    o[i * 2 + 1] = __floats2half2_rn(v.z, v.w);
}

// ---------------- embedding ----------------
__global__ void embed_k(const int* __restrict__ ids, const float* __restrict__ te,
                        const float* __restrict__ pe, float* __restrict__ x) {
    int i = blockIdx.x * blockDim.x + threadIdx.x;
    if (i >= Mv * Dv) return;
    int r = i / Dv, d = i - r * Dv;
    int t = r % Tv;
    x[i] = te[(size_t)ids[r] * Dv + d] + pe[(size_t)t * Dv + d];
}

// ---------------- layernorm (writes half) ----------------
__global__ void ln_k(const float* __restrict__ x, const float* __restrict__ s,
                     const float* __restrict__ bb, __half* __restrict__ y) {
    int r = blockIdx.x;
    const float* xr = x + (size_t)r * Dv;
    __half*      yr = y + (size_t)r * Dv;
    __shared__ float red[8];
    int tid = threadIdx.x; // 256
    float v0 = xr[tid], v1 = xr[tid + 256], v2 = xr[tid + 512];
    float sum = v0 + v1 + v2;
    #pragma unroll
    for (int o = 16; o; o >>= 1) sum += __shfl_xor_sync(0xffffffffu, sum, o);
    if ((tid & 31) == 0) red[tid >> 5] = sum;
    __syncthreads();
    float mu = (red[0]+red[1]+red[2]+red[3]+red[4]+red[5]+red[6]+red[7]) * (1.0f/Dv);
    float d0 = v0 - mu, d1 = v1 - mu, d2 = v2 - mu;
    float sq = d0*d0 + d1*d1 + d2*d2;
    __syncthreads();
    #pragma unroll
    for (int o = 16; o; o >>= 1) sq += __shfl_xor_sync(0xffffffffu, sq, o);
    if ((tid & 31) == 0) red[tid >> 5] = sq;
    __syncthreads();
    float var = (red[0]+red[1]+red[2]+red[3]+red[4]+red[5]+red[6]+red[7]) * (1.0f/Dv);
    float rstd = rsqrtf(var + 1e-5f);
    yr[tid      ] = __float2half(d0 * rstd * s[tid      ] + bb[tid      ]);
    yr[tid + 256] = __float2half(d1 * rstd * s[tid + 256] + bb[tid + 256]);
    yr[tid + 512] = __float2half(d2 * rstd * s[tid + 512] + bb[tid + 512]);
}

// ---------------- fp16 tensor-core GEMM (128x128): C = A @ B^T ------------------
#define HSTU 20
#define NSTG 5
#define TILEW (128*HSTU)
#define SWU (2*TILEW)
#define GEMM_H_SMEM (NSTG * SWU * 4)

template <int ACT, bool RES, int OUT>
__global__ __launch_bounds__(256, 2) void gemm_h(
    const __half* __restrict__ A, const __half* __restrict__ B,
    const float* __restrict__ bias, const float* __restrict__ res,
    float* __restrict__ C, __half* __restrict__ Ch, int M, int N, int K) {
    extern __shared__ unsigned ghsm[];
    const int tid  = threadIdx.x;
    const int lane = tid & 31, warp = tid >> 5;
    const int wm = warp >> 1, wn = warp & 1;
    const int g8 = lane >> 3, lr = lane & 7;
    const int m0 = blockIdx.y * 128, n0 = blockIdx.x * 128;
    const unsigned sbase = (unsigned)__cvta_generic_to_shared(ghsm);

    float acc[2][8][4];
    #pragma unroll
    for (int i = 0; i < 2; i++)
        #pragma unroll
        for (int j = 0; j < 8; j++)
            #pragma unroll
            for (int q = 0; q < 4; q++) acc[i][j][q] = 0.0f;

    auto issue = [&](int stg, int k0) {
        #pragma unroll
        for (int i = 0; i < 2; i++) {
            int c = tid + 256 * i;
            int row = c >> 2, off = (c & 3) * 8;
            unsigned ad = sbase + (stg * SWU + row * HSTU) * 4 + off * 2;
            cp16(ad, A + (size_t)(m0 + row) * K + k0 + off);
            cp16(ad + TILEW * 4, B + (size_t)(n0 + row) * K + k0 + off);
        }
    };

    const int nslab = K / 32;
    #pragma unroll
    for (int s = 0; s < NSTG - 1; s++) {
        if (s < nslab) issue(s, s * 32);
        cp_commit();
    }

    for (int i = 0; i < nslab; i++) {
        cp_wait<NSTG - 2>();
        __syncthreads();

        const unsigned sA = sbase + ((i % NSTG) * SWU) * 4;
        const unsigned sB = sA + TILEW * 4;

        #pragma unroll
        for (int ks = 0; ks < 2; ks++) {
            const int kb = ks * 8;
            unsigned af[2][4], bf[8][2];
            #pragma unroll
            for (int mt = 0; mt < 2; mt++) {
                int m = wm * 32 + mt * 16 + (g8 & 1) * 8 + lr;
                ldsm4(af[mt], sA + (m * HSTU + kb + (g8 >> 1) * 4) * 4);
            }
            #pragma unroll
            for (int ntp = 0; ntp < 8; ntp += 2) {
                int n = wn * 64 + ntp * 8 + (g8 >> 1) * 8 + lr;
                unsigned tmp[4];
                ldsm4(tmp, sB + (n * HSTU + kb + (g8 & 1) * 4) * 4);
                bf[ntp][0] = tmp[0]; bf[ntp][1] = tmp[1];
                bf[ntp + 1][0] = tmp[2]; bf[ntp + 1][1] = tmp[3];
            }
            #pragma unroll
            for (int mt = 0; mt < 2; mt++)
                #pragma unroll
                for (int nt = 0; nt < 8; nt++)
                    mma_f16(acc[mt][nt], af[mt], bf[nt]);
        }

        int j = i + NSTG - 1;
        if (j < nslab) issue(j % NSTG, j * 32);
        cp_commit();
    }

    #pragma unroll
    for (int mt = 0; mt < 2; mt++) {
        int r0 = m0 + wm * 32 + mt * 16 + (lane >> 2);
        #pragma unroll
        for (int nt = 0; nt < 8; nt++) {
            int c0i = n0 + wn * 64 + nt * 8 + 2 * (lane & 3);
            #pragma unroll
            for (int half = 0; half < 2; half++) {
                int r = r0 + half * 8;
                float v0 = acc[mt][nt][half * 2 + 0];
                float v1 = acc[mt][nt][half * 2 + 1];
                if (bias) { v0 += bias[c0i]; v1 += bias[c0i + 1]; }
                if (ACT == 1) {
                    v0 = v0 * (1.0f / (1.0f + __expf(-v0)));
                    v1 = v1 * (1.0f / (1.0f + __expf(-v1)));
                }
                if (RES) {
                    const float* rp = res + (size_t)r * N + c0i;
                    v0 += rp[0]; v1 += rp[1];
                }
                if (OUT == 2) {
                    *(__half2*)(Ch + (size_t)r * N + c0i) = __floats2half2_rn(v0, v1);
                } else {
                    *(float2*)(C + (size_t)r * N + c0i) = make_float2(v0, v1);
                }
            }
        }
    }
}

// ---------------- fp16 GEMM, 128x64 tile (out/dn projections) ------------------
#define NSTG4 4
#define SW64 (TILEW + 64*HSTU)
#define GEMM_H64_SMEM (NSTG4 * SW64 * 4)

template <int ACT, bool RES, int OUT>
__global__ __launch_bounds__(256, 3) void gemm_h64(
    const __half* __restrict__ A, const __half* __restrict__ B,
    const float* __restrict__ bias, const float* __restrict__ res,
    float* __restrict__ C, __half* __restrict__ Ch, int M, int N, int K) {
    extern __shared__ unsigned ghsm[];
    const int tid  = threadIdx.x;
    const int lane = tid & 31, warp = tid >> 5;
    const int wm = warp >> 1, wn = warp & 1;
    const int g8 = lane >> 3, lr = lane & 7;
    const int m0 = blockIdx.y * 128, n0 = blockIdx.x * 64;
    const unsigned sbase = (unsigned)__cvta_generic_to_shared(ghsm);

    float acc[2][4][4];
    #pragma unroll
    for (int i = 0; i < 2; i++)
        #pragma unroll
        for (int j = 0; j < 4; j++)
            #pragma unroll
            for (int q = 0; q < 4; q++) acc[i][j][q] = 0.0f;

    auto issue = [&](int stg, int k0) {
        #pragma unroll
        for (int i = 0; i < 3; i++) {
            int c = tid + 256 * i;
            if (c < 512) {
                int row = c >> 2, off = (c & 3) * 8;
                unsigned ad = sbase + (stg * SW64 + row * HSTU) * 4 + off * 2;
                cp16(ad, A + (size_t)(m0 + row) * K + k0 + off);
            } else {
                int cb = c - 512;
                int row = cb >> 2, off = (cb & 3) * 8;
                unsigned bd = sbase + (stg * SW64 + TILEW + row * HSTU) * 4 + off * 2;
                cp16(bd, B + (size_t)(n0 + row) * K + k0 + off);
            }
        }
    };

    const int nslab = K / 32;
    #pragma unroll
    for (int s = 0; s < NSTG4 - 1; s++) {
        if (s < nslab) issue(s, s * 32);
        cp_commit();
    }

    for (int i = 0; i < nslab; i++) {
        cp_wait<NSTG4 - 2>();
        __syncthreads();

        const unsigned sA = sbase + ((i % NSTG4) * SW64) * 4;
        const unsigned sB = sA + TILEW * 4;

        #pragma unroll
        for (int ks = 0; ks < 2; ks++) {
            const int kb = ks * 8;
            unsigned af[2][4], bf[4][2];
            #pragma unroll
            for (int mt = 0; mt < 2; mt++) {
                int m = wm * 32 + mt * 16 + (g8 & 1) * 8 + lr;
                ldsm4(af[mt], sA + (m * HSTU + kb + (g8 >> 1) * 4) * 4);
            }
            #pragma unroll
            for (int ntp = 0; ntp < 4; ntp += 2) {
                int n = wn * 32 + ntp * 8 + (g8 >> 1) * 8 + lr;
                unsigned tmp[4];
                ldsm4(tmp, sB + (n * HSTU + kb + (g8 & 1) * 4) * 4);
                bf[ntp][0] = tmp[0]; bf[ntp][1] = tmp[1];
                bf[ntp + 1][0] = tmp[2]; bf[ntp + 1][1] = tmp[3];
            }
            #pragma unroll
            for (int mt = 0; mt < 2; mt++)
                #pragma unroll
                for (int nt = 0; nt < 4; nt++)
                    mma_f16(acc[mt][nt], af[mt], bf[nt]);
        }

        int j = i + NSTG4 - 1;
        if (j < nslab) issue(j % NSTG4, j * 32);
        cp_commit();
    }

    #pragma unroll
    for (int mt = 0; mt < 2; mt++) {
        int r0 = m0 + wm * 32 + mt * 16 + (lane >> 2);
        #pragma unroll
        for (int nt = 0; nt < 4; nt++) {
            int c0i = n0 + wn * 32 + nt * 8 + 2 * (lane & 3);
            #pragma unroll
            for (int half = 0; half < 2; half++) {
                int r = r0 + half * 8;
                float v0 = acc[mt][nt][half * 2 + 0];
                float v1 = acc[mt][nt][half * 2 + 1];
                if (bias) { v0 += bias[c0i]; v1 += bias[c0i + 1]; }
                if (ACT == 1) {
                    v0 = v0 * (1.0f / (1.0f + __expf(-v0)));
                    v1 = v1 * (1.0f / (1.0f + __expf(-v1)));
                }
                if (RES) {
                    const float* rp = res + (size_t)r * N + c0i;
                    v0 += rp[0]; v1 += rp[1];
                }
                if (OUT == 2) {
                    *(__half2*)(Ch + (size_t)r * N + c0i) = __floats2half2_rn(v0, v1);
                } else {
                    *(float2*)(C + (size_t)r * N + c0i) = make_float2(v0, v1);
                }
            }
        }
    }
}

// ---------------- fp16 flash attention, register softmax + ldmatrix ------------
#define AHS 36
#define ATTN_SMEM ((4*64*AHS + 6*64) * 4)

__global__ __launch_bounds__(256) void attn_h_k(
    const __half* __restrict__ qkv, __half* __restrict__ out) {
    extern __shared__ unsigned asm_[];
    unsigned* Qs = asm_;                      // [64][AHS]
    unsigned* Ks = Qs + 64 * AHS;             // [64][AHS]
    unsigned* Vt = Ks + 64 * AHS;             // [64 d][AHS] (V transposed)
    unsigned* Ps = Vt + 64 * AHS;             // [64][AHS]  (P halves, exchange)
    float*    m_sm  = (float*)(Ps + 64 * AHS);  // [64]
    float*    l_sm  = m_sm + 64;                // [64]
    float*    wmax  = l_sm + 64;                // [2][64]
    float*    wsum  = wmax + 2 * 64;            // [2][64]

    const int q0 = ((int)gridDim.x - 1 - (int)blockIdx.x) * 64;  // heavy-first
    const int h  = blockIdx.y;
    const int b  = blockIdx.z;
    const int tid = threadIdx.x;
    const int lane = tid & 31, warp = tid >> 5;
    const int wm = warp >> 1, wn = warp & 1;   // 4 x 2, warp S-tile 16x32
    const int lrow = lane >> 2, lcol = lane & 3;
    const int g8 = lane >> 3, lr = lane & 7;
    const unsigned sQ = (unsigned)__cvta_generic_to_shared(Qs);
    const unsigned sK = (unsigned)__cvta_generic_to_shared(Ks);
    const unsigned sV = (unsigned)__cvta_generic_to_shared(Vt);
    const unsigned sP = (unsigned)__cvta_generic_to_shared(Ps);

    const __half* qbase = qkv + (size_t)(b * Tv) * QKVN + h * HDv;
    const __half* kbase = qbase + Hv * HDv;
    const __half* vbase = qbase + 2 * Hv * HDv;

    const int srow = tid >> 2, sseg = tid & 3;

    {
        const __half* src = qbase + (size_t)(q0 + srow) * QKVN + sseg * 16;
        uint4 a = *(const uint4*)src;
        uint4 bq = *(const uint4*)(src + 8);
        unsigned va[8] = {a.x, a.y, a.z, a.w, bq.x, bq.y, bq.z, bq.w};
        const __half2 sc = __floats2half2_rn(0.125f, 0.125f);
        unsigned* dst = Qs + srow * AHS + sseg * 8;
        #pragma unroll
        for (int i = 0; i < 8; i++) {
            __half2 hv = __hmul2(*(__half2*)&va[i], sc);
            dst[i] = *(unsigned*)&hv;
        }
    }
    if (tid < 64) { m_sm[tid] = -1e30f; l_sm[tid] = 0.0f; }

    float acc_o[4][4];
    #pragma unroll
    for (int i = 0; i < 4; i++)
        #pragma unroll
        for (int j = 0; j < 4; j++) acc_o[i][j] = 0.0f;

    for (int c0 = 0; c0 <= q0; c0 += 64) {
        {
            const __half* ksrc = kbase + (size_t)(c0 + srow) * QKVN + sseg * 16;
            uint4 a = *(const uint4*)ksrc;
            uint4 bk = *(const uint4*)(ksrc + 8);
            unsigned* dst = Ks + srow * AHS + sseg * 8;
            *(uint4*)dst = a;
            *(uint4*)(dst + 4) = bk;

            const __half* vsrc = vbase + (size_t)(c0 + srow) * QKVN + sseg * 16;
            uint4 va = *(const uint4*)vsrc;
            uint4 vb = *(const uint4*)(vsrc + 8);
            unsigned vv[8] = {va.x, va.y, va.z, va.w, vb.x, vb.y, vb.z, vb.w};
            __half* VtH = (__half*)Vt;
            #pragma unroll
            for (int i = 0; i < 8; i++) {
                int d = sseg * 16 + i * 2;
                __half2 hv = *(__half2*)&vv[i];
                VtH[(size_t)d * (AHS * 2) + srow]       = __low2half(hv);
                VtH[(size_t)(d + 1) * (AHS * 2) + srow] = __high2half(hv);
            }
        }
        __syncthreads();                                   // (1)

        // ---- S = Q . K^T (ldmatrix fragments) ----
        float s_acc[4][4];
        #pragma unroll
        for (int i = 0; i < 4; i++)
            #pragma unroll
            for (int j = 0; j < 4; j++) s_acc[i][j] = 0.0f;
        #pragma unroll
        for (int kb = 0; kb < 32; kb += 8) {
            unsigned af[4], bf[4][2];
            int m = wm * 16 + (g8 & 1) * 8 + lr;
            ldsm4(af, sQ + (m * AHS + kb + (g8 >> 1) * 4) * 4);
            #pragma unroll
            for (int ntp = 0; ntp < 4; ntp += 2) {
                int n = wn * 32 + ntp * 8 + (g8 >> 1) * 8 + lr;
                unsigned tmp[4];
                ldsm4(tmp, sK + (n * AHS + kb + (g8 & 1) * 4) * 4);
                bf[ntp][0] = tmp[0]; bf[ntp][1] = tmp[1];
                bf[ntp + 1][0] = tmp[2]; bf[ntp + 1][1] = tmp[3];
            }
            #pragma unroll
            for (int nt = 0; nt < 4; nt++)
                mma_f16(s_acc[nt], af, bf[nt]);
        }

        if (c0 == q0) {
            #pragma unroll
            for (int nt = 0; nt < 4; nt++) {
                int c = wn * 32 + nt * 8 + 2 * lcol;
                int r0r = wm * 16 + lrow;
                if (c     > r0r)     s_acc[nt][0] = -1e30f;
                if (c + 1 > r0r)     s_acc[nt][1] = -1e30f;
                if (c     > r0r + 8) s_acc[nt][2] = -1e30f;
                if (c + 1 > r0r + 8) s_acc[nt][3] = -1e30f;
            }
        }

        float mx0 = -1e30f, mx1 = -1e30f;
        #pragma unroll
        for (int nt = 0; nt < 4; nt++) {
            mx0 = fmaxf(mx0, fmaxf(s_acc[nt][0], s_acc[nt][1]));
            mx1 = fmaxf(mx1, fmaxf(s_acc[nt][2], s_acc[nt][3]));
        }
        mx0 = fmaxf(mx0, __shfl_xor_sync(0xffffffffu, mx0, 1));
        mx0 = fmaxf(mx0, __shfl_xor_sync(0xffffffffu, mx0, 2));
        mx1 = fmaxf(mx1, __shfl_xor_sync(0xffffffffu, mx1, 1));
        mx1 = fmaxf(mx1, __shfl_xor_sync(0xffffffffu, mx1, 2));
        if (lcol == 0) {
            wmax[wn * 64 + wm * 16 + lrow]     = mx0;
            wmax[wn * 64 + wm * 16 + lrow + 8] = mx1;
        }
        __syncthreads();                                   // (2)

        int row0 = wm * 16 + lrow, row1 = row0 + 8;
        float m_old0 = m_sm[row0], m_old1 = m_sm[row1];
        float m_new0 = fmaxf(m_old0, fmaxf(wmax[row0], wmax[64 + row0]));
        float m_new1 = fmaxf(m_old1, fmaxf(wmax[row1], wmax[64 + row1]));
        float scale0 = __expf(m_old0 - m_new0);
        float scale1 = __expf(m_old1 - m_new1);
        float cs0 = 0.0f, cs1 = 0.0f;
        unsigned pk[4][2];
        #pragma unroll
        for (int nt = 0; nt < 4; nt++) {
            float p0 = __expf(s_acc[nt][0] - m_new0);
            float p1 = __expf(s_acc[nt][1] - m_new0);
            float p2 = __expf(s_acc[nt][2] - m_new1);
            float p3 = __expf(s_acc[nt][3] - m_new1);
            cs0 += p0 + p1; cs1 += p2 + p3;
            __half2 h0 = __floats2half2_rn(p0, p1);
            __half2 h1 = __floats2half2_rn(p2, p3);
            pk[nt][0] = *(unsigned*)&h0;
            pk[nt][1] = *(unsigned*)&h1;
        }
        cs0 += __shfl_xor_sync(0xffffffffu, cs0, 1);
        cs0 += __shfl_xor_sync(0xffffffffu, cs0, 2);
        cs1 += __shfl_xor_sync(0xffffffffu, cs1, 1);
        cs1 += __shfl_xor_sync(0xffffffffu, cs1, 2);
        if (lcol == 0) {
            wsum[wn * 64 + row0] = cs0;
            wsum[wn * 64 + row1] = cs1;
        }
        #pragma unroll
        for (int nt = 0; nt < 4; nt++) {
            Ps[row0 * AHS + wn * 16 + nt * 4 + lcol] = pk[nt][0];
            Ps[row1 * AHS + wn * 16 + nt * 4 + lcol] = pk[nt][1];
        }
        __syncthreads();                                   // (3)

        if (wn == 0 && lcol == 0) {
            l_sm[row0] = l_sm[row0] * scale0 + wsum[row0] + wsum[64 + row0];
            l_sm[row1] = l_sm[row1] * scale1 + wsum[row1] + wsum[64 + row1];
            m_sm[row0] = m_new0;
            m_sm[row1] = m_new1;
        }

        #pragma unroll
        for (int nt = 0; nt < 4; nt++) {
            acc_o[nt][0] *= scale0; acc_o[nt][1] *= scale0;
            acc_o[nt][2] *= scale1; acc_o[nt][3] *= scale1;
        }
        // ---- O += P . V (ldmatrix fragments) ----
        #pragma unroll
        for (int kb = 0; kb < 32; kb += 8) {
            unsigned af[4], bf[4][2];
            int m = wm * 16 + (g8 & 1) * 8 + lr;
            ldsm4(af, sP + (m * AHS + kb + (g8 >> 1) * 4) * 4);
            #pragma unroll
            for (int ntp = 0; ntp < 4; ntp += 2) {
                int n = wn * 32 + ntp * 8 + (g8 >> 1) * 8 + lr;
                unsigned tmp[4];
                ldsm4(tmp, sV + (n * AHS + kb + (g8 & 1) * 4) * 4);
                bf[ntp][0] = tmp[0]; bf[ntp][1] = tmp[1];
                bf[ntp + 1][0] = tmp[2]; bf[ntp + 1][1] = tmp[3];
            }
            #pragma unroll
            for (int nt = 0; nt < 4; nt++)
                mma_f16(acc_o[nt], af, bf[nt]);
        }
        __syncthreads();                                   // (4)
    }

    {
        int r1 = wm * 16 + lrow;
        float inv1 = 1.0f / l_sm[r1], inv2 = 1.0f / l_sm[r1 + 8];
        #pragma unroll
        for (int nt = 0; nt < 4; nt++) {
            int c = wn * 32 + nt * 8 + 2 * lcol;
            __half* o1 = out + (size_t)(b * Tv + q0 + r1) * Dv + h * HDv + c;
            __half* o2 = out + (size_t)(b * Tv + q0 + r1 + 8) * Dv + h * HDv + c;
            *(__half2*)o1 = __floats2half2_rn(acc_o[nt][0] * inv1, acc_o[nt][1] * inv1);
            *(__half2*)o2 = __floats2half2_rn(acc_o[nt][2] * inv2, acc_o[nt][3] * inv2);
        }
    }
}

// ---------------- driver ----------------
extern "C" void kernel_launch(void* const* d_in, const int* in_sizes, int n_in,
                              void* d_out, int out_size) {
    const int*   ids   = (const int*)  d_in[0];
    const float* te    = (const float*)d_in[1];
    const float* pe    = (const float*)d_in[2];
    const float* ln1_s = (const float*)d_in[3];
    const float* ln1_b = (const float*)d_in[4];
    const float* qkv_w = (const float*)d_in[5];
    const float* qkv_b = (const float*)d_in[6];
    const float* out_w = (const float*)d_in[7];
    const float* out_b = (const float*)d_in[8];
    const float* ln2_s = (const float*)d_in[9];
    const float* ln2_b = (const float*)d_in[10];
    const float* up_w  = (const float*)d_in[11];
    const float* up_b  = (const float*)d_in[12];
    const float* dn_w  = (const float*)d_in[13];
    const float* dn_b  = (const float*)d_in[14];
    const float* lnf_s = (const float*)d_in[15];
    const float* lnf_b = (const float*)d_in[16];
    float* logits = (float*)d_out;

    float *x;
    __half *qkvh, *lnb, *att, *ff, *wqkv, *wout, *wup, *wdn, *teh;
    cudaGetSymbolAddress((void**)&x,    g_x);
    cudaGetSymbolAddress((void**)&qkvh, g_qkvh);
    cudaGetSymbolAddress((void**)&lnb,  g_ln);
    cudaGetSymbolAddress((void**)&att,  g_att);
    cudaGetSymbolAddress((void**)&ff,   g_ff);
    cudaGetSymbolAddress((void**)&wqkv, g_wqkv);
    cudaGetSymbolAddress((void**)&wout, g_wout);
    cudaGetSymbolAddress((void**)&wup,  g_wup);
    cudaGetSymbolAddress((void**)&wdn,  g_wdn);
    cudaGetSymbolAddress((void**)&teh,  g_te);

    cudaFuncSetAttribute(attn_h_k,
                         cudaFuncAttributeMaxDynamicSharedMemorySize, ATTN_SMEM);
    cudaFuncSetAttribute(gemm_h<0, false, 2>,
                         cudaFuncAttributeMaxDynamicSharedMemorySize, GEMM_H_SMEM);
    cudaFuncSetAttribute(gemm_h<1, false, 2>,
                         cudaFuncAttributeMaxDynamicSharedMemorySize, GEMM_H_SMEM);
    cudaFuncSetAttribute(gemm_h<0, false, 0>,
                         cudaFuncAttributeMaxDynamicSharedMemorySize, GEMM_H_SMEM);
    cudaFuncSetAttribute(gemm_h64<0, true, 0>,
                         cudaFuncAttributeMaxDynamicSharedMemorySize, GEMM_H64_SMEM);

    // ---- weight prep: transpose + half-convert (every launch; deterministic) ----
    {
        dim3 blk(32, 8);
        thsplit_k<<<dim3(QKVN / 32, Dv / 32, Lv), blk>>>(qkv_w, wqkv, Dv, QKVN);
        thsplit_k<<<dim3(Dv / 32,   Dv / 32, Lv), blk>>>(out_w, wout, Dv, Dv);
        thsplit_k<<<dim3(DFv / 32,  Dv / 32, Lv), blk>>>(up_w,  wup,  Dv, DFv);
        thsplit_k<<<dim3(Dv / 32,  DFv / 32, Lv), blk>>>(dn_w,  wdn,  DFv, Dv);
        int n4 = Vv * Dv / 4;
        hcvt_k<<<(n4 + 255) / 256, 256>>>(te, teh, n4);
    }

    embed_k<<<(Mv * Dv + 255) / 256, 256>>>(ids, te, pe, x);

    for (int i = 0; i < Lv; i++) {
        ln_k<<<Mv, 256>>>(x, ln1_s + (size_t)i * Dv, ln1_b + (size_t)i * Dv, lnb);
        gemm_h<0, false, 2><<<dim3(QKVN / 128, Mv / 128), 256, GEMM_H_SMEM>>>(
            lnb, wqkv + (size_t)i * QKVN * Dv, qkv_b + (size_t)i * QKVN,
            nullptr, nullptr, qkvh, Mv, QKVN, Dv);
        attn_h_k<<<dim3(Tv / 64, Hv, Bv), 256, ATTN_SMEM>>>(qkvh, att);
        gemm_h64<0, true, 0><<<dim3(Dv / 64, Mv / 128), 256, GEMM_H64_SMEM>>>(
            att, wout + (size_t)i * Dv * Dv, out_b + (size_t)i * Dv,
            x, x, nullptr, Mv, Dv, Dv);
        ln_k<<<Mv, 256>>>(x, ln2_s + (size_t)i * Dv, ln2_b + (size_t)i * Dv, lnb);
        gemm_h<1, false, 2><<<dim3(DFv / 128, Mv / 128), 256, GEMM_H_SMEM>>>(
            lnb, wup + (size_t)i * DFv * Dv, up_b + (size_t)i * DFv,
            nullptr, nullptr, ff, Mv, DFv, Dv);
        gemm_h64<0, true, 0><<<dim3(Dv / 64, Mv / 128), 256, GEMM_H64_SMEM>>>(
            ff, wdn + (size_t)i * Dv * DFv, dn_b + (size_t)i * Dv,
            x, x, nullptr, Mv, Dv, DFv);
    }

    ln_k<<<Mv, 256>>>(x, lnf_s, lnf_b, lnb);
    gemm_h<0, false, 0><<<dim3(Vv / 128, Mv / 128), 256, GEMM_H_SMEM>>>(
        lnb, teh, nullptr, nullptr, logits, nullptr, Mv, Vv, Dv);
}